// round 11
// baseline (speedup 1.0000x reference)
#include <cuda_runtime.h>
#include <cuda_fp16.h>
#include <math.h>
#include <stdint.h>

#define Bn    64
#define Nn    256
#define XDim  118
#define EDim  5
#define Hd    384
#define NHd   8
#define DHd   48
#define DFFd  1536
#define DEPTH 6
#define Mrows (Bn * Nn)            /* 16384 */
#define KCAT  (XDim + Nn * EDim)   /* 1398  */
#define KPAD  1408
#define EROW  (Nn * EDim)
#define H3    (3 * Hd)             /* 1152 */

// ---------------- scratch (device globals; zero-init, no allocation) ----------------
__device__ __half g_cath[(size_t)Mrows * KPAD];
__device__ float  g_z  [(size_t)Mrows * Hd];
__device__ __half g_zh [(size_t)Mrows * Hd];
__device__ __half g_yh [(size_t)Mrows * Hd];
__device__ float  g_x1 [(size_t)Mrows * Hd];
__device__ __half g_x1h[(size_t)Mrows * Hd];
__device__ __half g_ffnh[(size_t)Mrows * DFFd];
__device__ __half g_atth[(size_t)Bn * NHd * Nn * Nn];
__device__ float  g_D  [(size_t)Bn * Nn * Nn];
__device__ float  g_sq [Mrows];
// per-head padded Q/K: [b,h,256,64] (cols 48..63 stay zero)
__device__ __half g_qhp[(size_t)Bn * NHd * Nn * 64];
__device__ __half g_khp[(size_t)Bn * NHd * Nn * 64];
// per-head transposed V: [b,h,48,256]
__device__ __half g_vth[(size_t)Bn * NHd * DHd * Nn];
// transposed fp16 weights [N][K]
__device__ __half g_wembTh[(size_t)Hd * KPAD];
__device__ __half g_wqkvT[(size_t)DEPTH * H3 * Hd];
__device__ float  g_bqkv [(size_t)DEPTH * H3];
__device__ __half g_woTh [(size_t)DEPTH * Hd * Hd];
__device__ __half g_w1Th [(size_t)DEPTH * DFFd * Hd];
__device__ __half g_w2Th [(size_t)DEPTH * Hd * DFFd];

// ---------------- PTX helpers (sm_80+ base ISA) ----------------
__device__ __forceinline__ uint32_t smem_to_u32(const void* p) {
    uint32_t a;
    asm("{ .reg .u64 t; cvta.to.shared.u64 t, %1; cvt.u32.u64 %0, t; }"
        : "=r"(a) : "l"(p));
    return a;
}
#define CP_ASYNC16(dst, src) \
    asm volatile("cp.async.cg.shared.global [%0], [%1], 16;" \
                 :: "r"(dst), "l"(src) : "memory")
#define CP_COMMIT() asm volatile("cp.async.commit_group;" ::: "memory")
#define CP_WAIT1()  asm volatile("cp.async.wait_group 1;" ::: "memory")
#define CP_WAIT0()  asm volatile("cp.async.wait_group 0;" ::: "memory")
#define LDSM4(r, addr) \
    asm volatile("ldmatrix.sync.aligned.m8n8.x4.shared.b16 {%0,%1,%2,%3}, [%4];" \
                 : "=r"((r)[0]), "=r"((r)[1]), "=r"((r)[2]), "=r"((r)[3]) \
                 : "r"(addr))
#define MMA16816(d, a, b0_, b1_) \
    asm volatile("mma.sync.aligned.m16n8k16.row.col.f32.f16.f16.f32 " \
                 "{%0,%1,%2,%3}, {%4,%5,%6,%7}, {%8,%9}, {%0,%1,%2,%3};" \
                 : "+f"((d)[0]), "+f"((d)[1]), "+f"((d)[2]), "+f"((d)[3]) \
                 : "r"((a)[0]), "r"((a)[1]), "r"((a)[2]), "r"((a)[3]), \
                   "r"(b0_), "r"(b1_))

// ---------------- reductions ----------------
__device__ __forceinline__ float blocksum128(float v) {
    __shared__ float red[4];
    #pragma unroll
    for (int o = 16; o > 0; o >>= 1) v += __shfl_xor_sync(0xffffffffu, v, o);
    if ((threadIdx.x & 31) == 0) red[threadIdx.x >> 5] = v;
    __syncthreads();
    float s = red[0] + red[1] + red[2] + red[3];
    __syncthreads();
    return s;
}

// ---------------- concat [x | e_flat | 0-pad] -> fp16 ----------------
__global__ void cat_kernel(const float* __restrict__ x, const float* __restrict__ e) {
    size_t idx = (size_t)blockIdx.x * blockDim.x + threadIdx.x;
    if (idx >= (size_t)Mrows * KPAD) return;
    size_t r = idx / KPAD;
    int    c = (int)(idx - r * KPAD);
    float v;
    if (c < XDim)      v = x[r * XDim + c];
    else if (c < KCAT) v = e[r * (size_t)EROW + (c - XDim)];
    else               v = 0.f;
    g_cath[idx] = __float2half(v);
}

// ---------------- transpose fp32 -> fp16 ----------------
__global__ void transpose_kernel(const float* __restrict__ in, __half* __restrict__ out,
                                 int R, int C, int outLd,
                                 size_t inStride, size_t outStride) {
    __shared__ float tile[32][33];
    const float* ip = in + (size_t)blockIdx.z * inStride;
    __half* op = out + (size_t)blockIdx.z * outStride;
    int c0 = blockIdx.x * 32, r0 = blockIdx.y * 32;
    int tx = threadIdx.x, ty = threadIdx.y;
    #pragma unroll
    for (int i = 0; i < 32; i += 8) {
        int r = r0 + ty + i, c = c0 + tx;
        tile[ty + i][tx] = (r < R && c < C) ? ip[(size_t)r * C + c] : 0.f;
    }
    __syncthreads();
    #pragma unroll
    for (int i = 0; i < 32; i += 8) {
        int oc = c0 + ty + i, orow = r0 + tx;
        if (oc < C && orow < outLd)
            op[(size_t)oc * outLd + orow] = __float2half(tile[tx][ty + i]);
    }
}

// ---------------- concat qkv bias ----------------
__global__ void qkvbias_kernel(const float* __restrict__ bq, const float* __restrict__ bk,
                               const float* __restrict__ bv) {
    int i = blockIdx.x * blockDim.x + threadIdx.x;
    if (i >= DEPTH * H3) return;
    int l = i / H3, r = i - l * H3;
    float v;
    if (r < Hd)           v = bq[l * Hd + r];
    else if (r < 2 * Hd)  v = bk[l * Hd + r - Hd];
    else                  v = bv[l * Hd + r - 2 * Hd];
    g_bqkv[i] = v;
}

// ============================================================================
// fp16 HMMA GEMM, 128x128x32 tiles, 8 warps, 3-stage cp.async.
// mode 0: C fp32 (+Ch fp16 row-major)
// mode 3: fused QKV -> qhp/khp/vth head layouts (N = 1152)
// ============================================================================
#define GK_RS      40
#define GK_OPB     (128 * GK_RS * 2)
#define GK_STAGE_B (2 * GK_OPB)
#define GK_SMEM_B  (3 * GK_STAGE_B)

__global__ __launch_bounds__(256)
void gemm_h_kernel(const __half* __restrict__ A, int lda,
                   const __half* __restrict__ BT, int ldb,
                   const float* __restrict__ bias,
                   float* __restrict__ C, __half* __restrict__ Ch,
                   int ldc, int K, int relu, int mode) {
    extern __shared__ char smem[];
    const uint32_t sb = smem_to_u32(smem);
    const int t = threadIdx.x, lane = t & 31, wid = t >> 5;
    const int m0 = blockIdx.y * 128, n0 = blockIdx.x * 128;
    const int mW = (wid & 3) * 32, nW = (wid >> 2) * 64;

    const int r0 = t >> 2,          q0 = t & 3;
    const int r1 = (t + 256) >> 2,  q1 = (t + 256) & 3;
    const int lq = lane >> 3, lr = lane & 7;
    const int aRow = (lq & 1) * 8 + lr, aCol = (lq >> 1) * 8;
    const int bRow = (lq >> 1) * 8 + lr, bCol = (lq & 1) * 8;
    const uint32_t aOff = (uint32_t)(((mW + aRow) * GK_RS + aCol) * 2);
    const uint32_t bOff = (uint32_t)(GK_OPB + ((nW + bRow) * GK_RS + bCol) * 2);

    float acc[2][8][4];
    #pragma unroll
    for (int i = 0; i < 2; i++)
        #pragma unroll
        for (int j = 0; j < 8; j++)
            #pragma unroll
            for (int r = 0; r < 4; r++) acc[i][j][r] = 0.f;

    const int nch = K >> 5;
    auto issue = [&](int ch) {
        const uint32_t dstA = sb + (uint32_t)(ch % 3) * GK_STAGE_B;
        const uint32_t dstB = dstA + GK_OPB;
        const __half* sa  = A  + (size_t)m0 * lda + ch * 32;
        const __half* sbp = BT + (size_t)n0 * ldb + ch * 32;
        CP_ASYNC16(dstA + (uint32_t)((r0 * GK_RS + q0 * 8) * 2), sa  + (size_t)r0 * lda + q0 * 8);
        CP_ASYNC16(dstA + (uint32_t)((r1 * GK_RS + q1 * 8) * 2), sa  + (size_t)r1 * lda + q1 * 8);
        CP_ASYNC16(dstB + (uint32_t)((r0 * GK_RS + q0 * 8) * 2), sbp + (size_t)r0 * ldb + q0 * 8);
        CP_ASYNC16(dstB + (uint32_t)((r1 * GK_RS + q1 * 8) * 2), sbp + (size_t)r1 * ldb + q1 * 8);
        CP_COMMIT();
    };
    issue(0);
    issue(1);

    for (int ch = 0; ch < nch; ch++) {
        if (ch + 1 < nch) { CP_WAIT1(); } else { CP_WAIT0(); }
        __syncthreads();
        const uint32_t base = sb + (uint32_t)(ch % 3) * GK_STAGE_B;
        #pragma unroll
        for (int ks = 0; ks < 2; ks++) {
            uint32_t a[2][4], b[4][4];
            #pragma unroll
            for (int mt = 0; mt < 2; mt++)
                LDSM4(a[mt], base + aOff + (uint32_t)((mt * 16 * GK_RS + ks * 16) * 2));
            #pragma unroll
            for (int g = 0; g < 4; g++)
                LDSM4(b[g], base + bOff + (uint32_t)((g * 16 * GK_RS + ks * 16) * 2));
            #pragma unroll
            for (int mt = 0; mt < 2; mt++)
                #pragma unroll
                for (int g = 0; g < 4; g++) {
                    MMA16816(acc[mt][2 * g],     a[mt], b[g][0], b[g][1]);
                    MMA16816(acc[mt][2 * g + 1], a[mt], b[g][2], b[g][3]);
                }
        }
        if (ch + 2 < nch) issue(ch + 2);
    }

    const int rBase = m0 + mW + (lane >> 2);
    const int cBase = n0 + nW + (lane & 3) * 2;
    #pragma unroll
    for (int mt = 0; mt < 2; mt++) {
        #pragma unroll
        for (int nt = 0; nt < 8; nt++) {
            const int c = cBase + nt * 8;
            float b0 = 0.f, b1 = 0.f;
            if (bias) { b0 = bias[c]; b1 = bias[c + 1]; }
            float v00 = acc[mt][nt][0] + b0, v01 = acc[mt][nt][1] + b1;
            float v10 = acc[mt][nt][2] + b0, v11 = acc[mt][nt][3] + b1;
            if (relu) {
                v00 = fmaxf(v00, 0.f); v01 = fmaxf(v01, 0.f);
                v10 = fmaxf(v10, 0.f); v11 = fmaxf(v11, 0.f);
            }
            const int rA = rBase + mt * 16, rB = rA + 8;
            if (mode == 0) {
                if (C) {
                    *(float2*)(C + (size_t)rA * ldc + c) = make_float2(v00, v01);
                    *(float2*)(C + (size_t)rB * ldc + c) = make_float2(v10, v11);
                }
                if (Ch) {
                    *(__half2*)(Ch + (size_t)rA * ldc + c) = __floats2half2_rn(v00, v01);
                    *(__half2*)(Ch + (size_t)rB * ldc + c) = __floats2half2_rn(v10, v11);
                }
            } else {
                // mode 3: c in [0,1152): sec 0=Q,1=K,2=V
                const int sec = c / Hd;
                const int cc  = c - sec * Hd;
                const int h = cc / DHd, d = cc - h * DHd;
                const int bIdx = rA >> 8;
                if (sec < 2) {
                    __half* dst = (sec == 0) ? g_qhp : g_khp;
                    size_t p0 = ((((size_t)bIdx * NHd + h) << 8) | (rA & 255)) * 64 + d;
                    size_t p1 = ((((size_t)bIdx * NHd + h) << 8) | (rB & 255)) * 64 + d;
                    *(__half2*)(dst + p0) = __floats2half2_rn(v00, v01);
                    *(__half2*)(dst + p1) = __floats2half2_rn(v10, v11);
                } else {
                    size_t hb = ((size_t)bIdx * NHd + h) * DHd;
                    g_vth[(hb + d)     * Nn + (rA & 255)] = __float2half(v00);
                    g_vth[(hb + d + 1) * Nn + (rA & 255)] = __float2half(v01);
                    g_vth[(hb + d)     * Nn + (rB & 255)] = __float2half(v10);
                    g_vth[(hb + d + 1) * Nn + (rB & 255)] = __float2half(v11);
                }
            }
        }
    }
}

// ============================================================================
// gemmln: C = LayerNorm(resid + A@BT + bias) -> out fp32 + outh fp16 (+sq).
// Tile 64m x 384n (full row), 512 threads (16 warps, 4m x 4n, warp 16x96),
// 3-stage cp.async over K chunks of 32. K in {384, 1536}.
// ============================================================================
#define GL_ARS   40
#define GL_ABUF  (64 * GL_ARS * 2)      /*  5120 */
#define GL_BBUF  (384 * GL_ARS * 2)     /* 30720 */
#define GL_STAGE (GL_ABUF + GL_BBUF)    /* 35840 */
#define GL_RED   (3 * GL_STAGE)         /* 107520 */
#define GL_SMEM  (GL_RED + 256 * 4)

__global__ __launch_bounds__(512)
void gemmln_kernel(const __half* __restrict__ A, int lda,
                   const __half* __restrict__ BT,
                   const float* __restrict__ bias,
                   const float* __restrict__ resid,
                   const float* __restrict__ gam, const float* __restrict__ bet,
                   float* __restrict__ out, __half* __restrict__ outh,
                   float* __restrict__ sqout, int K) {
    extern __shared__ char smem[];
    const uint32_t sb = smem_to_u32(smem);
    float* red = (float*)(smem + GL_RED);    // [4][64]
    const int t = threadIdx.x, lane = t & 31, wid = t >> 5;
    const int m0 = blockIdx.x * 64;
    const int mW = (wid & 3) * 16, nW = (wid >> 2) * 96;

    const int lq = lane >> 3, lr = lane & 7;
    const int aRow = (lq & 1) * 8 + lr, aCol = (lq >> 1) * 8;
    const int bRow = (lq >> 1) * 8 + lr, bCol = (lq & 1) * 8;
    const uint32_t aOff = (uint32_t)(((mW + aRow) * GL_ARS + aCol) * 2);
    const uint32_t bOff = (uint32_t)(GL_ABUF + ((nW + bRow) * GL_ARS + bCol) * 2);

    float acc[12][4];
    #pragma unroll
    for (int j = 0; j < 12; j++)
        #pragma unroll
        for (int r = 0; r < 4; r++) acc[j][r] = 0.f;

    const int nch = K >> 5;
    auto issue = [&](int ch) {
        const uint32_t dstA = sb + (uint32_t)(ch % 3) * GL_STAGE;
        const uint32_t dstB = dstA + GL_ABUF;
        if (t < 256) {
            int row = t >> 2, seg = t & 3;
            CP_ASYNC16(dstA + (uint32_t)((row * GL_ARS + seg * 8) * 2),
                       A + (size_t)(m0 + row) * lda + ch * 32 + seg * 8);
        }
        #pragma unroll
        for (int u = 0; u < 3; u++) {
            int p = t + u * 512, row = p >> 2, seg = p & 3;
            CP_ASYNC16(dstB + (uint32_t)((row * GL_ARS + seg * 8) * 2),
                       BT + (size_t)row * K + ch * 32 + seg * 8);
        }
        CP_COMMIT();
    };
    issue(0);
    issue(1);

    for (int ch = 0; ch < nch; ch++) {
        if (ch + 1 < nch) { CP_WAIT1(); } else { CP_WAIT0(); }
        __syncthreads();
        const uint32_t base = sb + (uint32_t)(ch % 3) * GL_STAGE;
        #pragma unroll
        for (int ks = 0; ks < 2; ks++) {
            uint32_t a[4];
            LDSM4(a, base + aOff + (uint32_t)(ks * 16 * 2));
            #pragma unroll
            for (int g = 0; g < 6; g++) {
                uint32_t bf[4];
                LDSM4(bf, base + bOff + (uint32_t)((g * 16 * GL_ARS + ks * 16) * 2));
                MMA16816(acc[2 * g],     a, bf[0], bf[1]);
                MMA16816(acc[2 * g + 1], a, bf[2], bf[3]);
            }
        }
        if (ch + 2 < nch) issue(ch + 2);
    }

    // ---- epilogue: +bias +residual, LayerNorm over 384 cols ----
    const int rloc0 = mW + (lane >> 2), rloc1 = rloc0 + 8;
    const int grow0 = m0 + rloc0, grow1 = m0 + rloc1;
    const int nwg = wid >> 2;     // n-warp group 0..3
    const int cL = nW + (lane & 3) * 2;

    #pragma unroll
    for (int nt = 0; nt < 12; nt++) {
        const int c = cL + nt * 8;
        float2 bi = *(const float2*)(bias + c);
        float2 r0 = *(const float2*)(resid + (size_t)grow0 * Hd + c);
        float2 r1 = *(const float2*)(resid + (size_t)grow1 * Hd + c);
        acc[nt][0] += bi.x + r0.x;  acc[nt][1] += bi.y + r0.y;
        acc[nt][2] += bi.x + r1.x;  acc[nt][3] += bi.y + r1.y;
    }
    // mean
    float s0 = 0.f, s1 = 0.f;
    #pragma unroll
    for (int nt = 0; nt < 12; nt++) {
        s0 += acc[nt][0] + acc[nt][1];
        s1 += acc[nt][2] + acc[nt][3];
    }
    #pragma unroll
    for (int o = 1; o < 4; o <<= 1) {
        s0 += __shfl_xor_sync(0xffffffffu, s0, o);
        s1 += __shfl_xor_sync(0xffffffffu, s1, o);
    }
    if ((lane & 3) == 0) {
        red[nwg * 64 + rloc0] = s0;
        red[nwg * 64 + rloc1] = s1;
    }
    __syncthreads();
    const float mu0 = (red[rloc0] + red[64 + rloc0] + red[128 + rloc0] + red[192 + rloc0])
                      * (1.f / Hd);
    const float mu1 = (red[rloc1] + red[64 + rloc1] + red[128 + rloc1] + red[192 + rloc1])
                      * (1.f / Hd);
    __syncthreads();
    // variance
    s0 = 0.f; s1 = 0.f;
    #pragma unroll
    for (int nt = 0; nt < 12; nt++) {
        float d;
        d = acc[nt][0] - mu0; s0 += d * d;
        d = acc[nt][1] - mu0; s0 += d * d;
        d = acc[nt][2] - mu1; s1 += d * d;
        d = acc[nt][3] - mu1; s1 += d * d;
    }
    #pragma unroll
    for (int o = 1; o < 4; o <<= 1) {
        s0 += __shfl_xor_sync(0xffffffffu, s0, o);
        s1 += __shfl_xor_sync(0xffffffffu, s1, o);
    }
    if ((lane & 3) == 0) {
        red[nwg * 64 + rloc0] = s0;
        red[nwg * 64 + rloc1] = s1;
    }
    __syncthreads();
    const float rstd0 = rsqrtf((red[rloc0] + red[64 + rloc0] + red[128 + rloc0] +
                                red[192 + rloc0]) * (1.f / Hd) + 1e-5f);
    const float rstd1 = rsqrtf((red[rloc1] + red[64 + rloc1] + red[128 + rloc1] +
                                red[192 + rloc1]) * (1.f / Hd) + 1e-5f);
    __syncthreads();
    // normalize + write (+sq accumulate)
    s0 = 0.f; s1 = 0.f;
    #pragma unroll
    for (int nt = 0; nt < 12; nt++) {
        const int c = cL + nt * 8;
        float2 gv = *(const float2*)(gam + c);
        float2 bv = *(const float2*)(bet + c);
        float o00 = (acc[nt][0] - mu0) * rstd0 * gv.x + bv.x;
        float o01 = (acc[nt][1] - mu0) * rstd0 * gv.y + bv.y;
        float o10 = (acc[nt][2] - mu1) * rstd1 * gv.x + bv.x;
        float o11 = (acc[nt][3] - mu1) * rstd1 * gv.y + bv.y;
        *(float2*)(out + (size_t)grow0 * Hd + c) = make_float2(o00, o01);
        *(float2*)(out + (size_t)grow1 * Hd + c) = make_float2(o10, o11);
        *(__half2*)(outh + (size_t)grow0 * Hd + c) = __floats2half2_rn(o00, o01);
        *(__half2*)(outh + (size_t)grow1 * Hd + c) = __floats2half2_rn(o10, o11);
        s0 += o00 * o00 + o01 * o01;
        s1 += o10 * o10 + o11 * o11;
    }
    if (sqout) {
        #pragma unroll
        for (int o = 1; o < 4; o <<= 1) {
            s0 += __shfl_xor_sync(0xffffffffu, s0, o);
            s1 += __shfl_xor_sync(0xffffffffu, s1, o);
        }
        if ((lane & 3) == 0) {
            red[nwg * 64 + rloc0] = s0;
            red[nwg * 64 + rloc1] = s1;
        }
        __syncthreads();
        if (nwg == 0 && (lane & 3) == 0) {
            sqout[grow0] = red[rloc0] + red[64 + rloc0] + red[128 + rloc0] + red[192 + rloc0];
            sqout[grow1] = red[rloc1] + red[64 + rloc1] + red[128 + rloc1] + red[192 + rloc1];
        }
    }
}

// ============================================================================
// distrow: fused gram(zh) + sqrt + mask + rowmax-bias -> g_D. 64m x 256n, K=384.
// ============================================================================
#define DR_ARS   40
#define DR_ABUF  (64 * DR_ARS * 2)
#define DR_BBUF  (256 * DR_ARS * 2)
#define DR_STAGE (DR_ABUF + DR_BBUF)
#define DR_RED   (3 * DR_STAGE)
#define DR_SMEM  (DR_RED + 128 * 4)

__global__ __launch_bounds__(256)
void distrow_kernel(const __half* __restrict__ Z, const float* __restrict__ mask) {
    extern __shared__ char smem[];
    const uint32_t sb = smem_to_u32(smem);
    float* rmax = (float*)(smem + DR_RED);
    const int t = threadIdx.x, lane = t & 31, wid = t >> 5;
    const int bz = blockIdx.y, m0 = blockIdx.x * 64;
    const __half* A = Z + (size_t)bz * Nn * Hd + (size_t)m0 * Hd;
    const __half* B = Z + (size_t)bz * Nn * Hd;
    const int mW = (wid & 3) * 16, nW = (wid >> 2) * 128;

    const int lq = lane >> 3, lr = lane & 7;
    const int aRow = (lq & 1) * 8 + lr, aCol = (lq >> 1) * 8;
    const int bRow = (lq >> 1) * 8 + lr, bCol = (lq & 1) * 8;
    const uint32_t aOff = (uint32_t)(((mW + aRow) * DR_ARS + aCol) * 2);
    const uint32_t bOff = (uint32_t)(DR_ABUF + ((nW + bRow) * DR_ARS + bCol) * 2);

    float acc[16][4];
    #pragma unroll
    for (int j = 0; j < 16; j++)
        #pragma unroll
        for (int r = 0; r < 4; r++) acc[j][r] = 0.f;

    auto issue = [&](int ch) {
        const uint32_t dstA = sb + (uint32_t)(ch % 3) * DR_STAGE;
        const uint32_t dstB = dstA + DR_ABUF;
        CP_ASYNC16(dstA + (uint32_t)(((t >> 2) * DR_ARS + (t & 3) * 8) * 2),
                   A + (size_t)(t >> 2) * Hd + ch * 32 + (t & 3) * 8);
        #pragma unroll
        for (int u = 0; u < 4; u++) {
            int p = t + u * 256, row = p >> 2, seg = p & 3;
            CP_ASYNC16(dstB + (uint32_t)((row * DR_ARS + seg * 8) * 2),
                       B + (size_t)row * Hd + ch * 32 + seg * 8);
        }
        CP_COMMIT();
    };
    issue(0);
    issue(1);

    const int nch = Hd >> 5;
    for (int ch = 0; ch < nch; ch++) {
        if (ch + 1 < nch) { CP_WAIT1(); } else { CP_WAIT0(); }
        __syncthreads();
        const uint32_t base = sb + (uint32_t)(ch % 3) * DR_STAGE;
        #pragma unroll
        for (int ks = 0; ks < 2; ks++) {
            uint32_t a[4];
            LDSM4(a, base + aOff + (uint32_t)(ks * 16 * 2));
            #pragma unroll
            for (int g = 0; g < 8; g++) {
                uint32_t bf[4];
                LDSM4(bf, base + bOff + (uint32_t)((g * 16 * DR_ARS + ks * 16) * 2));
                MMA16816(acc[2 * g],     a, bf[0], bf[1]);
                MMA16816(acc[2 * g + 1], a, bf[2], bf[3]);
            }
        }
        if (ch + 2 < nch) issue(ch + 2);
    }

    const int rloc0 = mW + (lane >> 2), rloc1 = rloc0 + 8;
    const int gi0 = m0 + rloc0, gi1 = m0 + rloc1;
    const int cB = nW + (lane & 3) * 2;
    const float sqi0 = g_sq[bz * Nn + gi0], sqi1 = g_sq[bz * Nn + gi1];
    const float mi0 = mask[bz * Nn + gi0],  mi1 = mask[bz * Nn + gi1];
    #pragma unroll
    for (int nt = 0; nt < 16; nt++) {
        const int gj = cB + nt * 8;
        float sj0 = g_sq[bz * Nn + gj], sj1 = g_sq[bz * Nn + gj + 1];
        float mj0 = mask[bz * Nn + gj], mj1 = mask[bz * Nn + gj + 1];
        float d2;
        d2 = fmaxf(sqi0 + sj0 - 2.f * acc[nt][0], 0.f);
        acc[nt][0] = ((d2 > 1e-12f) ? sqrtf(d2) : 0.f) * mi0 * mj0;
        d2 = fmaxf(sqi0 + sj1 - 2.f * acc[nt][1], 0.f);
        acc[nt][1] = ((d2 > 1e-12f) ? sqrtf(d2) : 0.f) * mi0 * mj1;
        d2 = fmaxf(sqi1 + sj0 - 2.f * acc[nt][2], 0.f);
        acc[nt][2] = ((d2 > 1e-12f) ? sqrtf(d2) : 0.f) * mi1 * mj0;
        d2 = fmaxf(sqi1 + sj1 - 2.f * acc[nt][3], 0.f);
        acc[nt][3] = ((d2 > 1e-12f) ? sqrtf(d2) : 0.f) * mi1 * mj1;
    }
    float mx0 = 0.f, mx1 = 0.f;
    #pragma unroll
    for (int nt = 0; nt < 16; nt++) {
        mx0 = fmaxf(mx0, fmaxf(acc[nt][0], acc[nt][1]));
        mx1 = fmaxf(mx1, fmaxf(acc[nt][2], acc[nt][3]));
    }
    #pragma unroll
    for (int o = 1; o < 4; o <<= 1) {
        mx0 = fmaxf(mx0, __shfl_xor_sync(0xffffffffu, mx0, o));
        mx1 = fmaxf(mx1, __shfl_xor_sync(0xffffffffu, mx1, o));
    }
    const int nw = wid >> 2;
    rmax[nw * 64 + rloc0] = mx0;
    rmax[nw * 64 + rloc1] = mx1;
    __syncthreads();
    const float M0 = fmaxf(rmax[rloc0], rmax[64 + rloc0]);
    const float M1 = fmaxf(rmax[rloc1], rmax[64 + rloc1]);
    float* Dp = g_D + (size_t)bz * Nn * Nn;
    #pragma unroll
    for (int nt = 0; nt < 16; nt++) {
        const int gj = cB + nt * 8;
        float mj0 = mask[bz * Nn + gj], mj1 = mask[bz * Nn + gj + 1];
        float o00 = (gi0 == gj)     ? 0.f : (M0 - acc[nt][0]) * mi0 * mj0;
        float o01 = (gi0 == gj + 1) ? 0.f : (M0 - acc[nt][1]) * mi0 * mj1;
        float o10 = (gi1 == gj)     ? 0.f : (M1 - acc[nt][2]) * mi1 * mj0;
        float o11 = (gi1 == gj + 1) ? 0.f : (M1 - acc[nt][3]) * mi1 * mj1;
        *(float2*)(Dp + (size_t)gi0 * Nn + gj) = make_float2(o00, o01);
        *(float2*)(Dp + (size_t)gi1 * Nn + gj) = make_float2(o10, o11);
    }
}

// ============================================================================
// qksm: fused QK^T + D-bias + softmax -> fp16 probs. 64m x 256n, K=64.
// ============================================================================
#define QS_ARS   72
#define QS_ABUF  (64 * QS_ARS * 2)
#define QS_BBUF  (256 * QS_ARS * 2)
#define QS_RED   (QS_ABUF + QS_BBUF)
#define QS_SMEM  (QS_RED + 2 * 128 * 4)

__global__ __launch_bounds__(256)
void qksm_kernel(const __half* __restrict__ qhp, const __half* __restrict__ khp) {
    extern __shared__ char smem[];
    const uint32_t sb = smem_to_u32(smem);
    float* rmax = (float*)(smem + QS_RED);
    float* rsum = rmax + 128;
    const int t = threadIdx.x, lane = t & 31, wid = t >> 5;
    const int bh = blockIdx.y, m0 = blockIdx.x * 64;
    const int b = bh >> 3;
    const __half* A = qhp + (size_t)bh * Nn * 64 + (size_t)m0 * 64;
    const __half* B = khp + (size_t)bh * Nn * 64;
    const int mW = (wid & 3) * 16, nW = (wid >> 2) * 128;

    #pragma unroll
    for (int u = 0; u < 2; u++) {
        int p = t + u * 256, row = p >> 3, seg = p & 7;
        CP_ASYNC16(sb + (uint32_t)((row * QS_ARS + seg * 8) * 2),
                   A + (size_t)row * 64 + seg * 8);
    }
    #pragma unroll
    for (int u = 0; u < 8; u++) {
        int p = t + u * 256, row = p >> 3, seg = p & 7;
        CP_ASYNC16(sb + (uint32_t)(QS_ABUF + (row * QS_ARS + seg * 8) * 2),
                   B + (size_t)row * 64 + seg * 8);
    }
    CP_COMMIT();
    CP_WAIT0();
    __syncthreads();

    const int lq = lane >> 3, lr = lane & 7;
    const int aRow = (lq & 1) * 8 + lr, aCol = (lq >> 1) * 8;
    const int bRow = (lq >> 1) * 8 + lr, bCol = (lq & 1) * 8;
    const uint32_t aOff = sb + (uint32_t)(((mW + aRow) * QS_ARS + aCol) * 2);
    const uint32_t bOff = sb + (uint32_t)(QS_ABUF + ((nW + bRow) * QS_ARS + bCol) * 2);

    float acc[16][4];
    #pragma unroll
    for (int j = 0; j < 16; j++)
        #pragma unroll
        for (int r = 0; r < 4; r++) acc[j][r] = 0.f;

    #pragma unroll
    for (int ks = 0; ks < 4; ks++) {
        uint32_t a[4];
        LDSM4(a, aOff + (uint32_t)(ks * 16 * 2));
        #pragma unroll
        for (int g = 0; g < 8; g++) {
            uint32_t bf[4];
            LDSM4(bf, bOff + (uint32_t)((g * 16 * QS_ARS + ks * 16) * 2));
            MMA16816(acc[2 * g],     a, bf[0], bf[1]);
            MMA16816(acc[2 * g + 1], a, bf[2], bf[3]);
        }
    }

    const float scale = 0.144337567297406441f;
    const int rloc0 = mW + (lane >> 2), rloc1 = rloc0 + 8;
    const int gi0 = m0 + rloc0, gi1 = m0 + rloc1;
    const int cB = nW + (lane & 3) * 2;
    #pragma unroll
    for (int nt = 0; nt < 16; nt++) {
        const int gj = cB + nt * 8;
        float2 d0 = *(const float2*)(g_D + ((size_t)b * Nn + gi0) * Nn + gj);
        float2 d1 = *(const float2*)(g_D + ((size_t)b * Nn + gi1) * Nn + gj);
        acc[nt][0] = acc[nt][0] * scale + d0.x;
        acc[nt][1] = acc[nt][1] * scale + d0.y;
        acc[nt][2] = acc[nt][2] * scale + d1.x;
        acc[nt][3] = acc[nt][3] * scale + d1.y;
    }
    float mx0 = -1e30f, mx1 = -1e30f;
    #pragma unroll
    for (int nt = 0; nt < 16; nt++) {
        mx0 = fmaxf(mx0, fmaxf(acc[nt][0], acc[nt][1]));
        mx1 = fmaxf(mx1, fmaxf(acc[nt][2], acc[nt][3]));
    }
    #pragma unroll
    for (int o = 1; o < 4; o <<= 1) {
        mx0 = fmaxf(mx0, __shfl_xor_sync(0xffffffffu, mx0, o));
        mx1 = fmaxf(mx1, __shfl_xor_sync(0xffffffffu, mx1, o));
    }
    const int nw = wid >> 2;
    rmax[nw * 64 + rloc0] = mx0;
    rmax[nw * 64 + rloc1] = mx1;
    __syncthreads();
    const float M0 = fmaxf(rmax[rloc0], rmax[64 + rloc0]);
    const float M1 = fmaxf(rmax[rloc1], rmax[64 + rloc1]);
    float s0 = 0.f, s1 = 0.f;
    #pragma unroll
    for (int nt = 0; nt < 16; nt++) {
        acc[nt][0] = __expf(acc[nt][0] - M0);
        acc[nt][1] = __expf(acc[nt][1] - M0);
        acc[nt][2] = __expf(acc[nt][2] - M1);
        acc[nt][3] = __expf(acc[nt][3] - M1);
        s0 += acc[nt][0] + acc[nt][1];
        s1 += acc[nt][2] + acc[nt][3];
    }
    #pragma unroll
    for (int o = 1; o < 4; o <<= 1) {
        s0 += __shfl_xor_sync(0xffffffffu, s0, o);
        s1 += __shfl_xor_sync(0xffffffffu, s1, o);
    }
    rsum[nw * 64 + rloc0] = s0;
    rsum[nw * 64 + rloc1] = s1;
    __syncthreads();
    const float inv0 = 1.f / (rsum[rloc0] + rsum[64 + rloc0]);
    const float inv1 = 1.f / (rsum[rloc1] + rsum[64 + rloc1]);
    __half* outp = g_atth + (size_t)bh * Nn * Nn;
    #pragma unroll
    for (int nt = 0; nt < 16; nt++) {
        const int gj = cB + nt * 8;
        *(__half2*)(outp + (size_t)gi0 * Nn + gj) =
            __floats2half2_rn(acc[nt][0] * inv0, acc[nt][1] * inv0);
        *(__half2*)(outp + (size_t)gi1 * Nn + gj) =
            __floats2half2_rn(acc[nt][2] * inv1, acc[nt][3] * inv1);
    }
}

// ============================================================================
// attnv: y = P @ V^T per head. 128m x 48n x 256k, 4 warps, 3-stage cp.async.
// ============================================================================
#define AV_RS    40
#define AV_ABUF  (128 * AV_RS * 2)
#define AV_BBUF  (48 * AV_RS * 2)
#define AV_STAGE (AV_ABUF + AV_BBUF)
#define AV_SMEM  (3 * AV_STAGE)

__global__ __launch_bounds__(128)
void attnv_h_kernel() {
    extern __shared__ char smem[];
    const uint32_t sb = smem_to_u32(smem);
    const int t = threadIdx.x, lane = t & 31, wid = t >> 5;
    const int bh = blockIdx.y, m0 = blockIdx.x * 128;
    const __half* A = g_atth + (size_t)bh * Nn * Nn;
    const __half* B = g_vth + (size_t)bh * DHd * Nn;
    const int mW = wid * 32;

    const int lq = lane >> 3, lr = lane & 7;
    const int aRow = (lq & 1) * 8 + lr, aCol = (lq >> 1) * 8;
    const int bRow = (lq >> 1) * 8 + lr, bCol = (lq & 1) * 8;
    const uint32_t aOff = (uint32_t)(((mW + aRow) * AV_RS + aCol) * 2);
    const uint32_t bOff = (uint32_t)(AV_ABUF + (bRow * AV_RS + bCol) * 2);

    float acc[2][6][4];
    #pragma unroll
    for (int i = 0; i < 2; i++)
        #pragma unroll
        for (int j = 0; j < 6; j++)
            #pragma unroll
            for (int r = 0; r < 4; r++) acc[i][j][r] = 0.f;

    auto issue = [&](int ch) {
        const uint32_t dstA = sb + (uint32_t)(ch % 3) * AV_STAGE;
        const uint32_t dstB = dstA + AV_ABUF;
        #pragma unroll
        for (int u = 0; u < 4; u++) {
            int p = t + u * 128, row = p >> 2, seg = p & 3;
            CP_ASYNC16(dstA + (uint32_t)((row * AV_RS + seg * 8) * 2),
                       A + (size_t)(m0 + row) * Nn + ch * 32 + seg * 8);
        }
        #pragma unroll
        for (int u = 0; u < 2; u++) {
            int p = t + u * 128;
            if (p < 192) {
                int row = p >> 2, seg = p & 3;
                CP_ASYNC16(dstB + (uint32_t)((row * AV_RS + seg * 8) * 2),
                           B + (size_t)row * Nn + ch * 32 + seg * 8);
            }
        }
        CP_COMMIT();
    };
    issue(0);
    issue(1);

    const int nch = Nn >> 5;
    for (int ch = 0; ch < nch; ch++) {
        if (ch + 1 < nch) { CP_WAIT1(); } else { CP_WAIT0(); }
        __syncthreads();
        const uint32_t base = sb + (uint32_t)(ch % 3) * AV_STAGE;
        #pragma unroll
        for (int ks = 0; ks < 2; ks++) {
            uint32_t a[2][4], b[3][4];
            #pragma unroll
            for (int mt = 0; mt < 2; mt++)
                LDSM4(a[mt], base + aOff + (uint32_t)((mt * 16 * AV_RS + ks * 16) * 2));
            #pragma unroll
            for (int g = 0; g < 3; g++)
                LDSM4(b[g], base + bOff + (uint32_t)((g * 16 * AV_RS + ks * 16) * 2));
            #pragma unroll
            for (int mt = 0; mt < 2; mt++)
                #pragma unroll
                for (int g = 0; g < 3; g++) {
                    MMA16816(acc[mt][2 * g],     a[mt], b[g][0], b[g][1]);
                    MMA16816(acc[mt][2 * g + 1], a[mt], b[g][2], b[g][3]);
                }
        }
        if (ch + 2 < nch) issue(ch + 2);
    }

    const int b = bh >> 3, h = bh & 7;
    const int rBase = m0 + mW + (lane >> 2);
    const int cBase = (lane & 3) * 2;
    #pragma unroll
    for (int mt = 0; mt < 2; mt++) {
        #pragma unroll
        for (int nt = 0; nt < 6; nt++) {
            const int c = cBase + nt * 8;
            const int gi = rBase + mt * 16;
            *(__half2*)(g_yh + ((size_t)b * Nn + gi) * Hd + h * DHd + c) =
                __floats2half2_rn(acc[mt][nt][0], acc[mt][nt][1]);
            *(__half2*)(g_yh + ((size_t)b * Nn + gi + 8) * Hd + h * DHd + c) =
                __floats2half2_rn(acc[mt][nt][2], acc[mt][nt][3]);
        }
    }
}

// ---------------- row squared norms of z (post-embed only) ----------------
__global__ void sqnorm_kernel() {
    int r = blockIdx.x;
    float s = 0.f;
    for (int c = threadIdx.x; c < Hd; c += 128) {
        float v = g_z[(size_t)r * Hd + c];
        s += v * v;
    }
    s = blocksum128(s);
    if (threadIdx.x == 0) g_sq[r] = s;
}

// ---------------- masked outputs ----------------
__global__ void out_x_kernel(const float* __restrict__ x, const float* __restrict__ mask,
                             float* __restrict__ out) {
    size_t idx = (size_t)blockIdx.x * blockDim.x + threadIdx.x;
    if (idx >= (size_t)Bn * Nn * XDim) return;
    out[idx] = x[idx] * mask[idx / XDim];
}
__global__ void out_e_kernel(const float* __restrict__ e, const float* __restrict__ mask,
                             float* __restrict__ out) {
    size_t idx = (size_t)blockIdx.x * blockDim.x + threadIdx.x;
    if (idx >= (size_t)Bn * Nn * Nn * EDim) return;
    size_t pair = idx / EDim;
    int j  = (int)(pair % Nn);
    size_t bi = pair / Nn;
    int b  = (int)(bi / Nn);
    out[idx] = e[idx] * mask[bi] * mask[(size_t)b * Nn + j];
}
__global__ void out_z_kernel(const float* __restrict__ mask, float* __restrict__ out) {
    size_t idx = (size_t)blockIdx.x * blockDim.x + threadIdx.x;
    if (idx >= (size_t)Mrows * Hd) return;
    out[idx] = g_z[idx] * mask[idx / Hd];
}

// ---------------- launcher ----------------
extern "C" void kernel_launch(void* const* d_in, const int* in_sizes, int n_in,
                              void* d_out, int out_size) {
    const float* x    = (const float*)d_in[0];
    const float* e    = (const float*)d_in[1];
    const float* mask = (const float*)d_in[2];
    const float* Wemb = (const float*)d_in[3];
    const float* Wq = (const float*)d_in[4];  const float* bq = (const float*)d_in[5];
    const float* Wk = (const float*)d_in[6];  const float* bk = (const float*)d_in[7];
    const float* Wv = (const float*)d_in[8];  const float* bv = (const float*)d_in[9];
    const float* Wo = (const float*)d_in[10]; const float* bo = (const float*)d_in[11];
    const float* g1 = (const float*)d_in[12]; const float* be1 = (const float*)d_in[13];
    const float* W1 = (const float*)d_in[14]; const float* b1  = (const float*)d_in[15];
    const float* W2 = (const float*)d_in[16]; const float* b2  = (const float*)d_in[17];
    const float* g2 = (const float*)d_in[18]; const float* be2 = (const float*)d_in[19];
    float* out = (float*)d_out;

    float  *z, *x1, *sq, *bqkv;
    __half *cath, *zh, *x1h, *yh, *ffnh, *qhp, *khp;
    __half *wembTh, *wqkvT, *woTh, *w1Th, *w2Th;
    cudaGetSymbolAddress((void**)&cath,  g_cath);
    cudaGetSymbolAddress((void**)&z,     g_z);
    cudaGetSymbolAddress((void**)&zh,    g_zh);
    cudaGetSymbolAddress((void**)&yh,    g_yh);
    cudaGetSymbolAddress((void**)&x1,    g_x1);
    cudaGetSymbolAddress((void**)&x1h,   g_x1h);
    cudaGetSymbolAddress((void**)&ffnh,  g_ffnh);
    cudaGetSymbolAddress((void**)&qhp,   g_qhp);
    cudaGetSymbolAddress((void**)&khp,   g_khp);
    cudaGetSymbolAddress((void**)&sq,    g_sq);
    cudaGetSymbolAddress((void**)&bqkv,  g_bqkv);
    cudaGetSymbolAddress((void**)&wembTh, g_wembTh);
    cudaGetSymbolAddress((void**)&wqkvT, g_wqkvT);
    cudaGetSymbolAddress((void**)&woTh,  g_woTh);
    cudaGetSymbolAddress((void**)&w1Th,  g_w1Th);
    cudaGetSymbolAddress((void**)&w2Th,  g_w2Th);

    cudaFuncSetAttribute(gemm_h_kernel,
                         cudaFuncAttributeMaxDynamicSharedMemorySize, GK_SMEM_B);
    cudaFuncSetAttribute(gemmln_kernel,
                         cudaFuncAttributeMaxDynamicSharedMemorySize, GL_SMEM);
    cudaFuncSetAttribute(distrow_kernel,
                         cudaFuncAttributeMaxDynamicSharedMemorySize, DR_SMEM);
    cudaFuncSetAttribute(qksm_kernel,
                         cudaFuncAttributeMaxDynamicSharedMemorySize, QS_SMEM);
    cudaFuncSetAttribute(attnv_h_kernel,
                         cudaFuncAttributeMaxDynamicSharedMemorySize, AV_SMEM);

    dim3 tb(32, 8);
    {
        size_t tot = (size_t)Mrows * KPAD;
        cat_kernel<<<(unsigned)((tot + 255) / 256), 256>>>(x, e);
    }
    transpose_kernel<<<dim3(12, 44, 1), tb>>>(Wemb, wembTh, KCAT, Hd, KPAD, 0, 0);
    transpose_kernel<<<dim3(12, 12, DEPTH), tb>>>(Wq, wqkvT, Hd, Hd, Hd,
                                                  (size_t)Hd * Hd, (size_t)H3 * Hd);
    transpose_kernel<<<dim3(12, 12, DEPTH), tb>>>(Wk, wqkvT + (size_t)Hd * Hd, Hd, Hd, Hd,
                                                  (size_t)Hd * Hd, (size_t)H3 * Hd);
    transpose_kernel<<<dim3(12, 12, DEPTH), tb>>>(Wv, wqkvT + 2 * (size_t)Hd * Hd, Hd, Hd, Hd,
                                                  (size_t)Hd * Hd, (size_t)H3 * Hd);
    qkvbias_kernel<<<(DEPTH * H3 + 255) / 256, 256>>>(bq, bk, bv);
    gemm_h_kernel<<<dim3(Hd / 128, Mrows / 128), 256, GK_SMEM_B>>>(
        cath, KPAD, wembTh, KPAD, nullptr, z, zh, Hd, KPAD, 0, 0);
    transpose_kernel<<<dim3(12, 12, DEPTH), tb>>>(Wo, woTh, Hd, Hd, Hd,
                                                  (size_t)Hd * Hd, (size_t)Hd * Hd);
    transpose_kernel<<<dim3(48, 12, DEPTH), tb>>>(W1, w1Th, Hd, DFFd, Hd,
                                                  (size_t)Hd * DFFd, (size_t)DFFd * Hd);
    transpose_kernel<<<dim3(12, 48, DEPTH), tb>>>(W2, w2Th, DFFd, Hd, DFFd,
                                                  (size_t)DFFd * Hd, (size_t)Hd * DFFd);
    sqnorm_kernel<<<Mrows, 128>>>();

    for (int l = 0; l < DEPTH; l++) {
        const size_t wofs  = (size_t)l * Hd * Hd;
        const size_t w1ofs = (size_t)l * DFFd * Hd;
        // fused distance-bias
        distrow_kernel<<<dim3(4, Bn), 256, DR_SMEM>>>(zh, mask);
        // fused QKV GEMM into per-head layouts
        gemm_h_kernel<<<dim3(H3 / 128, Mrows / 128), 256, GK_SMEM_B>>>(
            zh, Hd, wqkvT + (size_t)l * H3 * Hd, Hd, bqkv + (size_t)l * H3,
            nullptr, nullptr, 0, Hd, 0, 3);
        // attention
        qksm_kernel<<<dim3(4, Bn * NHd), 256, QS_SMEM>>>(qhp, khp);
        attnv_h_kernel<<<dim3(2, Bn * NHd), 128, AV_SMEM>>>();
        // Wo projection fused with AddNorm1  -> x1, x1h
        gemmln_kernel<<<Mrows / 64, 512, GL_SMEM>>>(
            yh, Hd, woTh + wofs, bo + (size_t)l * Hd, z,
            g1 + (size_t)l * Hd, be1 + (size_t)l * Hd, x1, x1h, nullptr, Hd);
        // FFN1
        gemm_h_kernel<<<dim3(DFFd / 128, Mrows / 128), 256, GK_SMEM_B>>>(
            x1h, Hd, w1Th + w1ofs, Hd, b1 + (size_t)l * DFFd,
            nullptr, ffnh, DFFd, Hd, 1, 0);
        // FFN2 fused with AddNorm2 + next-layer sq-norms -> z, zh
        gemmln_kernel<<<Mrows / 64, 512, GL_SMEM>>>(
            ffnh, DFFd, w2Th + w1ofs, b2 + (size_t)l * Hd, x1,
            g2 + (size_t)l * Hd, be2 + (size_t)l * Hd, z, zh, sq, DFFd);
    }

    // outputs: [X_out | E_out | z_out]
    const size_t XTOT = (size_t)Bn * Nn * XDim;
    const size_t ETOT = (size_t)Bn * Nn * Nn * EDim;
    const size_t ZTOT = (size_t)Mrows * Hd;
    out_x_kernel<<<(unsigned)((XTOT + 255) / 256), 256>>>(x, mask, out);
    out_e_kernel<<<(unsigned)((ETOT + 255) / 256), 256>>>(e, mask, out + XTOT);
    out_z_kernel<<<(unsigned)((ZTOT + 255) / 256), 256>>>(mask, out + XTOT + ETOT);
    (void)in_sizes; (void)n_in; (void)out_size;
}

// round 13
// speedup vs baseline: 1.1449x; 1.1449x over previous
#include <cuda_runtime.h>
#include <cuda_fp16.h>
#include <math.h>
#include <stdint.h>

#define Bn    64
#define Nn    256
#define XDim  118
#define EDim  5
#define Hd    384
#define NHd   8
#define DHd   48
#define DFFd  1536
#define DEPTH 6
#define Mrows (Bn * Nn)            /* 16384 */
#define KCAT  (XDim + Nn * EDim)   /* 1398  */
#define KPAD  1408
#define EROW  (Nn * EDim)
#define H3    (3 * Hd)             /* 1152 */

// ---------------- scratch (device globals; zero-init, no allocation) ----------------
__device__ __half g_cath[(size_t)Mrows * KPAD];
__device__ float  g_z  [(size_t)Mrows * Hd];
__device__ __half g_zh [(size_t)Mrows * Hd];
__device__ float  g_q  [(size_t)Mrows * Hd];
__device__ __half g_yh [(size_t)Mrows * Hd];
__device__ float  g_x1 [(size_t)Mrows * Hd];
__device__ __half g_x1h[(size_t)Mrows * Hd];
__device__ __half g_ffnh[(size_t)Mrows * DFFd];
__device__ float  g_D  [(size_t)Bn * Nn * Nn];
__device__ float  g_sq [Mrows];
// per-head padded Q/K: [b,h,256,64] (cols 48..63 stay zero)
__device__ __half g_qhp[(size_t)Bn * NHd * Nn * 64];
__device__ __half g_khp[(size_t)Bn * NHd * Nn * 64];
// per-head transposed V: [b,h,48,256]
__device__ __half g_vth[(size_t)Bn * NHd * DHd * Nn];
// transposed fp16 weights [N][K]
__device__ __half g_wembTh[(size_t)Hd * KPAD];
__device__ __half g_wqkvT[(size_t)DEPTH * H3 * Hd];
__device__ float  g_bqkv [(size_t)DEPTH * H3];
__device__ __half g_woTh [(size_t)DEPTH * Hd * Hd];
__device__ __half g_w1Th [(size_t)DEPTH * DFFd * Hd];
__device__ __half g_w2Th [(size_t)DEPTH * Hd * DFFd];

// ---------------- PTX helpers (sm_80+ base ISA) ----------------
__device__ __forceinline__ uint32_t smem_to_u32(const void* p) {
    uint32_t a;
    asm("{ .reg .u64 t; cvta.to.shared.u64 t, %1; cvt.u32.u64 %0, t; }"
        : "=r"(a) : "l"(p));
    return a;
}
#define CP_ASYNC16(dst, src) \
    asm volatile("cp.async.cg.shared.global [%0], [%1], 16;" \
                 :: "r"(dst), "l"(src) : "memory")
#define CP_COMMIT() asm volatile("cp.async.commit_group;" ::: "memory")
#define CP_WAIT1()  asm volatile("cp.async.wait_group 1;" ::: "memory")
#define CP_WAIT0()  asm volatile("cp.async.wait_group 0;" ::: "memory")
#define LDSM4(r, addr) \
    asm volatile("ldmatrix.sync.aligned.m8n8.x4.shared.b16 {%0,%1,%2,%3}, [%4];" \
                 : "=r"((r)[0]), "=r"((r)[1]), "=r"((r)[2]), "=r"((r)[3]) \
                 : "r"(addr))
#define MMA16816(d, a, b0_, b1_) \
    asm volatile("mma.sync.aligned.m16n8k16.row.col.f32.f16.f16.f32 " \
                 "{%0,%1,%2,%3}, {%4,%5,%6,%7}, {%8,%9}, {%0,%1,%2,%3};" \
                 : "+f"((d)[0]), "+f"((d)[1]), "+f"((d)[2]), "+f"((d)[3]) \
                 : "r"((a)[0]), "r"((a)[1]), "r"((a)[2]), "r"((a)[3]), \
                   "r"(b0_), "r"(b1_))

// ---------------- reductions ----------------
__device__ __forceinline__ float blocksum128(float v) {
    __shared__ float red[4];
    #pragma unroll
    for (int o = 16; o > 0; o >>= 1) v += __shfl_xor_sync(0xffffffffu, v, o);
    if ((threadIdx.x & 31) == 0) red[threadIdx.x >> 5] = v;
    __syncthreads();
    float s = red[0] + red[1] + red[2] + red[3];
    __syncthreads();
    return s;
}

// ---------------- concat [x | e_flat | 0-pad] -> fp16 ----------------
__global__ void cat_kernel(const float* __restrict__ x, const float* __restrict__ e) {
    size_t idx = (size_t)blockIdx.x * blockDim.x + threadIdx.x;
    if (idx >= (size_t)Mrows * KPAD) return;
    size_t r = idx / KPAD;
    int    c = (int)(idx - r * KPAD);
    float v;
    if (c < XDim)      v = x[r * XDim + c];
    else if (c < KCAT) v = e[r * (size_t)EROW + (c - XDim)];
    else               v = 0.f;
    g_cath[idx] = __float2half(v);
}

// ---------------- transpose fp32 -> fp16 ----------------
__global__ void transpose_kernel(const float* __restrict__ in, __half* __restrict__ out,
                                 int R, int C, int outLd,
                                 size_t inStride, size_t outStride) {
    __shared__ float tile[32][33];
    const float* ip = in + (size_t)blockIdx.z * inStride;
    __half* op = out + (size_t)blockIdx.z * outStride;
    int c0 = blockIdx.x * 32, r0 = blockIdx.y * 32;
    int tx = threadIdx.x, ty = threadIdx.y;
    #pragma unroll
    for (int i = 0; i < 32; i += 8) {
        int r = r0 + ty + i, c = c0 + tx;
        tile[ty + i][tx] = (r < R && c < C) ? ip[(size_t)r * C + c] : 0.f;
    }
    __syncthreads();
    #pragma unroll
    for (int i = 0; i < 32; i += 8) {
        int oc = c0 + ty + i, orow = r0 + tx;
        if (oc < C && orow < outLd)
            op[(size_t)oc * outLd + orow] = __float2half(tile[tx][ty + i]);
    }
}

// ---------------- concat qkv bias ----------------
__global__ void qkvbias_kernel(const float* __restrict__ bq, const float* __restrict__ bk,
                               const float* __restrict__ bv) {
    int i = blockIdx.x * blockDim.x + threadIdx.x;
    if (i >= DEPTH * H3) return;
    int l = i / H3, r = i - l * H3;
    float v;
    if (r < Hd)           v = bq[l * Hd + r];
    else if (r < 2 * Hd)  v = bk[l * Hd + r - Hd];
    else                  v = bv[l * Hd + r - 2 * Hd];
    g_bqkv[i] = v;
}

// ============================================================================
// fp16 HMMA GEMM, 128x128x32 tiles, 8 warps, 3-stage cp.async.
// mode 0: C fp32 (+Ch fp16 row-major)
// mode 3: fused QKV -> qhp/khp/vth head layouts (N = 1152)
// ============================================================================
#define GK_RS      40
#define GK_OPB     (128 * GK_RS * 2)
#define GK_STAGE_B (2 * GK_OPB)
#define GK_SMEM_B  (3 * GK_STAGE_B)

__global__ __launch_bounds__(256)
void gemm_h_kernel(const __half* __restrict__ A, int lda,
                   const __half* __restrict__ BT, int ldb,
                   const float* __restrict__ bias,
                   float* __restrict__ C, __half* __restrict__ Ch,
                   int ldc, int K, int relu, int mode) {
    extern __shared__ char smem[];
    const uint32_t sb = smem_to_u32(smem);
    const int t = threadIdx.x, lane = t & 31, wid = t >> 5;
    const int m0 = blockIdx.y * 128, n0 = blockIdx.x * 128;
    const int mW = (wid & 3) * 32, nW = (wid >> 2) * 64;

    const int r0 = t >> 2,          q0 = t & 3;
    const int r1 = (t + 256) >> 2,  q1 = (t + 256) & 3;
    const int lq = lane >> 3, lr = lane & 7;
    const int aRow = (lq & 1) * 8 + lr, aCol = (lq >> 1) * 8;
    const int bRow = (lq >> 1) * 8 + lr, bCol = (lq & 1) * 8;
    const uint32_t aOff = (uint32_t)(((mW + aRow) * GK_RS + aCol) * 2);
    const uint32_t bOff = (uint32_t)(GK_OPB + ((nW + bRow) * GK_RS + bCol) * 2);

    float acc[2][8][4];
    #pragma unroll
    for (int i = 0; i < 2; i++)
        #pragma unroll
        for (int j = 0; j < 8; j++)
            #pragma unroll
            for (int r = 0; r < 4; r++) acc[i][j][r] = 0.f;

    const int nch = K >> 5;
    auto issue = [&](int ch) {
        const uint32_t dstA = sb + (uint32_t)(ch % 3) * GK_STAGE_B;
        const uint32_t dstB = dstA + GK_OPB;
        const __half* sa  = A  + (size_t)m0 * lda + ch * 32;
        const __half* sbp = BT + (size_t)n0 * ldb + ch * 32;
        CP_ASYNC16(dstA + (uint32_t)((r0 * GK_RS + q0 * 8) * 2), sa  + (size_t)r0 * lda + q0 * 8);
        CP_ASYNC16(dstA + (uint32_t)((r1 * GK_RS + q1 * 8) * 2), sa  + (size_t)r1 * lda + q1 * 8);
        CP_ASYNC16(dstB + (uint32_t)((r0 * GK_RS + q0 * 8) * 2), sbp + (size_t)r0 * ldb + q0 * 8);
        CP_ASYNC16(dstB + (uint32_t)((r1 * GK_RS + q1 * 8) * 2), sbp + (size_t)r1 * ldb + q1 * 8);
        CP_COMMIT();
    };
    issue(0);
    issue(1);

    for (int ch = 0; ch < nch; ch++) {
        if (ch + 1 < nch) { CP_WAIT1(); } else { CP_WAIT0(); }
        __syncthreads();
        const uint32_t base = sb + (uint32_t)(ch % 3) * GK_STAGE_B;
        #pragma unroll
        for (int ks = 0; ks < 2; ks++) {
            uint32_t a[2][4], b[4][4];
            #pragma unroll
            for (int mt = 0; mt < 2; mt++)
                LDSM4(a[mt], base + aOff + (uint32_t)((mt * 16 * GK_RS + ks * 16) * 2));
            #pragma unroll
            for (int g = 0; g < 4; g++)
                LDSM4(b[g], base + bOff + (uint32_t)((g * 16 * GK_RS + ks * 16) * 2));
            #pragma unroll
            for (int mt = 0; mt < 2; mt++)
                #pragma unroll
                for (int g = 0; g < 4; g++) {
                    MMA16816(acc[mt][2 * g],     a[mt], b[g][0], b[g][1]);
                    MMA16816(acc[mt][2 * g + 1], a[mt], b[g][2], b[g][3]);
                }
        }
        if (ch + 2 < nch) issue(ch + 2);
    }

    const int rBase = m0 + mW + (lane >> 2);
    const int cBase = n0 + nW + (lane & 3) * 2;
    #pragma unroll
    for (int mt = 0; mt < 2; mt++) {
        #pragma unroll
        for (int nt = 0; nt < 8; nt++) {
            const int c = cBase + nt * 8;
            float b0 = 0.f, b1 = 0.f;
            if (bias) { b0 = bias[c]; b1 = bias[c + 1]; }
            float v00 = acc[mt][nt][0] + b0, v01 = acc[mt][nt][1] + b1;
            float v10 = acc[mt][nt][2] + b0, v11 = acc[mt][nt][3] + b1;
            if (relu) {
                v00 = fmaxf(v00, 0.f); v01 = fmaxf(v01, 0.f);
                v10 = fmaxf(v10, 0.f); v11 = fmaxf(v11, 0.f);
            }
            const int rA = rBase + mt * 16, rB = rA + 8;
            if (mode == 0) {
                if (C) {
                    *(float2*)(C + (size_t)rA * ldc + c) = make_float2(v00, v01);
                    *(float2*)(C + (size_t)rB * ldc + c) = make_float2(v10, v11);
                }
                if (Ch) {
                    *(__half2*)(Ch + (size_t)rA * ldc + c) = __floats2half2_rn(v00, v01);
                    *(__half2*)(Ch + (size_t)rB * ldc + c) = __floats2half2_rn(v10, v11);
                }
            } else {
                const int sec = c / Hd;
                const int cc  = c - sec * Hd;
                const int h = cc / DHd, d = cc - h * DHd;
                const int bIdx = rA >> 8;
                if (sec < 2) {
                    __half* dst = (sec == 0) ? g_qhp : g_khp;
                    size_t p0 = ((((size_t)bIdx * NHd + h) << 8) | (rA & 255)) * 64 + d;
                    size_t p1 = ((((size_t)bIdx * NHd + h) << 8) | (rB & 255)) * 64 + d;
                    *(__half2*)(dst + p0) = __floats2half2_rn(v00, v01);
                    *(__half2*)(dst + p1) = __floats2half2_rn(v10, v11);
                } else {
                    size_t hb = ((size_t)bIdx * NHd + h) * DHd;
                    g_vth[(hb + d)     * Nn + (rA & 255)] = __float2half(v00);
                    g_vth[(hb + d + 1) * Nn + (rA & 255)] = __float2half(v01);
                    g_vth[(hb + d)     * Nn + (rB & 255)] = __float2half(v10);
                    g_vth[(hb + d + 1) * Nn + (rB & 255)] = __float2half(v11);
                }
            }
        }
    }
}

// ============================================================================
// distrow: fused gram(zh) + sqrt + mask + rowmax-bias -> g_D. 64m x 256n, K=384.
// ============================================================================
#define DR_ARS   40
#define DR_ABUF  (64 * DR_ARS * 2)
#define DR_BBUF  (256 * DR_ARS * 2)
#define DR_STAGE (DR_ABUF + DR_BBUF)
#define DR_RED   (3 * DR_STAGE)
#define DR_SMEM  (DR_RED + 128 * 4)

__global__ __launch_bounds__(256)
void distrow_kernel(const __half* __restrict__ Z, const float* __restrict__ mask) {
    extern __shared__ char smem[];
    const uint32_t sb = smem_to_u32(smem);
    float* rmax = (float*)(smem + DR_RED);
    const int t = threadIdx.x, lane = t & 31, wid = t >> 5;
    const int bz = blockIdx.y, m0 = blockIdx.x * 64;
    const __half* A = Z + (size_t)bz * Nn * Hd + (size_t)m0 * Hd;
    const __half* B = Z + (size_t)bz * Nn * Hd;
    const int mW = (wid & 3) * 16, nW = (wid >> 2) * 128;

    const int lq = lane >> 3, lr = lane & 7;
    const int aRow = (lq & 1) * 8 + lr, aCol = (lq >> 1) * 8;
    const int bRow = (lq >> 1) * 8 + lr, bCol = (lq & 1) * 8;
    const uint32_t aOff = (uint32_t)(((mW + aRow) * DR_ARS + aCol) * 2);
    const uint32_t bOff = (uint32_t)(DR_ABUF + ((nW + bRow) * DR_ARS + bCol) * 2);

    float acc[16][4];
    #pragma unroll
    for (int j = 0; j < 16; j++)
        #pragma unroll
        for (int r = 0; r < 4; r++) acc[j][r] = 0.f;

    auto issue = [&](int ch) {
        const uint32_t dstA = sb + (uint32_t)(ch % 3) * DR_STAGE;
        const uint32_t dstB = dstA + DR_ABUF;
        CP_ASYNC16(dstA + (uint32_t)(((t >> 2) * DR_ARS + (t & 3) * 8) * 2),
                   A + (size_t)(t >> 2) * Hd + ch * 32 + (t & 3) * 8);
        #pragma unroll
        for (int u = 0; u < 4; u++) {
            int p = t + u * 256, row = p >> 2, seg = p & 3;
            CP_ASYNC16(dstB + (uint32_t)((row * DR_ARS + seg * 8) * 2),
                       B + (size_t)row * Hd + ch * 32 + seg * 8);
        }
        CP_COMMIT();
    };
    issue(0);
    issue(1);

    const int nch = Hd >> 5;
    for (int ch = 0; ch < nch; ch++) {
        if (ch + 1 < nch) { CP_WAIT1(); } else { CP_WAIT0(); }
        __syncthreads();
        const uint32_t base = sb + (uint32_t)(ch % 3) * DR_STAGE;
        #pragma unroll
        for (int ks = 0; ks < 2; ks++) {
            uint32_t a[4];
            LDSM4(a, base + aOff + (uint32_t)(ks * 16 * 2));
            #pragma unroll
            for (int g = 0; g < 8; g++) {
                uint32_t bf[4];
                LDSM4(bf, base + bOff + (uint32_t)((g * 16 * DR_ARS + ks * 16) * 2));
                MMA16816(acc[2 * g],     a, bf[0], bf[1]);
                MMA16816(acc[2 * g + 1], a, bf[2], bf[3]);
            }
        }
        if (ch + 2 < nch) issue(ch + 2);
    }

    const int rloc0 = mW + (lane >> 2), rloc1 = rloc0 + 8;
    const int gi0 = m0 + rloc0, gi1 = m0 + rloc1;
    const int cB = nW + (lane & 3) * 2;
    const float sqi0 = g_sq[bz * Nn + gi0], sqi1 = g_sq[bz * Nn + gi1];
    const float mi0 = mask[bz * Nn + gi0],  mi1 = mask[bz * Nn + gi1];
    #pragma unroll
    for (int nt = 0; nt < 16; nt++) {
        const int gj = cB + nt * 8;
        float sj0 = g_sq[bz * Nn + gj], sj1 = g_sq[bz * Nn + gj + 1];
        float mj0 = mask[bz * Nn + gj], mj1 = mask[bz * Nn + gj + 1];
        float d2;
        d2 = fmaxf(sqi0 + sj0 - 2.f * acc[nt][0], 0.f);
        acc[nt][0] = ((d2 > 1e-12f) ? sqrtf(d2) : 0.f) * mi0 * mj0;
        d2 = fmaxf(sqi0 + sj1 - 2.f * acc[nt][1], 0.f);
        acc[nt][1] = ((d2 > 1e-12f) ? sqrtf(d2) : 0.f) * mi0 * mj1;
        d2 = fmaxf(sqi1 + sj0 - 2.f * acc[nt][2], 0.f);
        acc[nt][2] = ((d2 > 1e-12f) ? sqrtf(d2) : 0.f) * mi1 * mj0;
        d2 = fmaxf(sqi1 + sj1 - 2.f * acc[nt][3], 0.f);
        acc[nt][3] = ((d2 > 1e-12f) ? sqrtf(d2) : 0.f) * mi1 * mj1;
    }
    float mx0 = 0.f, mx1 = 0.f;
    #pragma unroll
    for (int nt = 0; nt < 16; nt++) {
        mx0 = fmaxf(mx0, fmaxf(acc[nt][0], acc[nt][1]));
        mx1 = fmaxf(mx1, fmaxf(acc[nt][2], acc[nt][3]));
    }
    #pragma unroll
    for (int o = 1; o < 4; o <<= 1) {
        mx0 = fmaxf(mx0, __shfl_xor_sync(0xffffffffu, mx0, o));
        mx1 = fmaxf(mx1, __shfl_xor_sync(0xffffffffu, mx1, o));
    }
    const int nw = wid >> 2;
    rmax[nw * 64 + rloc0] = mx0;
    rmax[nw * 64 + rloc1] = mx1;
    __syncthreads();
    const float M0 = fmaxf(rmax[rloc0], rmax[64 + rloc0]);
    const float M1 = fmaxf(rmax[rloc1], rmax[64 + rloc1]);
    float* Dp = g_D + (size_t)bz * Nn * Nn;
    #pragma unroll
    for (int nt = 0; nt < 16; nt++) {
        const int gj = cB + nt * 8;
        float mj0 = mask[bz * Nn + gj], mj1 = mask[bz * Nn + gj + 1];
        float o00 = (gi0 == gj)     ? 0.f : (M0 - acc[nt][0]) * mi0 * mj0;
        float o01 = (gi0 == gj + 1) ? 0.f : (M0 - acc[nt][1]) * mi0 * mj1;
        float o10 = (gi1 == gj)     ? 0.f : (M1 - acc[nt][2]) * mi1 * mj0;
        float o11 = (gi1 == gj + 1) ? 0.f : (M1 - acc[nt][3]) * mi1 * mj1;
        *(float2*)(Dp + (size_t)gi0 * Nn + gj) = make_float2(o00, o01);
        *(float2*)(Dp + (size_t)gi1 * Nn + gj) = make_float2(o10, o11);
    }
}

// ============================================================================
// attn: fully fused QK^T + D-bias + softmax + P@V^T per head.
// Tile 64 q-rows x full 256 kv, K=64; then AV 64m x 48n x 256k from smem.
// 256 threads. smem: Q(64x72) K(256x72) P(64x264) V(48x264) + red.
// ============================================================================
#define AT_ARS   72
#define AT_PRS   264
#define AT_QBUF  0
#define AT_KBUF  (64 * AT_ARS * 2)                   /*  9216 */
#define AT_PBUF  (AT_KBUF + 256 * AT_ARS * 2)        /* 46080 */
#define AT_VBUF  (AT_PBUF + 64 * AT_PRS * 2)         /* 79872 */
#define AT_RED   (AT_VBUF + 48 * AT_PRS * 2)         /* 105216 */
#define AT_SMEM  (AT_RED + 2 * 128 * 4)              /* 106240 */

__global__ __launch_bounds__(256)
void attn_kernel(const __half* __restrict__ qhp, const __half* __restrict__ khp) {
    extern __shared__ char smem[];
    const uint32_t sb = smem_to_u32(smem);
    float* rmax = (float*)(smem + AT_RED);
    float* rsum = rmax + 128;
    const int t = threadIdx.x, lane = t & 31, wid = t >> 5;
    const int bh = blockIdx.y, m0 = blockIdx.x * 64;
    const int b = bh >> 3, h = bh & 7;
    const __half* Aq = qhp + (size_t)bh * Nn * 64 + (size_t)m0 * 64;
    const __half* Bk = khp + (size_t)bh * Nn * 64;
    const __half* Vt = g_vth + (size_t)bh * DHd * Nn;
    const int mW = (wid & 3) * 16, nW = (wid >> 2) * 128;

    // stage Q(64x64), K(256x64), V(48x256) in one group
    #pragma unroll
    for (int u = 0; u < 2; u++) {
        int p = t + u * 256, row = p >> 3, seg = p & 7;
        CP_ASYNC16(sb + AT_QBUF + (uint32_t)((row * AT_ARS + seg * 8) * 2),
                   Aq + (size_t)row * 64 + seg * 8);
    }
    #pragma unroll
    for (int u = 0; u < 8; u++) {
        int p = t + u * 256, row = p >> 3, seg = p & 7;
        CP_ASYNC16(sb + AT_KBUF + (uint32_t)((row * AT_ARS + seg * 8) * 2),
                   Bk + (size_t)row * 64 + seg * 8);
    }
    #pragma unroll
    for (int u = 0; u < 6; u++) {
        int p = t + u * 256, row = p >> 5, seg = p & 31;
        CP_ASYNC16(sb + AT_VBUF + (uint32_t)((row * AT_PRS + seg * 8) * 2),
                   Vt + (size_t)row * Nn + seg * 8);
    }
    CP_COMMIT();
    CP_WAIT0();
    __syncthreads();

    const int lq = lane >> 3, lr = lane & 7;
    const int aRow = (lq & 1) * 8 + lr, aCol = (lq >> 1) * 8;
    const int bRow = (lq >> 1) * 8 + lr, bCol = (lq & 1) * 8;
    const uint32_t aOff = sb + AT_QBUF + (uint32_t)(((mW + aRow) * AT_ARS + aCol) * 2);
    const uint32_t bOff = sb + AT_KBUF + (uint32_t)(((nW + bRow) * AT_ARS + bCol) * 2);

    float acc[16][4];
    #pragma unroll
    for (int j = 0; j < 16; j++)
        #pragma unroll
        for (int r = 0; r < 4; r++) acc[j][r] = 0.f;

    #pragma unroll
    for (int ks = 0; ks < 4; ks++) {
        uint32_t a[4];
        LDSM4(a, aOff + (uint32_t)(ks * 16 * 2));
        #pragma unroll
        for (int g = 0; g < 8; g++) {
            uint32_t bf[4];
            LDSM4(bf, bOff + (uint32_t)((g * 16 * AT_ARS + ks * 16) * 2));
            MMA16816(acc[2 * g],     a, bf[0], bf[1]);
            MMA16816(acc[2 * g + 1], a, bf[2], bf[3]);
        }
    }

    // bias + softmax (fp32, in registers)
    const float scale = 0.144337567297406441f;
    const int rloc0 = mW + (lane >> 2), rloc1 = rloc0 + 8;
    const int gi0 = m0 + rloc0, gi1 = m0 + rloc1;
    const int cB = nW + (lane & 3) * 2;
    #pragma unroll
    for (int nt = 0; nt < 16; nt++) {
        const int gj = cB + nt * 8;
        float2 d0 = *(const float2*)(g_D + ((size_t)b * Nn + gi0) * Nn + gj);
        float2 d1 = *(const float2*)(g_D + ((size_t)b * Nn + gi1) * Nn + gj);
        acc[nt][0] = acc[nt][0] * scale + d0.x;
        acc[nt][1] = acc[nt][1] * scale + d0.y;
        acc[nt][2] = acc[nt][2] * scale + d1.x;
        acc[nt][3] = acc[nt][3] * scale + d1.y;
    }
    float mx0 = -1e30f, mx1 = -1e30f;
    #pragma unroll
    for (int nt = 0; nt < 16; nt++) {
        mx0 = fmaxf(mx0, fmaxf(acc[nt][0], acc[nt][1]));
        mx1 = fmaxf(mx1, fmaxf(acc[nt][2], acc[nt][3]));
    }
    #pragma unroll
    for (int o = 1; o < 4; o <<= 1) {
        mx0 = fmaxf(mx0, __shfl_xor_sync(0xffffffffu, mx0, o));
        mx1 = fmaxf(mx1, __shfl_xor_sync(0xffffffffu, mx1, o));
    }
    const int nwg = wid >> 2;
    rmax[nwg * 64 + rloc0] = mx0;
    rmax[nwg * 64 + rloc1] = mx1;
    __syncthreads();
    const float M0 = fmaxf(rmax[rloc0], rmax[64 + rloc0]);
    const float M1 = fmaxf(rmax[rloc1], rmax[64 + rloc1]);
    float s0 = 0.f, s1 = 0.f;
    #pragma unroll
    for (int nt = 0; nt < 16; nt++) {
        acc[nt][0] = __expf(acc[nt][0] - M0);
        acc[nt][1] = __expf(acc[nt][1] - M0);
        acc[nt][2] = __expf(acc[nt][2] - M1);
        acc[nt][3] = __expf(acc[nt][3] - M1);
        s0 += acc[nt][0] + acc[nt][1];
        s1 += acc[nt][2] + acc[nt][3];
    }
    #pragma unroll
    for (int o = 1; o < 4; o <<= 1) {
        s0 += __shfl_xor_sync(0xffffffffu, s0, o);
        s1 += __shfl_xor_sync(0xffffffffu, s1, o);
    }
    rsum[nwg * 64 + rloc0] = s0;
    rsum[nwg * 64 + rloc1] = s1;
    __syncthreads();
    const float inv0 = 1.f / (rsum[rloc0] + rsum[64 + rloc0]);
    const float inv1 = 1.f / (rsum[rloc1] + rsum[64 + rloc1]);
    // write fp16 probs to smem P buf (local rows)
    #pragma unroll
    for (int nt = 0; nt < 16; nt++) {
        const int gj = cB + nt * 8;
        *(__half2*)(smem + AT_PBUF + ((size_t)rloc0 * AT_PRS + gj) * 2) =
            __floats2half2_rn(acc[nt][0] * inv0, acc[nt][1] * inv0);
        *(__half2*)(smem + AT_PBUF + ((size_t)rloc1 * AT_PRS + gj) * 2) =
            __floats2half2_rn(acc[nt][2] * inv1, acc[nt][3] * inv1);
    }
    __syncthreads();

    // AV phase: warps 0-3, warp tile 16m x 48n, K=256 from smem
    if (wid < 4) {
        const int mW2 = wid * 16;
        const uint32_t pOff = sb + AT_PBUF + (uint32_t)(((mW2 + aRow) * AT_PRS + aCol) * 2);
        const uint32_t vOff = sb + AT_VBUF + (uint32_t)((bRow * AT_PRS + bCol) * 2);
        float av[6][4];
        #pragma unroll
        for (int j = 0; j < 6; j++)
            #pragma unroll
            for (int r = 0; r < 4; r++) av[j][r] = 0.f;
        #pragma unroll
        for (int ks = 0; ks < 16; ks++) {
            uint32_t a[4];
            LDSM4(a, pOff + (uint32_t)(ks * 16 * 2));
            #pragma unroll
            for (int g = 0; g < 3; g++) {
                uint32_t bf[4];
                LDSM4(bf, vOff + (uint32_t)((g * 16 * AT_PRS + ks * 16) * 2));
                MMA16816(av[2 * g],     a, bf[0], bf[1]);
                MMA16816(av[2 * g + 1], a, bf[2], bf[3]);
            }
        }
        const int rA = m0 + mW2 + (lane >> 2);
        const int cBase = (lane & 3) * 2;
        #pragma unroll
        for (int nt = 0; nt < 6; nt++) {
            const int c = cBase + nt * 8;
            *(__half2*)(g_yh + ((size_t)b * Nn + rA) * Hd + h * DHd + c) =
                __floats2half2_rn(av[nt][0], av[nt][1]);
            *(__half2*)(g_yh + ((size_t)b * Nn + rA + 8) * Hd + h * DHd + c) =
                __floats2half2_rn(av[nt][2], av[nt][3]);
        }
    }
}

// ---------------- row squared norms of z (post-embed only) ----------------
__global__ void sqnorm_kernel() {
    int r = blockIdx.x;
    float s = 0.f;
    for (int c = threadIdx.x; c < Hd; c += 128) {
        float v = g_z[(size_t)r * Hd + c];
        s += v * v;
    }
    s = blocksum128(s);
    if (threadIdx.x == 0) g_sq[r] = s;
}

// ---------------- out = LayerNorm(a + r); optional sq-norm of out ----------------
__global__ void addln_kernel(const float* __restrict__ a, const float* __restrict__ r,
                             const float* __restrict__ g, const float* __restrict__ be,
                             float* __restrict__ out, __half* __restrict__ outh,
                             float* __restrict__ sqout) {
    int row = blockIdx.x;
    int t = threadIdx.x;
    float vals[3];
    float s = 0.f;
    #pragma unroll
    for (int u = 0; u < 3; u++) {
        int c = t + u * 128;
        float v = a[(size_t)row * Hd + c] + r[(size_t)row * Hd + c];
        vals[u] = v;
        s += v;
    }
    float mu = blocksum128(s) * (1.f / Hd);
    float s2 = 0.f;
    #pragma unroll
    for (int u = 0; u < 3; u++) { float d = vals[u] - mu; s2 += d * d; }
    float var  = blocksum128(s2) * (1.f / Hd);
    float rstd = rsqrtf(var + 1e-5f);
    float s3 = 0.f;
    #pragma unroll
    for (int u = 0; u < 3; u++) {
        int c = t + u * 128;
        float o = (vals[u] - mu) * rstd * g[c] + be[c];
        out[(size_t)row * Hd + c]  = o;
        outh[(size_t)row * Hd + c] = __float2half(o);
        s3 += o * o;
    }
    if (sqout) {
        s3 = blocksum128(s3);
        if (t == 0) sqout[row] = s3;
    }
}

// ---------------- masked outputs ----------------
__global__ void out_x_kernel(const float* __restrict__ x, const float* __restrict__ mask,
                             float* __restrict__ out) {
    size_t idx = (size_t)blockIdx.x * blockDim.x + threadIdx.x;
    if (idx >= (size_t)Bn * Nn * XDim) return;
    out[idx] = x[idx] * mask[idx / XDim];
}
__global__ void out_e_kernel(const float* __restrict__ e, const float* __restrict__ mask,
                             float* __restrict__ out) {
    size_t idx = (size_t)blockIdx.x * blockDim.x + threadIdx.x;
    if (idx >= (size_t)Bn * Nn * Nn * EDim) return;
    size_t pair = idx / EDim;
    int j  = (int)(pair % Nn);
    size_t bi = pair / Nn;
    int b  = (int)(bi / Nn);
    out[idx] = e[idx] * mask[bi] * mask[(size_t)b * Nn + j];
}
__global__ void out_z_kernel(const float* __restrict__ mask, float* __restrict__ out) {
    size_t idx = (size_t)blockIdx.x * blockDim.x + threadIdx.x;
    if (idx >= (size_t)Mrows * Hd) return;
    out[idx] = g_z[idx] * mask[idx / Hd];
}

// ---------------- launcher ----------------
extern "C" void kernel_launch(void* const* d_in, const int* in_sizes, int n_in,
                              void* d_out, int out_size) {
    const float* x    = (const float*)d_in[0];
    const float* e    = (const float*)d_in[1];
    const float* mask = (const float*)d_in[2];
    const float* Wemb = (const float*)d_in[3];
    const float* Wq = (const float*)d_in[4];  const float* bq = (const float*)d_in[5];
    const float* Wk = (const float*)d_in[6];  const float* bk = (const float*)d_in[7];
    const float* Wv = (const float*)d_in[8];  const float* bv = (const float*)d_in[9];
    const float* Wo = (const float*)d_in[10]; const float* bo = (const float*)d_in[11];
    const float* g1 = (const float*)d_in[12]; const float* be1 = (const float*)d_in[13];
    const float* W1 = (const float*)d_in[14]; const float* b1  = (const float*)d_in[15];
    const float* W2 = (const float*)d_in[16]; const float* b2  = (const float*)d_in[17];
    const float* g2 = (const float*)d_in[18]; const float* be2 = (const float*)d_in[19];
    float* out = (float*)d_out;

    float  *z, *q, *x1, *sq, *bqkv;
    __half *cath, *zh, *x1h, *yh, *ffnh, *qhp, *khp;
    __half *wembTh, *wqkvT, *woTh, *w1Th, *w2Th;
    cudaGetSymbolAddress((void**)&cath,  g_cath);
    cudaGetSymbolAddress((void**)&z,     g_z);
    cudaGetSymbolAddress((void**)&zh,    g_zh);
    cudaGetSymbolAddress((void**)&q,     g_q);
    cudaGetSymbolAddress((void**)&yh,    g_yh);
    cudaGetSymbolAddress((void**)&x1,    g_x1);
    cudaGetSymbolAddress((void**)&x1h,   g_x1h);
    cudaGetSymbolAddress((void**)&ffnh,  g_ffnh);
    cudaGetSymbolAddress((void**)&qhp,   g_qhp);
    cudaGetSymbolAddress((void**)&khp,   g_khp);
    cudaGetSymbolAddress((void**)&sq,    g_sq);
    cudaGetSymbolAddress((void**)&bqkv,  g_bqkv);
    cudaGetSymbolAddress((void**)&wembTh, g_wembTh);
    cudaGetSymbolAddress((void**)&wqkvT, g_wqkvT);
    cudaGetSymbolAddress((void**)&woTh,  g_woTh);
    cudaGetSymbolAddress((void**)&w1Th,  g_w1Th);
    cudaGetSymbolAddress((void**)&w2Th,  g_w2Th);

    cudaFuncSetAttribute(gemm_h_kernel,
                         cudaFuncAttributeMaxDynamicSharedMemorySize, GK_SMEM_B);
    cudaFuncSetAttribute(distrow_kernel,
                         cudaFuncAttributeMaxDynamicSharedMemorySize, DR_SMEM);
    cudaFuncSetAttribute(attn_kernel,
                         cudaFuncAttributeMaxDynamicSharedMemorySize, AT_SMEM);

    dim3 tb(32, 8);
    {
        size_t tot = (size_t)Mrows * KPAD;
        cat_kernel<<<(unsigned)((tot + 255) / 256), 256>>>(x, e);
    }
    transpose_kernel<<<dim3(12, 44, 1), tb>>>(Wemb, wembTh, KCAT, Hd, KPAD, 0, 0);
    transpose_kernel<<<dim3(12, 12, DEPTH), tb>>>(Wq, wqkvT, Hd, Hd, Hd,
                                                  (size_t)Hd * Hd, (size_t)H3 * Hd);
    transpose_kernel<<<dim3(12, 12, DEPTH), tb>>>(Wk, wqkvT + (size_t)Hd * Hd, Hd, Hd, Hd,
                                                  (size_t)Hd * Hd, (size_t)H3 * Hd);
    transpose_kernel<<<dim3(12, 12, DEPTH), tb>>>(Wv, wqkvT + 2 * (size_t)Hd * Hd, Hd, Hd, Hd,
                                                  (size_t)Hd * Hd, (size_t)H3 * Hd);
    qkvbias_kernel<<<(DEPTH * H3 + 255) / 256, 256>>>(bq, bk, bv);
    gemm_h_kernel<<<dim3(Hd / 128, Mrows / 128), 256, GK_SMEM_B>>>(
        cath, KPAD, wembTh, KPAD, nullptr, z, zh, Hd, KPAD, 0, 0);
    transpose_kernel<<<dim3(12, 12, DEPTH), tb>>>(Wo, woTh, Hd, Hd, Hd,
                                                  (size_t)Hd * Hd, (size_t)Hd * Hd);
    transpose_kernel<<<dim3(48, 12, DEPTH), tb>>>(W1, w1Th, Hd, DFFd, Hd,
                                                  (size_t)Hd * DFFd, (size_t)DFFd * Hd);
    transpose_kernel<<<dim3(12, 48, DEPTH), tb>>>(W2, w2Th, DFFd, Hd, DFFd,
                                                  (size_t)DFFd * Hd, (size_t)Hd * DFFd);
    sqnorm_kernel<<<Mrows, 128>>>();

    for (int l = 0; l < DEPTH; l++) {
        const size_t wofs  = (size_t)l * Hd * Hd;
        const size_t w1ofs = (size_t)l * DFFd * Hd;
        // fused distance-bias
        distrow_kernel<<<dim3(4, Bn), 256, DR_SMEM>>>(zh, mask);
        // fused QKV GEMM into per-head layouts
        gemm_h_kernel<<<dim3(H3 / 128, Mrows / 128), 256, GK_SMEM_B>>>(
            zh, Hd, wqkvT + (size_t)l * H3 * Hd, Hd, bqkv + (size_t)l * H3,
            nullptr, nullptr, 0, Hd, 0, 3);
        // fully fused attention (QK^T + bias + softmax + AV)
        attn_kernel<<<dim3(4, Bn * NHd), 256, AT_SMEM>>>(qhp, khp);
        // output projection + AddNorm
        gemm_h_kernel<<<dim3(Hd / 128, Mrows / 128), 256, GK_SMEM_B>>>(
            yh, Hd, woTh + wofs, Hd, bo + (size_t)l * Hd, q, nullptr, Hd, Hd, 0, 0);
        addln_kernel<<<Mrows, 128>>>(z, q, g1 + (size_t)l * Hd, be1 + (size_t)l * Hd,
                                     x1, x1h, nullptr);
        // FFN
        gemm_h_kernel<<<dim3(DFFd / 128, Mrows / 128), 256, GK_SMEM_B>>>(
            x1h, Hd, w1Th + w1ofs, Hd, b1 + (size_t)l * DFFd,
            nullptr, ffnh, DFFd, Hd, 1, 0);
        gemm_h_kernel<<<dim3(Hd / 128, Mrows / 128), 256, GK_SMEM_B>>>(
            ffnh, DFFd, w2Th + w1ofs, DFFd, b2 + (size_t)l * Hd,
            q, nullptr, Hd, DFFd, 0, 0);
        addln_kernel<<<Mrows, 128>>>(x1, q, g2 + (size_t)l * Hd, be2 + (size_t)l * Hd,
                                     z, zh, sq);
    }

    // outputs: [X_out | E_out | z_out]
    const size_t XTOT = (size_t)Bn * Nn * XDim;
    const size_t ETOT = (size_t)Bn * Nn * Nn * EDim;
    const size_t ZTOT = (size_t)Mrows * Hd;
    out_x_kernel<<<(unsigned)((XTOT + 255) / 256), 256>>>(x, mask, out);
    out_e_kernel<<<(unsigned)((ETOT + 255) / 256), 256>>>(e, mask, out + XTOT);
    out_z_kernel<<<(unsigned)((ZTOT + 255) / 256), 256>>>(mask, out + XTOT + ETOT);
    (void)in_sizes; (void)n_in; (void)out_size;
}

// round 14
// speedup vs baseline: 1.1549x; 1.0087x over previous
#include <cuda_runtime.h>
#include <cuda_fp16.h>
#include <math.h>
#include <stdint.h>

#define Bn    64
#define Nn    256
#define XDim  118
#define EDim  5
#define Hd    384
#define NHd   8
#define DHd   48
#define DFFd  1536
#define DEPTH 6
#define Mrows (Bn * Nn)            /* 16384 */
#define KCAT  (XDim + Nn * EDim)   /* 1398  */
#define KPAD  1408
#define EROW  (Nn * EDim)
#define H3    (3 * Hd)             /* 1152 */

// ---------------- scratch (device globals; zero-init, no allocation) ----------------
__device__ __half g_cath[(size_t)Mrows * KPAD];
__device__ float  g_z  [(size_t)Mrows * Hd];
__device__ __half g_zh [(size_t)Mrows * Hd];
__device__ float  g_q  [(size_t)Mrows * Hd];
__device__ __half g_yh [(size_t)Mrows * Hd];
__device__ float  g_x1 [(size_t)Mrows * Hd];
__device__ __half g_x1h[(size_t)Mrows * Hd];
__device__ __half g_ffnh[(size_t)Mrows * DFFd];
__device__ float  g_D  [(size_t)Bn * Nn * Nn];
__device__ float  g_sq [Mrows];
// per-head padded Q/K: [b,h,256,64] (cols 48..63 stay zero)
__device__ __half g_qhp[(size_t)Bn * NHd * Nn * 64];
__device__ __half g_khp[(size_t)Bn * NHd * Nn * 64];
// per-head transposed V: [b,h,48,256]
__device__ __half g_vth[(size_t)Bn * NHd * DHd * Nn];
// transposed fp16 weights [N][K]
__device__ __half g_wembTh[(size_t)Hd * KPAD];
__device__ __half g_wqkvT[(size_t)DEPTH * H3 * Hd];
__device__ float  g_bqkv [(size_t)DEPTH * H3];
__device__ __half g_woTh [(size_t)DEPTH * Hd * Hd];
__device__ __half g_w1Th [(size_t)DEPTH * DFFd * Hd];
__device__ __half g_w2Th [(size_t)DEPTH * Hd * DFFd];

// ---------------- PTX helpers (sm_80+ base ISA) ----------------
__device__ __forceinline__ uint32_t smem_to_u32(const void* p) {
    uint32_t a;
    asm("{ .reg .u64 t; cvta.to.shared.u64 t, %1; cvt.u32.u64 %0, t; }"
        : "=r"(a) : "l"(p));
    return a;
}
#define CP_ASYNC16(dst, src) \
    asm volatile("cp.async.cg.shared.global [%0], [%1], 16;" \
                 :: "r"(dst), "l"(src) : "memory")
#define CP_COMMIT() asm volatile("cp.async.commit_group;" ::: "memory")
#define CP_WAIT2()  asm volatile("cp.async.wait_group 2;" ::: "memory")
#define CP_WAIT1()  asm volatile("cp.async.wait_group 1;" ::: "memory")
#define CP_WAIT0()  asm volatile("cp.async.wait_group 0;" ::: "memory")
#define LDSM4(r, addr) \
    asm volatile("ldmatrix.sync.aligned.m8n8.x4.shared.b16 {%0,%1,%2,%3}, [%4];" \
                 : "=r"((r)[0]), "=r"((r)[1]), "=r"((r)[2]), "=r"((r)[3]) \
                 : "r"(addr))
#define MMA16816(d, a, b0_, b1_) \
    asm volatile("mma.sync.aligned.m16n8k16.row.col.f32.f16.f16.f32 " \
                 "{%0,%1,%2,%3}, {%4,%5,%6,%7}, {%8,%9}, {%0,%1,%2,%3};" \
                 : "+f"((d)[0]), "+f"((d)[1]), "+f"((d)[2]), "+f"((d)[3]) \
                 : "r"((a)[0]), "r"((a)[1]), "r"((a)[2]), "r"((a)[3]), \
                   "r"(b0_), "r"(b1_))

// ---------------- reductions ----------------
__device__ __forceinline__ float blocksum128(float v) {
    __shared__ float red[4];
    #pragma unroll
    for (int o = 16; o > 0; o >>= 1) v += __shfl_xor_sync(0xffffffffu, v, o);
    if ((threadIdx.x & 31) == 0) red[threadIdx.x >> 5] = v;
    __syncthreads();
    float s = red[0] + red[1] + red[2] + red[3];
    __syncthreads();
    return s;
}
__device__ __forceinline__ float warpsum(float v) {
    #pragma unroll
    for (int o = 16; o > 0; o >>= 1) v += __shfl_xor_sync(0xffffffffu, v, o);
    return v;
}

// ---------------- concat [x | e_flat | 0-pad] -> fp16 ----------------
__global__ void cat_kernel(const float* __restrict__ x, const float* __restrict__ e) {
    size_t idx = (size_t)blockIdx.x * blockDim.x + threadIdx.x;
    if (idx >= (size_t)Mrows * KPAD) return;
    size_t r = idx / KPAD;
    int    c = (int)(idx - r * KPAD);
    float v;
    if (c < XDim)      v = x[r * XDim + c];
    else if (c < KCAT) v = e[r * (size_t)EROW + (c - XDim)];
    else               v = 0.f;
    g_cath[idx] = __float2half(v);
}

// ---------------- transpose fp32 -> fp16 ----------------
__global__ void transpose_kernel(const float* __restrict__ in, __half* __restrict__ out,
                                 int R, int C, int outLd,
                                 size_t inStride, size_t outStride) {
    __shared__ float tile[32][33];
    const float* ip = in + (size_t)blockIdx.z * inStride;
    __half* op = out + (size_t)blockIdx.z * outStride;
    int c0 = blockIdx.x * 32, r0 = blockIdx.y * 32;
    int tx = threadIdx.x, ty = threadIdx.y;
    #pragma unroll
    for (int i = 0; i < 32; i += 8) {
        int r = r0 + ty + i, c = c0 + tx;
        tile[ty + i][tx] = (r < R && c < C) ? ip[(size_t)r * C + c] : 0.f;
    }
    __syncthreads();
    #pragma unroll
    for (int i = 0; i < 32; i += 8) {
        int oc = c0 + ty + i, orow = r0 + tx;
        if (oc < C && orow < outLd)
            op[(size_t)oc * outLd + orow] = __float2half(tile[tx][ty + i]);
    }
}

// ---------------- concat qkv bias ----------------
__global__ void qkvbias_kernel(const float* __restrict__ bq, const float* __restrict__ bk,
                               const float* __restrict__ bv) {
    int i = blockIdx.x * blockDim.x + threadIdx.x;
    if (i >= DEPTH * H3) return;
    int l = i / H3, r = i - l * H3;
    float v;
    if (r < Hd)           v = bq[l * Hd + r];
    else if (r < 2 * Hd)  v = bk[l * Hd + r - Hd];
    else                  v = bv[l * Hd + r - 2 * Hd];
    g_bqkv[i] = v;
}

// ============================================================================
// fp16 HMMA GEMM, 128x128x32 tiles, 8 warps, 4-stage cp.async.
// mode 0: C fp32 (+Ch fp16 row-major)
// mode 3: fused QKV -> qhp/khp/vth head layouts (N = 1152)
// ============================================================================
#define GK_RS      40
#define GK_OPB     (128 * GK_RS * 2)
#define GK_STAGE_B (2 * GK_OPB)
#define GK_NSTG    4
#define GK_SMEM_B  (GK_NSTG * GK_STAGE_B)   /* 81920 */

__global__ __launch_bounds__(256)
void gemm_h_kernel(const __half* __restrict__ A, int lda,
                   const __half* __restrict__ BT, int ldb,
                   const float* __restrict__ bias,
                   float* __restrict__ C, __half* __restrict__ Ch,
                   int ldc, int K, int relu, int mode) {
    extern __shared__ char smem[];
    const uint32_t sb = smem_to_u32(smem);
    const int t = threadIdx.x, lane = t & 31, wid = t >> 5;
    const int m0 = blockIdx.y * 128, n0 = blockIdx.x * 128;
    const int mW = (wid & 3) * 32, nW = (wid >> 2) * 64;

    const int r0 = t >> 2,          q0 = t & 3;
    const int r1 = (t + 256) >> 2,  q1 = (t + 256) & 3;
    const int lq = lane >> 3, lr = lane & 7;
    const int aRow = (lq & 1) * 8 + lr, aCol = (lq >> 1) * 8;
    const int bRow = (lq >> 1) * 8 + lr, bCol = (lq & 1) * 8;
    const uint32_t aOff = (uint32_t)(((mW + aRow) * GK_RS + aCol) * 2);
    const uint32_t bOff = (uint32_t)(GK_OPB + ((nW + bRow) * GK_RS + bCol) * 2);

    float acc[2][8][4];
    #pragma unroll
    for (int i = 0; i < 2; i++)
        #pragma unroll
        for (int j = 0; j < 8; j++)
            #pragma unroll
            for (int r = 0; r < 4; r++) acc[i][j][r] = 0.f;

    const int nch = K >> 5;
    auto issue = [&](int ch) {
        const uint32_t dstA = sb + (uint32_t)(ch % GK_NSTG) * GK_STAGE_B;
        const uint32_t dstB = dstA + GK_OPB;
        const __half* sa  = A  + (size_t)m0 * lda + ch * 32;
        const __half* sbp = BT + (size_t)n0 * ldb + ch * 32;
        CP_ASYNC16(dstA + (uint32_t)((r0 * GK_RS + q0 * 8) * 2), sa  + (size_t)r0 * lda + q0 * 8);
        CP_ASYNC16(dstA + (uint32_t)((r1 * GK_RS + q1 * 8) * 2), sa  + (size_t)r1 * lda + q1 * 8);
        CP_ASYNC16(dstB + (uint32_t)((r0 * GK_RS + q0 * 8) * 2), sbp + (size_t)r0 * ldb + q0 * 8);
        CP_ASYNC16(dstB + (uint32_t)((r1 * GK_RS + q1 * 8) * 2), sbp + (size_t)r1 * ldb + q1 * 8);
        CP_COMMIT();
    };
    issue(0);
    if (nch > 1) issue(1);
    if (nch > 2) issue(2);

    for (int ch = 0; ch < nch; ch++) {
        const int rem = nch - 1 - ch;          // groups committed after this one
        if (rem >= 2)      { CP_WAIT2(); }
        else if (rem == 1) { CP_WAIT1(); }
        else               { CP_WAIT0(); }
        __syncthreads();
        const uint32_t base = sb + (uint32_t)(ch % GK_NSTG) * GK_STAGE_B;
        #pragma unroll
        for (int ks = 0; ks < 2; ks++) {
            uint32_t a[2][4], b[4][4];
            #pragma unroll
            for (int mt = 0; mt < 2; mt++)
                LDSM4(a[mt], base + aOff + (uint32_t)((mt * 16 * GK_RS + ks * 16) * 2));
            #pragma unroll
            for (int g = 0; g < 4; g++)
                LDSM4(b[g], base + bOff + (uint32_t)((g * 16 * GK_RS + ks * 16) * 2));
            #pragma unroll
            for (int mt = 0; mt < 2; mt++)
                #pragma unroll
                for (int g = 0; g < 4; g++) {
                    MMA16816(acc[mt][2 * g],     a[mt], b[g][0], b[g][1]);
                    MMA16816(acc[mt][2 * g + 1], a[mt], b[g][2], b[g][3]);
                }
        }
        if (ch + 3 < nch) issue(ch + 3);
    }

    const int rBase = m0 + mW + (lane >> 2);
    const int cBase = n0 + nW + (lane & 3) * 2;
    #pragma unroll
    for (int mt = 0; mt < 2; mt++) {
        #pragma unroll
        for (int nt = 0; nt < 8; nt++) {
            const int c = cBase + nt * 8;
            float b0 = 0.f, b1 = 0.f;
            if (bias) { b0 = bias[c]; b1 = bias[c + 1]; }
            float v00 = acc[mt][nt][0] + b0, v01 = acc[mt][nt][1] + b1;
            float v10 = acc[mt][nt][2] + b0, v11 = acc[mt][nt][3] + b1;
            if (relu) {
                v00 = fmaxf(v00, 0.f); v01 = fmaxf(v01, 0.f);
                v10 = fmaxf(v10, 0.f); v11 = fmaxf(v11, 0.f);
            }
            const int rA = rBase + mt * 16, rB = rA + 8;
            if (mode == 0) {
                if (C) {
                    *(float2*)(C + (size_t)rA * ldc + c) = make_float2(v00, v01);
                    *(float2*)(C + (size_t)rB * ldc + c) = make_float2(v10, v11);
                }
                if (Ch) {
                    *(__half2*)(Ch + (size_t)rA * ldc + c) = __floats2half2_rn(v00, v01);
                    *(__half2*)(Ch + (size_t)rB * ldc + c) = __floats2half2_rn(v10, v11);
                }
            } else {
                const int sec = c / Hd;
                const int cc  = c - sec * Hd;
                const int h = cc / DHd, d = cc - h * DHd;
                const int bIdx = rA >> 8;
                if (sec < 2) {
                    __half* dst = (sec == 0) ? g_qhp : g_khp;
                    size_t p0 = ((((size_t)bIdx * NHd + h) << 8) | (rA & 255)) * 64 + d;
                    size_t p1 = ((((size_t)bIdx * NHd + h) << 8) | (rB & 255)) * 64 + d;
                    *(__half2*)(dst + p0) = __floats2half2_rn(v00, v01);
                    *(__half2*)(dst + p1) = __floats2half2_rn(v10, v11);
                } else {
                    size_t hb = ((size_t)bIdx * NHd + h) * DHd;
                    g_vth[(hb + d)     * Nn + (rA & 255)] = __float2half(v00);
                    g_vth[(hb + d + 1) * Nn + (rA & 255)] = __float2half(v01);
                    g_vth[(hb + d)     * Nn + (rB & 255)] = __float2half(v10);
                    g_vth[(hb + d + 1) * Nn + (rB & 255)] = __float2half(v11);
                }
            }
        }
    }
}

// ============================================================================
// distrow: fused gram(zh) + sqrt + mask + rowmax-bias -> g_D. 64m x 256n, K=384.
// ============================================================================
#define DR_ARS   40
#define DR_ABUF  (64 * DR_ARS * 2)
#define DR_BBUF  (256 * DR_ARS * 2)
#define DR_STAGE (DR_ABUF + DR_BBUF)
#define DR_RED   (3 * DR_STAGE)
#define DR_SMEM  (DR_RED + 128 * 4)

__global__ __launch_bounds__(256)
void distrow_kernel(const __half* __restrict__ Z, const float* __restrict__ mask) {
    extern __shared__ char smem[];
    const uint32_t sb = smem_to_u32(smem);
    float* rmax = (float*)(smem + DR_RED);
    const int t = threadIdx.x, lane = t & 31, wid = t >> 5;
    const int bz = blockIdx.y, m0 = blockIdx.x * 64;
    const __half* A = Z + (size_t)bz * Nn * Hd + (size_t)m0 * Hd;
    const __half* B = Z + (size_t)bz * Nn * Hd;
    const int mW = (wid & 3) * 16, nW = (wid >> 2) * 128;

    const int lq = lane >> 3, lr = lane & 7;
    const int aRow = (lq & 1) * 8 + lr, aCol = (lq >> 1) * 8;
    const int bRow = (lq >> 1) * 8 + lr, bCol = (lq & 1) * 8;
    const uint32_t aOff = (uint32_t)(((mW + aRow) * DR_ARS + aCol) * 2);
    const uint32_t bOff = (uint32_t)(DR_ABUF + ((nW + bRow) * DR_ARS + bCol) * 2);

    float acc[16][4];
    #pragma unroll
    for (int j = 0; j < 16; j++)
        #pragma unroll
        for (int r = 0; r < 4; r++) acc[j][r] = 0.f;

    auto issue = [&](int ch) {
        const uint32_t dstA = sb + (uint32_t)(ch % 3) * DR_STAGE;
        const uint32_t dstB = dstA + DR_ABUF;
        CP_ASYNC16(dstA + (uint32_t)(((t >> 2) * DR_ARS + (t & 3) * 8) * 2),
                   A + (size_t)(t >> 2) * Hd + ch * 32 + (t & 3) * 8);
        #pragma unroll
        for (int u = 0; u < 4; u++) {
            int p = t + u * 256, row = p >> 2, seg = p & 3;
            CP_ASYNC16(dstB + (uint32_t)((row * DR_ARS + seg * 8) * 2),
                       B + (size_t)row * Hd + ch * 32 + seg * 8);
        }
        CP_COMMIT();
    };
    issue(0);
    issue(1);

    const int nch = Hd >> 5;
    for (int ch = 0; ch < nch; ch++) {
        if (ch + 1 < nch) { CP_WAIT1(); } else { CP_WAIT0(); }
        __syncthreads();
        const uint32_t base = sb + (uint32_t)(ch % 3) * DR_STAGE;
        #pragma unroll
        for (int ks = 0; ks < 2; ks++) {
            uint32_t a[4];
            LDSM4(a, base + aOff + (uint32_t)(ks * 16 * 2));
            #pragma unroll
            for (int g = 0; g < 8; g++) {
                uint32_t bf[4];
                LDSM4(bf, base + bOff + (uint32_t)((g * 16 * DR_ARS + ks * 16) * 2));
                MMA16816(acc[2 * g],     a, bf[0], bf[1]);
                MMA16816(acc[2 * g + 1], a, bf[2], bf[3]);
            }
        }
        if (ch + 2 < nch) issue(ch + 2);
    }

    const int rloc0 = mW + (lane >> 2), rloc1 = rloc0 + 8;
    const int gi0 = m0 + rloc0, gi1 = m0 + rloc1;
    const int cB = nW + (lane & 3) * 2;
    const float sqi0 = g_sq[bz * Nn + gi0], sqi1 = g_sq[bz * Nn + gi1];
    const float mi0 = mask[bz * Nn + gi0],  mi1 = mask[bz * Nn + gi1];
    #pragma unroll
    for (int nt = 0; nt < 16; nt++) {
        const int gj = cB + nt * 8;
        float sj0 = g_sq[bz * Nn + gj], sj1 = g_sq[bz * Nn + gj + 1];
        float mj0 = mask[bz * Nn + gj], mj1 = mask[bz * Nn + gj + 1];
        float d2;
        d2 = fmaxf(sqi0 + sj0 - 2.f * acc[nt][0], 0.f);
        acc[nt][0] = ((d2 > 1e-12f) ? sqrtf(d2) : 0.f) * mi0 * mj0;
        d2 = fmaxf(sqi0 + sj1 - 2.f * acc[nt][1], 0.f);
        acc[nt][1] = ((d2 > 1e-12f) ? sqrtf(d2) : 0.f) * mi0 * mj1;
        d2 = fmaxf(sqi1 + sj0 - 2.f * acc[nt][2], 0.f);
        acc[nt][2] = ((d2 > 1e-12f) ? sqrtf(d2) : 0.f) * mi1 * mj0;
        d2 = fmaxf(sqi1 + sj1 - 2.f * acc[nt][3], 0.f);
        acc[nt][3] = ((d2 > 1e-12f) ? sqrtf(d2) : 0.f) * mi1 * mj1;
    }
    float mx0 = 0.f, mx1 = 0.f;
    #pragma unroll
    for (int nt = 0; nt < 16; nt++) {
        mx0 = fmaxf(mx0, fmaxf(acc[nt][0], acc[nt][1]));
        mx1 = fmaxf(mx1, fmaxf(acc[nt][2], acc[nt][3]));
    }
    #pragma unroll
    for (int o = 1; o < 4; o <<= 1) {
        mx0 = fmaxf(mx0, __shfl_xor_sync(0xffffffffu, mx0, o));
        mx1 = fmaxf(mx1, __shfl_xor_sync(0xffffffffu, mx1, o));
    }
    const int nw = wid >> 2;
    rmax[nw * 64 + rloc0] = mx0;
    rmax[nw * 64 + rloc1] = mx1;
    __syncthreads();
    const float M0 = fmaxf(rmax[rloc0], rmax[64 + rloc0]);
    const float M1 = fmaxf(rmax[rloc1], rmax[64 + rloc1]);
    float* Dp = g_D + (size_t)bz * Nn * Nn;
    #pragma unroll
    for (int nt = 0; nt < 16; nt++) {
        const int gj = cB + nt * 8;
        float mj0 = mask[bz * Nn + gj], mj1 = mask[bz * Nn + gj + 1];
        float o00 = (gi0 == gj)     ? 0.f : (M0 - acc[nt][0]) * mi0 * mj0;
        float o01 = (gi0 == gj + 1) ? 0.f : (M0 - acc[nt][1]) * mi0 * mj1;
        float o10 = (gi1 == gj)     ? 0.f : (M1 - acc[nt][2]) * mi1 * mj0;
        float o11 = (gi1 == gj + 1) ? 0.f : (M1 - acc[nt][3]) * mi1 * mj1;
        *(float2*)(Dp + (size_t)gi0 * Nn + gj) = make_float2(o00, o01);
        *(float2*)(Dp + (size_t)gi1 * Nn + gj) = make_float2(o10, o11);
    }
}

// ============================================================================
// attn: fully fused QK^T + D-bias + softmax + P@V^T per head.
// ============================================================================
#define AT_ARS   72
#define AT_PRS   264
#define AT_QBUF  0
#define AT_KBUF  (64 * AT_ARS * 2)
#define AT_PBUF  (AT_KBUF + 256 * AT_ARS * 2)
#define AT_VBUF  (AT_PBUF + 64 * AT_PRS * 2)
#define AT_RED   (AT_VBUF + 48 * AT_PRS * 2)
#define AT_SMEM  (AT_RED + 2 * 128 * 4)

__global__ __launch_bounds__(256)
void attn_kernel(const __half* __restrict__ qhp, const __half* __restrict__ khp) {
    extern __shared__ char smem[];
    const uint32_t sb = smem_to_u32(smem);
    float* rmax = (float*)(smem + AT_RED);
    float* rsum = rmax + 128;
    const int t = threadIdx.x, lane = t & 31, wid = t >> 5;
    const int bh = blockIdx.y, m0 = blockIdx.x * 64;
    const int b = bh >> 3, h = bh & 7;
    const __half* Aq = qhp + (size_t)bh * Nn * 64 + (size_t)m0 * 64;
    const __half* Bk = khp + (size_t)bh * Nn * 64;
    const __half* Vt = g_vth + (size_t)bh * DHd * Nn;
    const int mW = (wid & 3) * 16, nW = (wid >> 2) * 128;

    #pragma unroll
    for (int u = 0; u < 2; u++) {
        int p = t + u * 256, row = p >> 3, seg = p & 7;
        CP_ASYNC16(sb + AT_QBUF + (uint32_t)((row * AT_ARS + seg * 8) * 2),
                   Aq + (size_t)row * 64 + seg * 8);
    }
    #pragma unroll
    for (int u = 0; u < 8; u++) {
        int p = t + u * 256, row = p >> 3, seg = p & 7;
        CP_ASYNC16(sb + AT_KBUF + (uint32_t)((row * AT_ARS + seg * 8) * 2),
                   Bk + (size_t)row * 64 + seg * 8);
    }
    #pragma unroll
    for (int u = 0; u < 6; u++) {
        int p = t + u * 256, row = p >> 5, seg = p & 31;
        CP_ASYNC16(sb + AT_VBUF + (uint32_t)((row * AT_PRS + seg * 8) * 2),
                   Vt + (size_t)row * Nn + seg * 8);
    }
    CP_COMMIT();
    CP_WAIT0();
    __syncthreads();

    const int lq = lane >> 3, lr = lane & 7;
    const int aRow = (lq & 1) * 8 + lr, aCol = (lq >> 1) * 8;
    const int bRow = (lq >> 1) * 8 + lr, bCol = (lq & 1) * 8;
    const uint32_t aOff = sb + AT_QBUF + (uint32_t)(((mW + aRow) * AT_ARS + aCol) * 2);
    const uint32_t bOff = sb + AT_KBUF + (uint32_t)(((nW + bRow) * AT_ARS + bCol) * 2);

    float acc[16][4];
    #pragma unroll
    for (int j = 0; j < 16; j++)
        #pragma unroll
        for (int r = 0; r < 4; r++) acc[j][r] = 0.f;

    #pragma unroll
    for (int ks = 0; ks < 4; ks++) {
        uint32_t a[4];
        LDSM4(a, aOff + (uint32_t)(ks * 16 * 2));
        #pragma unroll
        for (int g = 0; g < 8; g++) {
            uint32_t bf[4];
            LDSM4(bf, bOff + (uint32_t)((g * 16 * AT_ARS + ks * 16) * 2));
            MMA16816(acc[2 * g],     a, bf[0], bf[1]);
            MMA16816(acc[2 * g + 1], a, bf[2], bf[3]);
        }
    }

    const float scale = 0.144337567297406441f;
    const int rloc0 = mW + (lane >> 2), rloc1 = rloc0 + 8;
    const int gi0 = m0 + rloc0, gi1 = m0 + rloc1;
    const int cB = nW + (lane & 3) * 2;
    #pragma unroll
    for (int nt = 0; nt < 16; nt++) {
        const int gj = cB + nt * 8;
        float2 d0 = *(const float2*)(g_D + ((size_t)b * Nn + gi0) * Nn + gj);
        float2 d1 = *(const float2*)(g_D + ((size_t)b * Nn + gi1) * Nn + gj);
        acc[nt][0] = acc[nt][0] * scale + d0.x;
        acc[nt][1] = acc[nt][1] * scale + d0.y;
        acc[nt][2] = acc[nt][2] * scale + d1.x;
        acc[nt][3] = acc[nt][3] * scale + d1.y;
    }
    float mx0 = -1e30f, mx1 = -1e30f;
    #pragma unroll
    for (int nt = 0; nt < 16; nt++) {
        mx0 = fmaxf(mx0, fmaxf(acc[nt][0], acc[nt][1]));
        mx1 = fmaxf(mx1, fmaxf(acc[nt][2], acc[nt][3]));
    }
    #pragma unroll
    for (int o = 1; o < 4; o <<= 1) {
        mx0 = fmaxf(mx0, __shfl_xor_sync(0xffffffffu, mx0, o));
        mx1 = fmaxf(mx1, __shfl_xor_sync(0xffffffffu, mx1, o));
    }
    const int nwg = wid >> 2;
    rmax[nwg * 64 + rloc0] = mx0;
    rmax[nwg * 64 + rloc1] = mx1;
    __syncthreads();
    const float M0 = fmaxf(rmax[rloc0], rmax[64 + rloc0]);
    const float M1 = fmaxf(rmax[rloc1], rmax[64 + rloc1]);
    float s0 = 0.f, s1 = 0.f;
    #pragma unroll
    for (int nt = 0; nt < 16; nt++) {
        acc[nt][0] = __expf(acc[nt][0] - M0);
        acc[nt][1] = __expf(acc[nt][1] - M0);
        acc[nt][2] = __expf(acc[nt][2] - M1);
        acc[nt][3] = __expf(acc[nt][3] - M1);
        s0 += acc[nt][0] + acc[nt][1];
        s1 += acc[nt][2] + acc[nt][3];
    }
    #pragma unroll
    for (int o = 1; o < 4; o <<= 1) {
        s0 += __shfl_xor_sync(0xffffffffu, s0, o);
        s1 += __shfl_xor_sync(0xffffffffu, s1, o);
    }
    rsum[nwg * 64 + rloc0] = s0;
    rsum[nwg * 64 + rloc1] = s1;
    __syncthreads();
    const float inv0 = 1.f / (rsum[rloc0] + rsum[64 + rloc0]);
    const float inv1 = 1.f / (rsum[rloc1] + rsum[64 + rloc1]);
    #pragma unroll
    for (int nt = 0; nt < 16; nt++) {
        const int gj = cB + nt * 8;
        *(__half2*)(smem + AT_PBUF + ((size_t)rloc0 * AT_PRS + gj) * 2) =
            __floats2half2_rn(acc[nt][0] * inv0, acc[nt][1] * inv0);
        *(__half2*)(smem + AT_PBUF + ((size_t)rloc1 * AT_PRS + gj) * 2) =
            __floats2half2_rn(acc[nt][2] * inv1, acc[nt][3] * inv1);
    }
    __syncthreads();

    if (wid < 4) {
        const int mW2 = wid * 16;
        const uint32_t pOff = sb + AT_PBUF + (uint32_t)(((mW2 + aRow) * AT_PRS + aCol) * 2);
        const uint32_t vOff = sb + AT_VBUF + (uint32_t)((bRow * AT_PRS + bCol) * 2);
        float av[6][4];
        #pragma unroll
        for (int j = 0; j < 6; j++)
            #pragma unroll
            for (int r = 0; r < 4; r++) av[j][r] = 0.f;
        #pragma unroll
        for (int ks = 0; ks < 16; ks++) {
            uint32_t a[4];
            LDSM4(a, pOff + (uint32_t)(ks * 16 * 2));
            #pragma unroll
            for (int g = 0; g < 3; g++) {
                uint32_t bf[4];
                LDSM4(bf, vOff + (uint32_t)((g * 16 * AT_PRS + ks * 16) * 2));
                MMA16816(av[2 * g],     a, bf[0], bf[1]);
                MMA16816(av[2 * g + 1], a, bf[2], bf[3]);
            }
        }
        const int rA = m0 + mW2 + (lane >> 2);
        const int cBase = (lane & 3) * 2;
        #pragma unroll
        for (int nt = 0; nt < 6; nt++) {
            const int c = cBase + nt * 8;
            *(__half2*)(g_yh + ((size_t)b * Nn + rA) * Hd + h * DHd + c) =
                __floats2half2_rn(av[nt][0], av[nt][1]);
            *(__half2*)(g_yh + ((size_t)b * Nn + rA + 8) * Hd + h * DHd + c) =
                __floats2half2_rn(av[nt][2], av[nt][3]);
        }
    }
}

// ---------------- row squared norms of z (post-embed only) ----------------
__global__ void sqnorm_kernel() {
    int r = blockIdx.x;
    float s = 0.f;
    for (int c = threadIdx.x; c < Hd; c += 128) {
        float v = g_z[(size_t)r * Hd + c];
        s += v * v;
    }
    s = blocksum128(s);
    if (threadIdx.x == 0) g_sq[r] = s;
}

// ---------------- out = LayerNorm(a + r); warp-per-row, 8 rows/block ----------------
__global__ __launch_bounds__(256)
void addln_kernel(const float* __restrict__ a, const float* __restrict__ r,
                  const float* __restrict__ g, const float* __restrict__ be,
                  float* __restrict__ out, __half* __restrict__ outh,
                  float* __restrict__ sqout) {
    const int lane = threadIdx.x & 31;
    const int row = blockIdx.x * 8 + (threadIdx.x >> 5);
    const size_t base = (size_t)row * Hd;
    float4 va[3];
    float s = 0.f;
    #pragma unroll
    for (int u = 0; u < 3; u++) {
        const int c = u * 128 + lane * 4;
        float4 av = *(const float4*)(a + base + c);
        float4 rv = *(const float4*)(r + base + c);
        va[u] = make_float4(av.x + rv.x, av.y + rv.y, av.z + rv.z, av.w + rv.w);
        s += va[u].x + va[u].y + va[u].z + va[u].w;
    }
    const float mu = warpsum(s) * (1.f / Hd);
    float s2 = 0.f;
    #pragma unroll
    for (int u = 0; u < 3; u++) {
        float d;
        d = va[u].x - mu; s2 += d * d;
        d = va[u].y - mu; s2 += d * d;
        d = va[u].z - mu; s2 += d * d;
        d = va[u].w - mu; s2 += d * d;
    }
    const float rstd = rsqrtf(warpsum(s2) * (1.f / Hd) + 1e-5f);
    float s3 = 0.f;
    #pragma unroll
    for (int u = 0; u < 3; u++) {
        const int c = u * 128 + lane * 4;
        float4 gv = *(const float4*)(g + c);
        float4 bv = *(const float4*)(be + c);
        float4 o;
        o.x = (va[u].x - mu) * rstd * gv.x + bv.x;
        o.y = (va[u].y - mu) * rstd * gv.y + bv.y;
        o.z = (va[u].z - mu) * rstd * gv.z + bv.z;
        o.w = (va[u].w - mu) * rstd * gv.w + bv.w;
        *(float4*)(out + base + c) = o;
        __half2 h0 = __floats2half2_rn(o.x, o.y);
        __half2 h1 = __floats2half2_rn(o.z, o.w);
        *(__half2*)(outh + base + c)     = h0;
        *(__half2*)(outh + base + c + 2) = h1;
        s3 += o.x * o.x + o.y * o.y + o.z * o.z + o.w * o.w;
    }
    if (sqout) {
        s3 = warpsum(s3);
        if (lane == 0) sqout[row] = s3;
    }
}

// ---------------- masked outputs ----------------
__global__ void out_x_kernel(const float* __restrict__ x, const float* __restrict__ mask,
                             float* __restrict__ out) {
    size_t idx = (size_t)blockIdx.x * blockDim.x + threadIdx.x;
    if (idx >= (size_t)Bn * Nn * XDim) return;
    out[idx] = x[idx] * mask[idx / XDim];
}
__global__ void out_e_kernel(const float* __restrict__ e, const float* __restrict__ mask,
                             float* __restrict__ out) {
    size_t pair = (size_t)blockIdx.x * blockDim.x + threadIdx.x;
    if (pair >= (size_t)Bn * Nn * Nn) return;
    int j  = (int)(pair & (Nn - 1));
    size_t bi = pair >> 8;
    int b  = (int)(bi >> 8);
    float mm = mask[bi] * mask[(size_t)b * Nn + j];
    const float* ep = e + pair * EDim;
    float* op = out + pair * EDim;
    #pragma unroll
    for (int k = 0; k < EDim; k++) op[k] = ep[k] * mm;
}
__global__ void out_z_kernel(const float* __restrict__ mask, float* __restrict__ out) {
    size_t idx = (size_t)blockIdx.x * blockDim.x + threadIdx.x;
    if (idx >= (size_t)Mrows * Hd) return;
    out[idx] = g_z[idx] * mask[idx / Hd];
}

// ---------------- launcher ----------------
extern "C" void kernel_launch(void* const* d_in, const int* in_sizes, int n_in,
                              void* d_out, int out_size) {
    const float* x    = (const float*)d_in[0];
    const float* e    = (const float*)d_in[1];
    const float* mask = (const float*)d_in[2];
    const float* Wemb = (const float*)d_in[3];
    const float* Wq = (const float*)d_in[4];  const float* bq = (const float*)d_in[5];
    const float* Wk = (const float*)d_in[6];  const float* bk = (const float*)d_in[7];
    const float* Wv = (const float*)d_in[8];  const float* bv = (const float*)d_in[9];
    const float* Wo = (const float*)d_in[10]; const float* bo = (const float*)d_in[11];
    const float* g1 = (const float*)d_in[12]; const float* be1 = (const float*)d_in[13];
    const float* W1 = (const float*)d_in[14]; const float* b1  = (const float*)d_in[15];
    const float* W2 = (const float*)d_in[16]; const float* b2  = (const float*)d_in[17];
    const float* g2 = (const float*)d_in[18]; const float* be2 = (const float*)d_in[19];
    float* out = (float*)d_out;

    float  *z, *q, *x1, *sq, *bqkv;
    __half *cath, *zh, *x1h, *yh, *ffnh, *qhp, *khp;
    __half *wembTh, *wqkvT, *woTh, *w1Th, *w2Th;
    cudaGetSymbolAddress((void**)&cath,  g_cath);
    cudaGetSymbolAddress((void**)&z,     g_z);
    cudaGetSymbolAddress((void**)&zh,    g_zh);
    cudaGetSymbolAddress((void**)&q,     g_q);
    cudaGetSymbolAddress((void**)&yh,    g_yh);
    cudaGetSymbolAddress((void**)&x1,    g_x1);
    cudaGetSymbolAddress((void**)&x1h,   g_x1h);
    cudaGetSymbolAddress((void**)&ffnh,  g_ffnh);
    cudaGetSymbolAddress((void**)&qhp,   g_qhp);
    cudaGetSymbolAddress((void**)&khp,   g_khp);
    cudaGetSymbolAddress((void**)&sq,    g_sq);
    cudaGetSymbolAddress((void**)&bqkv,  g_bqkv);
    cudaGetSymbolAddress((void**)&wembTh, g_wembTh);
    cudaGetSymbolAddress((void**)&wqkvT, g_wqkvT);
    cudaGetSymbolAddress((void**)&woTh,  g_woTh);
    cudaGetSymbolAddress((void**)&w1Th,  g_w1Th);
    cudaGetSymbolAddress((void**)&w2Th,  g_w2Th);

    cudaFuncSetAttribute(gemm_h_kernel,
                         cudaFuncAttributeMaxDynamicSharedMemorySize, GK_SMEM_B);
    cudaFuncSetAttribute(distrow_kernel,
                         cudaFuncAttributeMaxDynamicSharedMemorySize, DR_SMEM);
    cudaFuncSetAttribute(attn_kernel,
                         cudaFuncAttributeMaxDynamicSharedMemorySize, AT_SMEM);

    dim3 tb(32, 8);
    {
        size_t tot = (size_t)Mrows * KPAD;
        cat_kernel<<<(unsigned)((tot + 255) / 256), 256>>>(x, e);
    }
    transpose_kernel<<<dim3(12, 44, 1), tb>>>(Wemb, wembTh, KCAT, Hd, KPAD, 0, 0);
    transpose_kernel<<<dim3(12, 12, DEPTH), tb>>>(Wq, wqkvT, Hd, Hd, Hd,
                                                  (size_t)Hd * Hd, (size_t)H3 * Hd);
    transpose_kernel<<<dim3(12, 12, DEPTH), tb>>>(Wk, wqkvT + (size_t)Hd * Hd, Hd, Hd, Hd,
                                                  (size_t)Hd * Hd, (size_t)H3 * Hd);
    transpose_kernel<<<dim3(12, 12, DEPTH), tb>>>(Wv, wqkvT + 2 * (size_t)Hd * Hd, Hd, Hd, Hd,
                                                  (size_t)Hd * Hd, (size_t)H3 * Hd);
    qkvbias_kernel<<<(DEPTH * H3 + 255) / 256, 256>>>(bq, bk, bv);
    gemm_h_kernel<<<dim3(Hd / 128, Mrows / 128), 256, GK_SMEM_B>>>(
        cath, KPAD, wembTh, KPAD, nullptr, z, zh, Hd, KPAD, 0, 0);
    transpose_kernel<<<dim3(12, 12, DEPTH), tb>>>(Wo, woTh, Hd, Hd, Hd,
                                                  (size_t)Hd * Hd, (size_t)Hd * Hd);
    transpose_kernel<<<dim3(48, 12, DEPTH), tb>>>(W1, w1Th, Hd, DFFd, Hd,
                                                  (size_t)Hd * DFFd, (size_t)DFFd * Hd);
    transpose_kernel<<<dim3(12, 48, DEPTH), tb>>>(W2, w2Th, DFFd, Hd, DFFd,
                                                  (size_t)DFFd * Hd, (size_t)Hd * DFFd);
    sqnorm_kernel<<<Mrows, 128>>>();

    for (int l = 0; l < DEPTH; l++) {
        const size_t wofs  = (size_t)l * Hd * Hd;
        const size_t w1ofs = (size_t)l * DFFd * Hd;
        // fused distance-bias
        distrow_kernel<<<dim3(4, Bn), 256, DR_SMEM>>>(zh, mask);
        // fused QKV GEMM into per-head layouts
        gemm_h_kernel<<<dim3(H3 / 128, Mrows / 128), 256, GK_SMEM_B>>>(
            zh, Hd, wqkvT + (size_t)l * H3 * Hd, Hd, bqkv + (size_t)l * H3,
            nullptr, nullptr, 0, Hd, 0, 3);
        // fully fused attention
        attn_kernel<<<dim3(4, Bn * NHd), 256, AT_SMEM>>>(qhp, khp);
        // output projection + AddNorm
        gemm_h_kernel<<<dim3(Hd / 128, Mrows / 128), 256, GK_SMEM_B>>>(
            yh, Hd, woTh + wofs, Hd, bo + (size_t)l * Hd, q, nullptr, Hd, Hd, 0, 0);
        addln_kernel<<<Mrows / 8, 256>>>(z, q, g1 + (size_t)l * Hd, be1 + (size_t)l * Hd,
                                         x1, x1h, nullptr);
        // FFN
        gemm_h_kernel<<<dim3(DFFd / 128, Mrows / 128), 256, GK_SMEM_B>>>(
            x1h, Hd, w1Th + w1ofs, Hd, b1 + (size_t)l * DFFd,
            nullptr, ffnh, DFFd, Hd, 1, 0);
        gemm_h_kernel<<<dim3(Hd / 128, Mrows / 128), 256, GK_SMEM_B>>>(
            ffnh, DFFd, w2Th + w1ofs, DFFd, b2 + (size_t)l * Hd,
            q, nullptr, Hd, DFFd, 0, 0);
        addln_kernel<<<Mrows / 8, 256>>>(x1, q, g2 + (size_t)l * Hd, be2 + (size_t)l * Hd,
                                         z, zh, sq);
    }

    // outputs: [X_out | E_out | z_out]
    const size_t XTOT = (size_t)Bn * Nn * XDim;
    const size_t ETOT = (size_t)Bn * Nn * Nn * EDim;
    const size_t ZTOT = (size_t)Mrows * Hd;
    const size_t EPAIRS = (size_t)Bn * Nn * Nn;
    out_x_kernel<<<(unsigned)((XTOT + 255) / 256), 256>>>(x, mask, out);
    out_e_kernel<<<(unsigned)((EPAIRS + 255) / 256), 256>>>(e, mask, out + XTOT);
    out_z_kernel<<<(unsigned)((ZTOT + 255) / 256), 256>>>(mask, out + XTOT + ETOT);
    (void)in_sizes; (void)n_in; (void)out_size;
}

// round 15
// speedup vs baseline: 1.1791x; 1.0209x over previous
#include <cuda_runtime.h>
#include <cuda_fp16.h>
#include <math.h>
#include <stdint.h>

#define Bn    64
#define Nn    256
#define XDim  118
#define EDim  5
#define Hd    384
#define NHd   8
#define DHd   48
#define DFFd  1536
#define DEPTH 6
#define Mrows (Bn * Nn)            /* 16384 */
#define KCAT  (XDim + Nn * EDim)   /* 1398  */
#define KPAD  1408
#define EROW  (Nn * EDim)
#define H3    (3 * Hd)             /* 1152 */

// ---------------- scratch (device globals; zero-init, no allocation) ----------------
__device__ __half g_cath[(size_t)Mrows * KPAD];
__device__ float  g_z  [(size_t)Mrows * Hd];
__device__ __half g_zh [(size_t)Mrows * Hd];
__device__ float  g_q  [(size_t)Mrows * Hd];
__device__ __half g_yh [(size_t)Mrows * Hd];
__device__ float  g_x1 [(size_t)Mrows * Hd];
__device__ __half g_x1h[(size_t)Mrows * Hd];
__device__ __half g_ffnh[(size_t)Mrows * DFFd];
__device__ float  g_D  [(size_t)Bn * Nn * Nn];
__device__ float  g_sq [Mrows];
__device__ __half g_qhp[(size_t)Bn * NHd * Nn * 64];
__device__ __half g_khp[(size_t)Bn * NHd * Nn * 64];
__device__ __half g_vth[(size_t)Bn * NHd * DHd * Nn];
__device__ __half g_wembTh[(size_t)Hd * KPAD];
__device__ __half g_wqkvT[(size_t)DEPTH * H3 * Hd];
__device__ float  g_bqkv [(size_t)DEPTH * H3];
__device__ __half g_woTh [(size_t)DEPTH * Hd * Hd];
__device__ __half g_w1Th [(size_t)DEPTH * DFFd * Hd];
__device__ __half g_w2Th [(size_t)DEPTH * Hd * DFFd];

// ---------------- PTX helpers (sm_80+ base ISA) ----------------
__device__ __forceinline__ uint32_t smem_to_u32(const void* p) {
    uint32_t a;
    asm("{ .reg .u64 t; cvta.to.shared.u64 t, %1; cvt.u32.u64 %0, t; }"
        : "=r"(a) : "l"(p));
    return a;
}
#define CP_ASYNC16(dst, src) \
    asm volatile("cp.async.cg.shared.global [%0], [%1], 16;" \
                 :: "r"(dst), "l"(src) : "memory")
#define CP_COMMIT() asm volatile("cp.async.commit_group;" ::: "memory")
#define CP_WAIT2()  asm volatile("cp.async.wait_group 2;" ::: "memory")
#define CP_WAIT1()  asm volatile("cp.async.wait_group 1;" ::: "memory")
#define CP_WAIT0()  asm volatile("cp.async.wait_group 0;" ::: "memory")
#define LDSM4(r, addr) \
    asm volatile("ldmatrix.sync.aligned.m8n8.x4.shared.b16 {%0,%1,%2,%3}, [%4];" \
                 : "=r"((r)[0]), "=r"((r)[1]), "=r"((r)[2]), "=r"((r)[3]) \
                 : "r"(addr))
#define MMA16816(d, a, b0_, b1_) \
    asm volatile("mma.sync.aligned.m16n8k16.row.col.f32.f16.f16.f32 " \
                 "{%0,%1,%2,%3}, {%4,%5,%6,%7}, {%8,%9}, {%0,%1,%2,%3};" \
                 : "+f"((d)[0]), "+f"((d)[1]), "+f"((d)[2]), "+f"((d)[3]) \
                 : "r"((a)[0]), "r"((a)[1]), "r"((a)[2]), "r"((a)[3]), \
                   "r"(b0_), "r"(b1_))

// ---------------- reductions ----------------
__device__ __forceinline__ float blocksum128(float v) {
    __shared__ float red[4];
    #pragma unroll
    for (int o = 16; o > 0; o >>= 1) v += __shfl_xor_sync(0xffffffffu, v, o);
    if ((threadIdx.x & 31) == 0) red[threadIdx.x >> 5] = v;
    __syncthreads();
    float s = red[0] + red[1] + red[2] + red[3];
    __syncthreads();
    return s;
}
__device__ __forceinline__ float warpsum(float v) {
    #pragma unroll
    for (int o = 16; o > 0; o >>= 1) v += __shfl_xor_sync(0xffffffffu, v, o);
    return v;
}

// ---------------- concat [x | e_flat | 0-pad] -> fp16 ----------------
__global__ void cat_kernel(const float* __restrict__ x, const float* __restrict__ e) {
    size_t idx = (size_t)blockIdx.x * blockDim.x + threadIdx.x;
    if (idx >= (size_t)Mrows * KPAD) return;
    size_t r = idx / KPAD;
    int    c = (int)(idx - r * KPAD);
    float v;
    if (c < XDim)      v = x[r * XDim + c];
    else if (c < KCAT) v = e[r * (size_t)EROW + (c - XDim)];
    else               v = 0.f;
    g_cath[idx] = __float2half(v);
}

// ---------------- transpose fp32 -> fp16 ----------------
__global__ void transpose_kernel(const float* __restrict__ in, __half* __restrict__ out,
                                 int R, int C, int outLd,
                                 size_t inStride, size_t outStride) {
    __shared__ float tile[32][33];
    const float* ip = in + (size_t)blockIdx.z * inStride;
    __half* op = out + (size_t)blockIdx.z * outStride;
    int c0 = blockIdx.x * 32, r0 = blockIdx.y * 32;
    int tx = threadIdx.x, ty = threadIdx.y;
    #pragma unroll
    for (int i = 0; i < 32; i += 8) {
        int r = r0 + ty + i, c = c0 + tx;
        tile[ty + i][tx] = (r < R && c < C) ? ip[(size_t)r * C + c] : 0.f;
    }
    __syncthreads();
    #pragma unroll
    for (int i = 0; i < 32; i += 8) {
        int oc = c0 + ty + i, orow = r0 + tx;
        if (oc < C && orow < outLd)
            op[(size_t)oc * outLd + orow] = __float2half(tile[tx][ty + i]);
    }
}

// ---------------- concat qkv bias ----------------
__global__ void qkvbias_kernel(const float* __restrict__ bq, const float* __restrict__ bk,
                               const float* __restrict__ bv) {
    int i = blockIdx.x * blockDim.x + threadIdx.x;
    if (i >= DEPTH * H3) return;
    int l = i / H3, r = i - l * H3;
    float v;
    if (r < Hd)           v = bq[l * Hd + r];
    else if (r < 2 * Hd)  v = bk[l * Hd + r - Hd];
    else                  v = bv[l * Hd + r - 2 * Hd];
    g_bqkv[i] = v;
}

// ============================================================================
// fp16 HMMA GEMM, 128x128x32 tiles, 8 warps, 4-stage cp.async.  (mode 0 only)
// ============================================================================
#define GK_RS      40
#define GK_OPB     (128 * GK_RS * 2)
#define GK_STAGE_B (2 * GK_OPB)
#define GK_NSTG    4
#define GK_SMEM_B  (GK_NSTG * GK_STAGE_B)   /* 81920 */

__global__ __launch_bounds__(256)
void gemm_h_kernel(const __half* __restrict__ A, int lda,
                   const __half* __restrict__ BT, int ldb,
                   const float* __restrict__ bias,
                   float* __restrict__ C, __half* __restrict__ Ch,
                   int ldc, int K, int relu) {
    extern __shared__ char smem[];
    const uint32_t sb = smem_to_u32(smem);
    const int t = threadIdx.x, lane = t & 31, wid = t >> 5;
    const int m0 = blockIdx.y * 128, n0 = blockIdx.x * 128;
    const int mW = (wid & 3) * 32, nW = (wid >> 2) * 64;

    const int r0 = t >> 2,          q0 = t & 3;
    const int r1 = (t + 256) >> 2,  q1 = (t + 256) & 3;
    const int lq = lane >> 3, lr = lane & 7;
    const int aRow = (lq & 1) * 8 + lr, aCol = (lq >> 1) * 8;
    const int bRow = (lq >> 1) * 8 + lr, bCol = (lq & 1) * 8;
    const uint32_t aOff = (uint32_t)(((mW + aRow) * GK_RS + aCol) * 2);
    const uint32_t bOff = (uint32_t)(GK_OPB + ((nW + bRow) * GK_RS + bCol) * 2);

    float acc[2][8][4];
    #pragma unroll
    for (int i = 0; i < 2; i++)
        #pragma unroll
        for (int j = 0; j < 8; j++)
            #pragma unroll
            for (int r = 0; r < 4; r++) acc[i][j][r] = 0.f;

    const int nch = K >> 5;
    auto issue = [&](int ch) {
        const uint32_t dstA = sb + (uint32_t)(ch % GK_NSTG) * GK_STAGE_B;
        const uint32_t dstB = dstA + GK_OPB;
        const __half* sa  = A  + (size_t)m0 * lda + ch * 32;
        const __half* sbp = BT + (size_t)n0 * ldb + ch * 32;
        CP_ASYNC16(dstA + (uint32_t)((r0 * GK_RS + q0 * 8) * 2), sa  + (size_t)r0 * lda + q0 * 8);
        CP_ASYNC16(dstA + (uint32_t)((r1 * GK_RS + q1 * 8) * 2), sa  + (size_t)r1 * lda + q1 * 8);
        CP_ASYNC16(dstB + (uint32_t)((r0 * GK_RS + q0 * 8) * 2), sbp + (size_t)r0 * ldb + q0 * 8);
        CP_ASYNC16(dstB + (uint32_t)((r1 * GK_RS + q1 * 8) * 2), sbp + (size_t)r1 * ldb + q1 * 8);
        CP_COMMIT();
    };
    issue(0);
    if (nch > 1) issue(1);
    if (nch > 2) issue(2);

    for (int ch = 0; ch < nch; ch++) {
        const int rem = nch - 1 - ch;
        if (rem >= 2)      { CP_WAIT2(); }
        else if (rem == 1) { CP_WAIT1(); }
        else               { CP_WAIT0(); }
        __syncthreads();
        const uint32_t base = sb + (uint32_t)(ch % GK_NSTG) * GK_STAGE_B;
        #pragma unroll
        for (int ks = 0; ks < 2; ks++) {
            uint32_t a[2][4], b[4][4];
            #pragma unroll
            for (int mt = 0; mt < 2; mt++)
                LDSM4(a[mt], base + aOff + (uint32_t)((mt * 16 * GK_RS + ks * 16) * 2));
            #pragma unroll
            for (int g = 0; g < 4; g++)
                LDSM4(b[g], base + bOff + (uint32_t)((g * 16 * GK_RS + ks * 16) * 2));
            #pragma unroll
            for (int mt = 0; mt < 2; mt++)
                #pragma unroll
                for (int g = 0; g < 4; g++) {
                    MMA16816(acc[mt][2 * g],     a[mt], b[g][0], b[g][1]);
                    MMA16816(acc[mt][2 * g + 1], a[mt], b[g][2], b[g][3]);
                }
        }
        if (ch + 3 < nch) issue(ch + 3);
    }

    const int rBase = m0 + mW + (lane >> 2);
    const int cBase = n0 + nW + (lane & 3) * 2;
    #pragma unroll
    for (int mt = 0; mt < 2; mt++) {
        #pragma unroll
        for (int nt = 0; nt < 8; nt++) {
            const int c = cBase + nt * 8;
            float b0 = 0.f, b1 = 0.f;
            if (bias) { b0 = bias[c]; b1 = bias[c + 1]; }
            float v00 = acc[mt][nt][0] + b0, v01 = acc[mt][nt][1] + b1;
            float v10 = acc[mt][nt][2] + b0, v11 = acc[mt][nt][3] + b1;
            if (relu) {
                v00 = fmaxf(v00, 0.f); v01 = fmaxf(v01, 0.f);
                v10 = fmaxf(v10, 0.f); v11 = fmaxf(v11, 0.f);
            }
            const int rA = rBase + mt * 16, rB = rA + 8;
            if (C) {
                *(float2*)(C + (size_t)rA * ldc + c) = make_float2(v00, v01);
                *(float2*)(C + (size_t)rB * ldc + c) = make_float2(v10, v11);
            }
            if (Ch) {
                *(__half2*)(Ch + (size_t)rA * ldc + c) = __floats2half2_rn(v00, v01);
                *(__half2*)(Ch + (size_t)rB * ldc + c) = __floats2half2_rn(v10, v11);
            }
        }
    }
}

// ============================================================================
// dqkv: fat kernel. blocks [0,1152): QKV GEMM tile -> qhp/khp/vth layouts;
// blocks [1152,1408): distrow (gram + sqrt + mask + rowmax-bias -> g_D).
// ============================================================================
#define DR_ARS   40
#define DR_ABUF  (64 * DR_ARS * 2)
#define DR_BBUF  (256 * DR_ARS * 2)
#define DR_STAGE (DR_ABUF + DR_BBUF)
#define DR_RED   (3 * DR_STAGE)
#define DQ_SMEM  GK_SMEM_B              /* 81920 >= DR_RED + 512 */

__global__ __launch_bounds__(256, 2)
void dqkv_kernel(const __half* __restrict__ Z,
                 const __half* __restrict__ WT, const float* __restrict__ bias,
                 const float* __restrict__ mask) {
    extern __shared__ char smem[];
    const uint32_t sb = smem_to_u32(smem);
    const int t = threadIdx.x, lane = t & 31, wid = t >> 5;
    const int lq = lane >> 3, lr = lane & 7;
    const int aRow = (lq & 1) * 8 + lr, aCol = (lq >> 1) * 8;
    const int bRow = (lq >> 1) * 8 + lr, bCol = (lq & 1) * 8;

    if (blockIdx.x < 1152) {
        // ---------------- QKV GEMM tile (mode-3 epilogue) ----------------
        const int id = blockIdx.x;
        const int m0 = (id / 9) * 128, n0 = (id % 9) * 128;
        const int mW = (wid & 3) * 32, nW = (wid >> 2) * 64;
        const int r0 = t >> 2,          q0 = t & 3;
        const int r1 = (t + 256) >> 2,  q1 = (t + 256) & 3;
        const uint32_t aOff = (uint32_t)(((mW + aRow) * GK_RS + aCol) * 2);
        const uint32_t bOff = (uint32_t)(GK_OPB + ((nW + bRow) * GK_RS + bCol) * 2);

        float acc[2][8][4];
        #pragma unroll
        for (int i = 0; i < 2; i++)
            #pragma unroll
            for (int j = 0; j < 8; j++)
                #pragma unroll
                for (int r = 0; r < 4; r++) acc[i][j][r] = 0.f;

        const int nch = Hd >> 5;  // 12
        auto issue = [&](int ch) {
            const uint32_t dstA = sb + (uint32_t)(ch % GK_NSTG) * GK_STAGE_B;
            const uint32_t dstB = dstA + GK_OPB;
            const __half* sa  = Z  + (size_t)m0 * Hd + ch * 32;
            const __half* sbp = WT + (size_t)n0 * Hd + ch * 32;
            CP_ASYNC16(dstA + (uint32_t)((r0 * GK_RS + q0 * 8) * 2), sa  + (size_t)r0 * Hd + q0 * 8);
            CP_ASYNC16(dstA + (uint32_t)((r1 * GK_RS + q1 * 8) * 2), sa  + (size_t)r1 * Hd + q1 * 8);
            CP_ASYNC16(dstB + (uint32_t)((r0 * GK_RS + q0 * 8) * 2), sbp + (size_t)r0 * Hd + q0 * 8);
            CP_ASYNC16(dstB + (uint32_t)((r1 * GK_RS + q1 * 8) * 2), sbp + (size_t)r1 * Hd + q1 * 8);
            CP_COMMIT();
        };
        issue(0); issue(1); issue(2);

        for (int ch = 0; ch < nch; ch++) {
            const int rem = nch - 1 - ch;
            if (rem >= 2)      { CP_WAIT2(); }
            else if (rem == 1) { CP_WAIT1(); }
            else               { CP_WAIT0(); }
            __syncthreads();
            const uint32_t base = sb + (uint32_t)(ch % GK_NSTG) * GK_STAGE_B;
            #pragma unroll
            for (int ks = 0; ks < 2; ks++) {
                uint32_t a[2][4], b[4][4];
                #pragma unroll
                for (int mt = 0; mt < 2; mt++)
                    LDSM4(a[mt], base + aOff + (uint32_t)((mt * 16 * GK_RS + ks * 16) * 2));
                #pragma unroll
                for (int g = 0; g < 4; g++)
                    LDSM4(b[g], base + bOff + (uint32_t)((g * 16 * GK_RS + ks * 16) * 2));
                #pragma unroll
                for (int mt = 0; mt < 2; mt++)
                    #pragma unroll
                    for (int g = 0; g < 4; g++) {
                        MMA16816(acc[mt][2 * g],     a[mt], b[g][0], b[g][1]);
                        MMA16816(acc[mt][2 * g + 1], a[mt], b[g][2], b[g][3]);
                    }
            }
            if (ch + 3 < nch) issue(ch + 3);
        }

        const int rBase = m0 + mW + (lane >> 2);
        const int cBase = n0 + nW + (lane & 3) * 2;
        #pragma unroll
        for (int mt = 0; mt < 2; mt++) {
            #pragma unroll
            for (int nt = 0; nt < 8; nt++) {
                const int c = cBase + nt * 8;
                const float b0 = bias[c], b1 = bias[c + 1];
                float v00 = acc[mt][nt][0] + b0, v01 = acc[mt][nt][1] + b1;
                float v10 = acc[mt][nt][2] + b0, v11 = acc[mt][nt][3] + b1;
                const int rA = rBase + mt * 16, rB = rA + 8;
                const int sec = c / Hd;
                const int cc  = c - sec * Hd;
                const int h = cc / DHd, d = cc - h * DHd;
                const int bIdx = rA >> 8;
                if (sec < 2) {
                    __half* dst = (sec == 0) ? g_qhp : g_khp;
                    size_t p0 = ((((size_t)bIdx * NHd + h) << 8) | (rA & 255)) * 64 + d;
                    size_t p1 = ((((size_t)bIdx * NHd + h) << 8) | (rB & 255)) * 64 + d;
                    *(__half2*)(dst + p0) = __floats2half2_rn(v00, v01);
                    *(__half2*)(dst + p1) = __floats2half2_rn(v10, v11);
                } else {
                    size_t hb = ((size_t)bIdx * NHd + h) * DHd;
                    g_vth[(hb + d)     * Nn + (rA & 255)] = __float2half(v00);
                    g_vth[(hb + d + 1) * Nn + (rA & 255)] = __float2half(v01);
                    g_vth[(hb + d)     * Nn + (rB & 255)] = __float2half(v10);
                    g_vth[(hb + d + 1) * Nn + (rB & 255)] = __float2half(v11);
                }
            }
        }
    } else {
        // ---------------- distrow tile ----------------
        const int id = blockIdx.x - 1152;
        const int bz = id >> 2, m0 = (id & 3) * 64;
        float* rmax = (float*)(smem + DR_RED);
        const __half* A = Z + (size_t)bz * Nn * Hd + (size_t)m0 * Hd;
        const __half* B = Z + (size_t)bz * Nn * Hd;
        const int mW = (wid & 3) * 16, nW = (wid >> 2) * 128;
        const uint32_t aOff = (uint32_t)(((mW + aRow) * DR_ARS + aCol) * 2);
        const uint32_t bOff = (uint32_t)(DR_ABUF + ((nW + bRow) * DR_ARS + bCol) * 2);

        float acc[16][4];
        #pragma unroll
        for (int j = 0; j < 16; j++)
            #pragma unroll
            for (int r = 0; r < 4; r++) acc[j][r] = 0.f;

        auto issue = [&](int ch) {
            const uint32_t dstA = sb + (uint32_t)(ch % 3) * DR_STAGE;
            const uint32_t dstB = dstA + DR_ABUF;
            CP_ASYNC16(dstA + (uint32_t)(((t >> 2) * DR_ARS + (t & 3) * 8) * 2),
                       A + (size_t)(t >> 2) * Hd + ch * 32 + (t & 3) * 8);
            #pragma unroll
            for (int u = 0; u < 4; u++) {
                int p = t + u * 256, row = p >> 2, seg = p & 3;
                CP_ASYNC16(dstB + (uint32_t)((row * DR_ARS + seg * 8) * 2),
                           B + (size_t)row * Hd + ch * 32 + seg * 8);
            }
            CP_COMMIT();
        };
        issue(0); issue(1);

        const int nch = Hd >> 5;
        for (int ch = 0; ch < nch; ch++) {
            if (ch + 1 < nch) { CP_WAIT1(); } else { CP_WAIT0(); }
            __syncthreads();
            const uint32_t base = sb + (uint32_t)(ch % 3) * DR_STAGE;
            #pragma unroll
            for (int ks = 0; ks < 2; ks++) {
                uint32_t a[4];
                LDSM4(a, base + aOff + (uint32_t)(ks * 16 * 2));
                #pragma unroll
                for (int g = 0; g < 8; g++) {
                    uint32_t bf[4];
                    LDSM4(bf, base + bOff + (uint32_t)((g * 16 * DR_ARS + ks * 16) * 2));
                    MMA16816(acc[2 * g],     a, bf[0], bf[1]);
                    MMA16816(acc[2 * g + 1], a, bf[2], bf[3]);
                }
            }
            if (ch + 2 < nch) issue(ch + 2);
        }

        const int rloc0 = mW + (lane >> 2), rloc1 = rloc0 + 8;
        const int gi0 = m0 + rloc0, gi1 = m0 + rloc1;
        const int cB = nW + (lane & 3) * 2;
        const float sqi0 = g_sq[bz * Nn + gi0], sqi1 = g_sq[bz * Nn + gi1];
        const float mi0 = mask[bz * Nn + gi0],  mi1 = mask[bz * Nn + gi1];
        #pragma unroll
        for (int nt = 0; nt < 16; nt++) {
            const int gj = cB + nt * 8;
            float sj0 = g_sq[bz * Nn + gj], sj1 = g_sq[bz * Nn + gj + 1];
            float mj0 = mask[bz * Nn + gj], mj1 = mask[bz * Nn + gj + 1];
            float d2;
            d2 = fmaxf(sqi0 + sj0 - 2.f * acc[nt][0], 0.f);
            acc[nt][0] = ((d2 > 1e-12f) ? sqrtf(d2) : 0.f) * mi0 * mj0;
            d2 = fmaxf(sqi0 + sj1 - 2.f * acc[nt][1], 0.f);
            acc[nt][1] = ((d2 > 1e-12f) ? sqrtf(d2) : 0.f) * mi0 * mj1;
            d2 = fmaxf(sqi1 + sj0 - 2.f * acc[nt][2], 0.f);
            acc[nt][2] = ((d2 > 1e-12f) ? sqrtf(d2) : 0.f) * mi1 * mj0;
            d2 = fmaxf(sqi1 + sj1 - 2.f * acc[nt][3], 0.f);
            acc[nt][3] = ((d2 > 1e-12f) ? sqrtf(d2) : 0.f) * mi1 * mj1;
        }
        float mx0 = 0.f, mx1 = 0.f;
        #pragma unroll
        for (int nt = 0; nt < 16; nt++) {
            mx0 = fmaxf(mx0, fmaxf(acc[nt][0], acc[nt][1]));
            mx1 = fmaxf(mx1, fmaxf(acc[nt][2], acc[nt][3]));
        }
        #pragma unroll
        for (int o = 1; o < 4; o <<= 1) {
            mx0 = fmaxf(mx0, __shfl_xor_sync(0xffffffffu, mx0, o));
            mx1 = fmaxf(mx1, __shfl_xor_sync(0xffffffffu, mx1, o));
        }
        const int nw = wid >> 2;
        rmax[nw * 64 + rloc0] = mx0;
        rmax[nw * 64 + rloc1] = mx1;
        __syncthreads();
        const float M0 = fmaxf(rmax[rloc0], rmax[64 + rloc0]);
        const float M1 = fmaxf(rmax[rloc1], rmax[64 + rloc1]);
        float* Dp = g_D + (size_t)bz * Nn * Nn;
        #pragma unroll
        for (int nt = 0; nt < 16; nt++) {
            const int gj = cB + nt * 8;
            float mj0 = mask[bz * Nn + gj], mj1 = mask[bz * Nn + gj + 1];
            float o00 = (gi0 == gj)     ? 0.f : (M0 - acc[nt][0]) * mi0 * mj0;
            float o01 = (gi0 == gj + 1) ? 0.f : (M0 - acc[nt][1]) * mi0 * mj1;
            float o10 = (gi1 == gj)     ? 0.f : (M1 - acc[nt][2]) * mi1 * mj0;
            float o11 = (gi1 == gj + 1) ? 0.f : (M1 - acc[nt][3]) * mi1 * mj1;
            *(float2*)(Dp + (size_t)gi0 * Nn + gj) = make_float2(o00, o01);
            *(float2*)(Dp + (size_t)gi1 * Nn + gj) = make_float2(o10, o11);
        }
    }
}

// ============================================================================
// attn: fused QK^T + D-bias + softmax + P@V^T. AV split across all 8 warps (K-halves).
// ============================================================================
#define AT_ARS   72
#define AT_PRS   264
#define AT_QBUF  0
#define AT_KBUF  (64 * AT_ARS * 2)
#define AT_PBUF  (AT_KBUF + 256 * AT_ARS * 2)
#define AT_VBUF  (AT_PBUF + 64 * AT_PRS * 2)
#define AT_RED   (AT_VBUF + 48 * AT_PRS * 2)
#define AT_SMEM  (AT_RED + 2 * 128 * 4)

__global__ __launch_bounds__(256)
void attn_kernel(const __half* __restrict__ qhp, const __half* __restrict__ khp) {
    extern __shared__ char smem[];
    const uint32_t sb = smem_to_u32(smem);
    float* rmax = (float*)(smem + AT_RED);
    float* rsum = rmax + 128;
    const int t = threadIdx.x, lane = t & 31, wid = t >> 5;
    const int bh = blockIdx.y, m0 = blockIdx.x * 64;
    const int b = bh >> 3, h = bh & 7;
    const __half* Aq = qhp + (size_t)bh * Nn * 64 + (size_t)m0 * 64;
    const __half* Bk = khp + (size_t)bh * Nn * 64;
    const __half* Vt = g_vth + (size_t)bh * DHd * Nn;
    const int mW = (wid & 3) * 16, nW = (wid >> 2) * 128;

    #pragma unroll
    for (int u = 0; u < 2; u++) {
        int p = t + u * 256, row = p >> 3, seg = p & 7;
        CP_ASYNC16(sb + AT_QBUF + (uint32_t)((row * AT_ARS + seg * 8) * 2),
                   Aq + (size_t)row * 64 + seg * 8);
    }
    #pragma unroll
    for (int u = 0; u < 8; u++) {
        int p = t + u * 256, row = p >> 3, seg = p & 7;
        CP_ASYNC16(sb + AT_KBUF + (uint32_t)((row * AT_ARS + seg * 8) * 2),
                   Bk + (size_t)row * 64 + seg * 8);
    }
    #pragma unroll
    for (int u = 0; u < 6; u++) {
        int p = t + u * 256, row = p >> 5, seg = p & 31;
        CP_ASYNC16(sb + AT_VBUF + (uint32_t)((row * AT_PRS + seg * 8) * 2),
                   Vt + (size_t)row * Nn + seg * 8);
    }
    CP_COMMIT();
    CP_WAIT0();
    __syncthreads();

    const int lq = lane >> 3, lr = lane & 7;
    const int aRow = (lq & 1) * 8 + lr, aCol = (lq >> 1) * 8;
    const int bRow = (lq >> 1) * 8 + lr, bCol = (lq & 1) * 8;
    const uint32_t aOff = sb + AT_QBUF + (uint32_t)(((mW + aRow) * AT_ARS + aCol) * 2);
    const uint32_t bOff = sb + AT_KBUF + (uint32_t)(((nW + bRow) * AT_ARS + bCol) * 2);

    float acc[16][4];
    #pragma unroll
    for (int j = 0; j < 16; j++)
        #pragma unroll
        for (int r = 0; r < 4; r++) acc[j][r] = 0.f;

    #pragma unroll
    for (int ks = 0; ks < 4; ks++) {
        uint32_t a[4];
        LDSM4(a, aOff + (uint32_t)(ks * 16 * 2));
        #pragma unroll
        for (int g = 0; g < 8; g++) {
            uint32_t bf[4];
            LDSM4(bf, bOff + (uint32_t)((g * 16 * AT_ARS + ks * 16) * 2));
            MMA16816(acc[2 * g],     a, bf[0], bf[1]);
            MMA16816(acc[2 * g + 1], a, bf[2], bf[3]);
        }
    }

    const float scale = 0.144337567297406441f;
    const int rloc0 = mW + (lane >> 2), rloc1 = rloc0 + 8;
    const int gi0 = m0 + rloc0, gi1 = m0 + rloc1;
    const int cB = nW + (lane & 3) * 2;
    #pragma unroll
    for (int nt = 0; nt < 16; nt++) {
        const int gj = cB + nt * 8;
        float2 d0 = *(const float2*)(g_D + ((size_t)b * Nn + gi0) * Nn + gj);
        float2 d1 = *(const float2*)(g_D + ((size_t)b * Nn + gi1) * Nn + gj);
        acc[nt][0] = acc[nt][0] * scale + d0.x;
        acc[nt][1] = acc[nt][1] * scale + d0.y;
        acc[nt][2] = acc[nt][2] * scale + d1.x;
        acc[nt][3] = acc[nt][3] * scale + d1.y;
    }
    float mx0 = -1e30f, mx1 = -1e30f;
    #pragma unroll
    for (int nt = 0; nt < 16; nt++) {
        mx0 = fmaxf(mx0, fmaxf(acc[nt][0], acc[nt][1]));
        mx1 = fmaxf(mx1, fmaxf(acc[nt][2], acc[nt][3]));
    }
    #pragma unroll
    for (int o = 1; o < 4; o <<= 1) {
        mx0 = fmaxf(mx0, __shfl_xor_sync(0xffffffffu, mx0, o));
        mx1 = fmaxf(mx1, __shfl_xor_sync(0xffffffffu, mx1, o));
    }
    const int nwg = wid >> 2;
    rmax[nwg * 64 + rloc0] = mx0;
    rmax[nwg * 64 + rloc1] = mx1;
    __syncthreads();
    const float M0 = fmaxf(rmax[rloc0], rmax[64 + rloc0]);
    const float M1 = fmaxf(rmax[rloc1], rmax[64 + rloc1]);
    float s0 = 0.f, s1 = 0.f;
    #pragma unroll
    for (int nt = 0; nt < 16; nt++) {
        acc[nt][0] = __expf(acc[nt][0] - M0);
        acc[nt][1] = __expf(acc[nt][1] - M0);
        acc[nt][2] = __expf(acc[nt][2] - M1);
        acc[nt][3] = __expf(acc[nt][3] - M1);
        s0 += acc[nt][0] + acc[nt][1];
        s1 += acc[nt][2] + acc[nt][3];
    }
    #pragma unroll
    for (int o = 1; o < 4; o <<= 1) {
        s0 += __shfl_xor_sync(0xffffffffu, s0, o);
        s1 += __shfl_xor_sync(0xffffffffu, s1, o);
    }
    rsum[nwg * 64 + rloc0] = s0;
    rsum[nwg * 64 + rloc1] = s1;
    __syncthreads();
    const float inv0 = 1.f / (rsum[rloc0] + rsum[64 + rloc0]);
    const float inv1 = 1.f / (rsum[rloc1] + rsum[64 + rloc1]);
    #pragma unroll
    for (int nt = 0; nt < 16; nt++) {
        const int gj = cB + nt * 8;
        *(__half2*)(smem + AT_PBUF + ((size_t)rloc0 * AT_PRS + gj) * 2) =
            __floats2half2_rn(acc[nt][0] * inv0, acc[nt][1] * inv0);
        *(__half2*)(smem + AT_PBUF + ((size_t)rloc1 * AT_PRS + gj) * 2) =
            __floats2half2_rn(acc[nt][2] * inv1, acc[nt][3] * inv1);
    }
    __syncthreads();

    // AV phase: all 8 warps; warps split the K=256 dimension in halves.
    {
        const int mW2 = (wid & 3) * 16;
        const int ksBase = (wid >> 2) * 8;   // 0 or 8 (x16 k-steps)
        const uint32_t pOff = sb + AT_PBUF + (uint32_t)(((mW2 + aRow) * AT_PRS + aCol) * 2);
        const uint32_t vOff = sb + AT_VBUF + (uint32_t)((bRow * AT_PRS + bCol) * 2);
        float av[6][4];
        #pragma unroll
        for (int j = 0; j < 6; j++)
            #pragma unroll
            for (int r = 0; r < 4; r++) av[j][r] = 0.f;
        #pragma unroll
        for (int ks = 0; ks < 8; ks++) {
            const int ksi = ksBase + ks;
            uint32_t a[4];
            LDSM4(a, pOff + (uint32_t)(ksi * 16 * 2));
            #pragma unroll
            for (int g = 0; g < 3; g++) {
                uint32_t bf[4];
                LDSM4(bf, vOff + (uint32_t)((g * 16 * AT_PRS + ksi * 16) * 2));
                MMA16816(av[2 * g],     a, bf[0], bf[1]);
                MMA16816(av[2 * g + 1], a, bf[2], bf[3]);
            }
        }
        // warps 4-7 deposit partials into (dead) Q/K smem region as [64][48] fp32
        float* pbuf = (float*)smem;   // 12288 B < AT_PBUF
        const int rl = mW2 + (lane >> 2);
        const int cb2 = (lane & 3) * 2;
        if (wid >= 4) {
            #pragma unroll
            for (int nt = 0; nt < 6; nt++) {
                const int c = cb2 + nt * 8;
                pbuf[(rl)     * 48 + c]     = av[nt][0];
                pbuf[(rl)     * 48 + c + 1] = av[nt][1];
                pbuf[(rl + 8) * 48 + c]     = av[nt][2];
                pbuf[(rl + 8) * 48 + c + 1] = av[nt][3];
            }
        }
        __syncthreads();
        if (wid < 4) {
            const int rA = m0 + rl;
            #pragma unroll
            for (int nt = 0; nt < 6; nt++) {
                const int c = cb2 + nt * 8;
                float v00 = av[nt][0] + pbuf[(rl)     * 48 + c];
                float v01 = av[nt][1] + pbuf[(rl)     * 48 + c + 1];
                float v10 = av[nt][2] + pbuf[(rl + 8) * 48 + c];
                float v11 = av[nt][3] + pbuf[(rl + 8) * 48 + c + 1];
                *(__half2*)(g_yh + ((size_t)b * Nn + rA) * Hd + h * DHd + c) =
                    __floats2half2_rn(v00, v01);
                *(__half2*)(g_yh + ((size_t)b * Nn + rA + 8) * Hd + h * DHd + c) =
                    __floats2half2_rn(v10, v11);
            }
        }
    }
}

// ---------------- row squared norms of z (post-embed only) ----------------
__global__ void sqnorm_kernel() {
    int r = blockIdx.x;
    float s = 0.f;
    for (int c = threadIdx.x; c < Hd; c += 128) {
        float v = g_z[(size_t)r * Hd + c];
        s += v * v;
    }
    s = blocksum128(s);
    if (threadIdx.x == 0) g_sq[r] = s;
}

// ---------------- out = LayerNorm(a + r); warp-per-row, 8 rows/block ----------------
__global__ __launch_bounds__(256)
void addln_kernel(const float* __restrict__ a, const float* __restrict__ r,
                  const float* __restrict__ g, const float* __restrict__ be,
                  float* __restrict__ out, __half* __restrict__ outh,
                  float* __restrict__ sqout) {
    const int lane = threadIdx.x & 31;
    const int row = blockIdx.x * 8 + (threadIdx.x >> 5);
    const size_t base = (size_t)row * Hd;
    float4 va[3];
    float s = 0.f;
    #pragma unroll
    for (int u = 0; u < 3; u++) {
        const int c = u * 128 + lane * 4;
        float4 av = *(const float4*)(a + base + c);
        float4 rv = *(const float4*)(r + base + c);
        va[u] = make_float4(av.x + rv.x, av.y + rv.y, av.z + rv.z, av.w + rv.w);
        s += va[u].x + va[u].y + va[u].z + va[u].w;
    }
    const float mu = warpsum(s) * (1.f / Hd);
    float s2 = 0.f;
    #pragma unroll
    for (int u = 0; u < 3; u++) {
        float d;
        d = va[u].x - mu; s2 += d * d;
        d = va[u].y - mu; s2 += d * d;
        d = va[u].z - mu; s2 += d * d;
        d = va[u].w - mu; s2 += d * d;
    }
    const float rstd = rsqrtf(warpsum(s2) * (1.f / Hd) + 1e-5f);
    float s3 = 0.f;
    #pragma unroll
    for (int u = 0; u < 3; u++) {
        const int c = u * 128 + lane * 4;
        float4 gv = *(const float4*)(g + c);
        float4 bv = *(const float4*)(be + c);
        float4 o;
        o.x = (va[u].x - mu) * rstd * gv.x + bv.x;
        o.y = (va[u].y - mu) * rstd * gv.y + bv.y;
        o.z = (va[u].z - mu) * rstd * gv.z + bv.z;
        o.w = (va[u].w - mu) * rstd * gv.w + bv.w;
        *(float4*)(out + base + c) = o;
        *(__half2*)(outh + base + c)     = __floats2half2_rn(o.x, o.y);
        *(__half2*)(outh + base + c + 2) = __floats2half2_rn(o.z, o.w);
        s3 += o.x * o.x + o.y * o.y + o.z * o.z + o.w * o.w;
    }
    if (sqout) {
        s3 = warpsum(s3);
        if (lane == 0) sqout[row] = s3;
    }
}

// ---------------- masked outputs ----------------
__global__ void out_x_kernel(const float* __restrict__ x, const float* __restrict__ mask,
                             float* __restrict__ out) {
    size_t idx = (size_t)blockIdx.x * blockDim.x + threadIdx.x;
    if (idx >= (size_t)Bn * Nn * XDim) return;
    out[idx] = x[idx] * mask[idx / XDim];
}
__global__ void out_e_kernel(const float* __restrict__ e, const float* __restrict__ mask,
                             float* __restrict__ out) {
    size_t pair = (size_t)blockIdx.x * blockDim.x + threadIdx.x;
    if (pair >= (size_t)Bn * Nn * Nn) return;
    int j  = (int)(pair & (Nn - 1));
    size_t bi = pair >> 8;
    int b  = (int)(bi >> 8);
    float mm = mask[bi] * mask[(size_t)b * Nn + j];
    const float* ep = e + pair * EDim;
    float* op = out + pair * EDim;
    #pragma unroll
    for (int k = 0; k < EDim; k++) op[k] = ep[k] * mm;
}
__global__ void out_z_kernel(const float* __restrict__ mask, float* __restrict__ out) {
    size_t idx = (size_t)blockIdx.x * blockDim.x + threadIdx.x;
    if (idx >= (size_t)Mrows * Hd) return;
    out[idx] = g_z[idx] * mask[idx / Hd];
}

// ---------------- launcher ----------------
extern "C" void kernel_launch(void* const* d_in, const int* in_sizes, int n_in,
                              void* d_out, int out_size) {
    const float* x    = (const float*)d_in[0];
    const float* e    = (const float*)d_in[1];
    const float* mask = (const float*)d_in[2];
    const float* Wemb = (const float*)d_in[3];
    const float* Wq = (const float*)d_in[4];  const float* bq = (const float*)d_in[5];
    const float* Wk = (const float*)d_in[6];  const float* bk = (const float*)d_in[7];
    const float* Wv = (const float*)d_in[8];  const float* bv = (const float*)d_in[9];
    const float* Wo = (const float*)d_in[10]; const float* bo = (const float*)d_in[11];
    const float* g1 = (const float*)d_in[12]; const float* be1 = (const float*)d_in[13];
    const float* W1 = (const float*)d_in[14]; const float* b1  = (const float*)d_in[15];
    const float* W2 = (const float*)d_in[16]; const float* b2  = (const float*)d_in[17];
    const float* g2 = (const float*)d_in[18]; const float* be2 = (const float*)d_in[19];
    float* out = (float*)d_out;

    float  *z, *q, *x1, *sq, *bqkv;
    __half *cath, *zh, *x1h, *yh, *ffnh, *qhp, *khp;
    __half *wembTh, *wqkvT, *woTh, *w1Th, *w2Th;
    cudaGetSymbolAddress((void**)&cath,  g_cath);
    cudaGetSymbolAddress((void**)&z,     g_z);
    cudaGetSymbolAddress((void**)&zh,    g_zh);
    cudaGetSymbolAddress((void**)&q,     g_q);
    cudaGetSymbolAddress((void**)&yh,    g_yh);
    cudaGetSymbolAddress((void**)&x1,    g_x1);
    cudaGetSymbolAddress((void**)&x1h,   g_x1h);
    cudaGetSymbolAddress((void**)&ffnh,  g_ffnh);
    cudaGetSymbolAddress((void**)&qhp,   g_qhp);
    cudaGetSymbolAddress((void**)&khp,   g_khp);
    cudaGetSymbolAddress((void**)&sq,    g_sq);
    cudaGetSymbolAddress((void**)&bqkv,  g_bqkv);
    cudaGetSymbolAddress((void**)&wembTh, g_wembTh);
    cudaGetSymbolAddress((void**)&wqkvT, g_wqkvT);
    cudaGetSymbolAddress((void**)&woTh,  g_woTh);
    cudaGetSymbolAddress((void**)&w1Th,  g_w1Th);
    cudaGetSymbolAddress((void**)&w2Th,  g_w2Th);

    cudaFuncSetAttribute(gemm_h_kernel,
                         cudaFuncAttributeMaxDynamicSharedMemorySize, GK_SMEM_B);
    cudaFuncSetAttribute(dqkv_kernel,
                         cudaFuncAttributeMaxDynamicSharedMemorySize, DQ_SMEM);
    cudaFuncSetAttribute(attn_kernel,
                         cudaFuncAttributeMaxDynamicSharedMemorySize, AT_SMEM);

    dim3 tb(32, 8);
    {
        size_t tot = (size_t)Mrows * KPAD;
        cat_kernel<<<(unsigned)((tot + 255) / 256), 256>>>(x, e);
    }
    transpose_kernel<<<dim3(12, 44, 1), tb>>>(Wemb, wembTh, KCAT, Hd, KPAD, 0, 0);
    transpose_kernel<<<dim3(12, 12, DEPTH), tb>>>(Wq, wqkvT, Hd, Hd, Hd,
                                                  (size_t)Hd * Hd, (size_t)H3 * Hd);
    transpose_kernel<<<dim3(12, 12, DEPTH), tb>>>(Wk, wqkvT + (size_t)Hd * Hd, Hd, Hd, Hd,
                                                  (size_t)Hd * Hd, (size_t)H3 * Hd);
    transpose_kernel<<<dim3(12, 12, DEPTH), tb>>>(Wv, wqkvT + 2 * (size_t)Hd * Hd, Hd, Hd, Hd,
                                                  (size_t)Hd * Hd, (size_t)H3 * Hd);
    qkvbias_kernel<<<(DEPTH * H3 + 255) / 256, 256>>>(bq, bk, bv);
    gemm_h_kernel<<<dim3(Hd / 128, Mrows / 128), 256, GK_SMEM_B>>>(
        cath, KPAD, wembTh, KPAD, nullptr, z, zh, Hd, KPAD, 0);
    transpose_kernel<<<dim3(12, 12, DEPTH), tb>>>(Wo, woTh, Hd, Hd, Hd,
                                                  (size_t)Hd * Hd, (size_t)Hd * Hd);
    transpose_kernel<<<dim3(48, 12, DEPTH), tb>>>(W1, w1Th, Hd, DFFd, Hd,
                                                  (size_t)Hd * DFFd, (size_t)DFFd * Hd);
    transpose_kernel<<<dim3(12, 48, DEPTH), tb>>>(W2, w2Th, DFFd, Hd, DFFd,
                                                  (size_t)DFFd * Hd, (size_t)Hd * DFFd);
    sqnorm_kernel<<<Mrows, 128>>>();

    for (int l = 0; l < DEPTH; l++) {
        const size_t wofs  = (size_t)l * Hd * Hd;
        const size_t w1ofs = (size_t)l * DFFd * Hd;
        // fat kernel: QKV GEMM tiles + distrow tiles in one launch
        dqkv_kernel<<<1152 + 256, 256, DQ_SMEM>>>(
            zh, wqkvT + (size_t)l * H3 * Hd, bqkv + (size_t)l * H3, mask);
        // fully fused attention
        attn_kernel<<<dim3(4, Bn * NHd), 256, AT_SMEM>>>(qhp, khp);
        // output projection + AddNorm
        gemm_h_kernel<<<dim3(Hd / 128, Mrows / 128), 256, GK_SMEM_B>>>(
            yh, Hd, woTh + wofs, Hd, bo + (size_t)l * Hd, q, nullptr, Hd, Hd, 0);
        addln_kernel<<<Mrows / 8, 256>>>(z, q, g1 + (size_t)l * Hd, be1 + (size_t)l * Hd,
                                         x1, x1h, nullptr);
        // FFN
        gemm_h_kernel<<<dim3(DFFd / 128, Mrows / 128), 256, GK_SMEM_B>>>(
            x1h, Hd, w1Th + w1ofs, Hd, b1 + (size_t)l * DFFd,
            nullptr, ffnh, DFFd, Hd, 1);
        gemm_h_kernel<<<dim3(Hd / 128, Mrows / 128), 256, GK_SMEM_B>>>(
            ffnh, DFFd, w2Th + w1ofs, DFFd, b2 + (size_t)l * Hd,
            q, nullptr, Hd, DFFd, 0);
        addln_kernel<<<Mrows / 8, 256>>>(x1, q, g2 + (size_t)l * Hd, be2 + (size_t)l * Hd,
                                         z, zh, sq);
    }

    // outputs: [X_out | E_out | z_out]
    const size_t XTOT = (size_t)Bn * Nn * XDim;
    const size_t ETOT = (size_t)Bn * Nn * Nn * EDim;
    const size_t ZTOT = (size_t)Mrows * Hd;
    const size_t EPAIRS = (size_t)Bn * Nn * Nn;
    out_x_kernel<<<(unsigned)((XTOT + 255) / 256), 256>>>(x, mask, out);
    out_e_kernel<<<(unsigned)((EPAIRS + 255) / 256), 256>>>(e, mask, out + XTOT);
    out_z_kernel<<<(unsigned)((ZTOT + 255) / 256), 256>>>(mask, out + XTOT + ETOT);
    (void)in_sizes; (void)n_in; (void)out_size;
}

// round 16
// speedup vs baseline: 1.2847x; 1.0896x over previous
#include <cuda_runtime.h>
#include <cuda_fp16.h>
#include <math.h>
#include <stdint.h>

#define Bn    64
#define Nn    256
#define XDim  118
#define EDim  5
#define Hd    384
#define NHd   8
#define DHd   48
#define DFFd  1536
#define DEPTH 6
#define Mrows (Bn * Nn)            /* 16384 */
#define KCAT  (XDim + Nn * EDim)   /* 1398  */
#define KPAD  1408                 /* divisible by 64 */
#define EROW  (Nn * EDim)
#define H3    (3 * Hd)             /* 1152 */

// ---------------- scratch (device globals; zero-init, no allocation) ----------------
__device__ __half g_cath[(size_t)Mrows * KPAD];
__device__ float  g_z  [(size_t)Mrows * Hd];
__device__ __half g_zh [(size_t)Mrows * Hd];
__device__ float  g_q  [(size_t)Mrows * Hd];
__device__ __half g_yh [(size_t)Mrows * Hd];
__device__ float  g_x1 [(size_t)Mrows * Hd];
__device__ __half g_x1h[(size_t)Mrows * Hd];
__device__ __half g_ffnh[(size_t)Mrows * DFFd];
__device__ float  g_D  [(size_t)Bn * Nn * Nn];
__device__ float  g_sq [Mrows];
__device__ __half g_qhp[(size_t)Bn * NHd * Nn * 64];
__device__ __half g_khp[(size_t)Bn * NHd * Nn * 64];
__device__ __half g_vth[(size_t)Bn * NHd * DHd * Nn];
__device__ __half g_wembTh[(size_t)Hd * KPAD];
__device__ __half g_wqkvT[(size_t)DEPTH * H3 * Hd];
__device__ float  g_bqkv [(size_t)DEPTH * H3];
__device__ __half g_woTh [(size_t)DEPTH * Hd * Hd];
__device__ __half g_w1Th [(size_t)DEPTH * DFFd * Hd];
__device__ __half g_w2Th [(size_t)DEPTH * Hd * DFFd];

// ---------------- PTX helpers (sm_80+ base ISA) ----------------
__device__ __forceinline__ uint32_t smem_to_u32(const void* p) {
    uint32_t a;
    asm("{ .reg .u64 t; cvta.to.shared.u64 t, %1; cvt.u32.u64 %0, t; }"
        : "=r"(a) : "l"(p));
    return a;
}
#define CP_ASYNC16(dst, src) \
    asm volatile("cp.async.cg.shared.global [%0], [%1], 16;" \
                 :: "r"(dst), "l"(src) : "memory")
#define CP_COMMIT() asm volatile("cp.async.commit_group;" ::: "memory")
#define CP_WAIT1()  asm volatile("cp.async.wait_group 1;" ::: "memory")
#define CP_WAIT0()  asm volatile("cp.async.wait_group 0;" ::: "memory")
#define LDSM4(r, addr) \
    asm volatile("ldmatrix.sync.aligned.m8n8.x4.shared.b16 {%0,%1,%2,%3}, [%4];" \
                 : "=r"((r)[0]), "=r"((r)[1]), "=r"((r)[2]), "=r"((r)[3]) \
                 : "r"(addr))
#define MMA16816(d, a, b0_, b1_) \
    asm volatile("mma.sync.aligned.m16n8k16.row.col.f32.f16.f16.f32 " \
                 "{%0,%1,%2,%3}, {%4,%5,%6,%7}, {%8,%9}, {%0,%1,%2,%3};" \
                 : "+f"((d)[0]), "+f"((d)[1]), "+f"((d)[2]), "+f"((d)[3]) \
                 : "r"((a)[0]), "r"((a)[1]), "r"((a)[2]), "r"((a)[3]), \
                   "r"(b0_), "r"(b1_))

// ---------------- reductions ----------------
__device__ __forceinline__ float blocksum128(float v) {
    __shared__ float red[4];
    #pragma unroll
    for (int o = 16; o > 0; o >>= 1) v += __shfl_xor_sync(0xffffffffu, v, o);
    if ((threadIdx.x & 31) == 0) red[threadIdx.x >> 5] = v;
    __syncthreads();
    float s = red[0] + red[1] + red[2] + red[3];
    __syncthreads();
    return s;
}
__device__ __forceinline__ float warpsum(float v) {
    #pragma unroll
    for (int o = 16; o > 0; o >>= 1) v += __shfl_xor_sync(0xffffffffu, v, o);
    return v;
}

// ---------------- concat [x | e_flat | 0-pad] -> fp16 ----------------
__global__ void cat_kernel(const float* __restrict__ x, const float* __restrict__ e) {
    size_t idx = (size_t)blockIdx.x * blockDim.x + threadIdx.x;
    if (idx >= (size_t)Mrows * KPAD) return;
    size_t r = idx / KPAD;
    int    c = (int)(idx - r * KPAD);
    float v;
    if (c < XDim)      v = x[r * XDim + c];
    else if (c < KCAT) v = e[r * (size_t)EROW + (c - XDim)];
    else               v = 0.f;
    g_cath[idx] = __float2half(v);
}

// ---------------- transpose fp32 -> fp16 ----------------
__global__ void transpose_kernel(const float* __restrict__ in, __half* __restrict__ out,
                                 int R, int C, int outLd,
                                 size_t inStride, size_t outStride) {
    __shared__ float tile[32][33];
    const float* ip = in + (size_t)blockIdx.z * inStride;
    __half* op = out + (size_t)blockIdx.z * outStride;
    int c0 = blockIdx.x * 32, r0 = blockIdx.y * 32;
    int tx = threadIdx.x, ty = threadIdx.y;
    #pragma unroll
    for (int i = 0; i < 32; i += 8) {
        int r = r0 + ty + i, c = c0 + tx;
        tile[ty + i][tx] = (r < R && c < C) ? ip[(size_t)r * C + c] : 0.f;
    }
    __syncthreads();
    #pragma unroll
    for (int i = 0; i < 32; i += 8) {
        int oc = c0 + ty + i, orow = r0 + tx;
        if (oc < C && orow < outLd)
            op[(size_t)oc * outLd + orow] = __float2half(tile[tx][ty + i]);
    }
}

// ---------------- concat qkv bias ----------------
__global__ void qkvbias_kernel(const float* __restrict__ bq, const float* __restrict__ bk,
                               const float* __restrict__ bv) {
    int i = blockIdx.x * blockDim.x + threadIdx.x;
    if (i >= DEPTH * H3) return;
    int l = i / H3, r = i - l * H3;
    float v;
    if (r < Hd)           v = bq[l * Hd + r];
    else if (r < 2 * Hd)  v = bk[l * Hd + r - Hd];
    else                  v = bv[l * Hd + r - 2 * Hd];
    g_bqkv[i] = v;
}

// ============================================================================
// fp16 HMMA GEMM, 128x128 tiles, K-chunks of 64, 3-stage cp.async, 8 warps.
// ============================================================================
#define GK_RS      72                    /* halves per smem row (64 + 8 pad) */
#define GK_OPB     (128 * GK_RS * 2)     /* 18432 B per operand */
#define GK_STAGE_B (2 * GK_OPB)          /* 36864 B per stage */
#define GK_NSTG    3
#define GK_SMEM_B  (GK_NSTG * GK_STAGE_B)   /* 110592 */

__global__ __launch_bounds__(256)
void gemm_h_kernel(const __half* __restrict__ A, int lda,
                   const __half* __restrict__ BT, int ldb,
                   const float* __restrict__ bias,
                   float* __restrict__ C, __half* __restrict__ Ch,
                   int ldc, int K, int relu) {
    extern __shared__ char smem[];
    const uint32_t sb = smem_to_u32(smem);
    const int t = threadIdx.x, lane = t & 31, wid = t >> 5;
    const int m0 = blockIdx.y * 128, n0 = blockIdx.x * 128;
    const int mW = (wid & 3) * 32, nW = (wid >> 2) * 64;

    const int lq = lane >> 3, lr = lane & 7;
    const int aRow = (lq & 1) * 8 + lr, aCol = (lq >> 1) * 8;
    const int bRow = (lq >> 1) * 8 + lr, bCol = (lq & 1) * 8;
    const uint32_t aOff = (uint32_t)(((mW + aRow) * GK_RS + aCol) * 2);
    const uint32_t bOff = (uint32_t)(GK_OPB + ((nW + bRow) * GK_RS + bCol) * 2);

    float acc[2][8][4];
    #pragma unroll
    for (int i = 0; i < 2; i++)
        #pragma unroll
        for (int j = 0; j < 8; j++)
            #pragma unroll
            for (int r = 0; r < 4; r++) acc[i][j][r] = 0.f;

    const int nch = K >> 6;
    auto issue = [&](int ch) {
        const uint32_t dstA = sb + (uint32_t)(ch % GK_NSTG) * GK_STAGE_B;
        const uint32_t dstB = dstA + GK_OPB;
        const __half* sa  = A  + (size_t)m0 * lda + ch * 64;
        const __half* sbp = BT + (size_t)n0 * ldb + ch * 64;
        #pragma unroll
        for (int u = 0; u < 4; u++) {
            int p = t + u * 256, row = p >> 3, seg = p & 7;
            CP_ASYNC16(dstA + (uint32_t)((row * GK_RS + seg * 8) * 2),
                       sa + (size_t)row * lda + seg * 8);
            CP_ASYNC16(dstB + (uint32_t)((row * GK_RS + seg * 8) * 2),
                       sbp + (size_t)row * ldb + seg * 8);
        }
        CP_COMMIT();
    };
    issue(0);
    if (nch > 1) issue(1);

    for (int ch = 0; ch < nch; ch++) {
        if (ch + 1 < nch) { CP_WAIT1(); } else { CP_WAIT0(); }
        __syncthreads();
        const uint32_t base = sb + (uint32_t)(ch % GK_NSTG) * GK_STAGE_B;
        #pragma unroll
        for (int ks = 0; ks < 4; ks++) {
            uint32_t a[2][4], b[4][4];
            #pragma unroll
            for (int mt = 0; mt < 2; mt++)
                LDSM4(a[mt], base + aOff + (uint32_t)((mt * 16 * GK_RS + ks * 16) * 2));
            #pragma unroll
            for (int g = 0; g < 4; g++)
                LDSM4(b[g], base + bOff + (uint32_t)((g * 16 * GK_RS + ks * 16) * 2));
            #pragma unroll
            for (int mt = 0; mt < 2; mt++)
                #pragma unroll
                for (int g = 0; g < 4; g++) {
                    MMA16816(acc[mt][2 * g],     a[mt], b[g][0], b[g][1]);
                    MMA16816(acc[mt][2 * g + 1], a[mt], b[g][2], b[g][3]);
                }
        }
        if (ch + 2 < nch) issue(ch + 2);
    }

    const int rBase = m0 + mW + (lane >> 2);
    const int cBase = n0 + nW + (lane & 3) * 2;
    #pragma unroll
    for (int mt = 0; mt < 2; mt++) {
        #pragma unroll
        for (int nt = 0; nt < 8; nt++) {
            const int c = cBase + nt * 8;
            float b0 = 0.f, b1 = 0.f;
            if (bias) { b0 = bias[c]; b1 = bias[c + 1]; }
            float v00 = acc[mt][nt][0] + b0, v01 = acc[mt][nt][1] + b1;
            float v10 = acc[mt][nt][2] + b0, v11 = acc[mt][nt][3] + b1;
            if (relu) {
                v00 = fmaxf(v00, 0.f); v01 = fmaxf(v01, 0.f);
                v10 = fmaxf(v10, 0.f); v11 = fmaxf(v11, 0.f);
            }
            const int rA = rBase + mt * 16, rB = rA + 8;
            if (C) {
                *(float2*)(C + (size_t)rA * ldc + c) = make_float2(v00, v01);
                *(float2*)(C + (size_t)rB * ldc + c) = make_float2(v10, v11);
            }
            if (Ch) {
                *(__half2*)(Ch + (size_t)rA * ldc + c) = __floats2half2_rn(v00, v01);
                *(__half2*)(Ch + (size_t)rB * ldc + c) = __floats2half2_rn(v10, v11);
            }
        }
    }
}

// ============================================================================
// dqkv: fat kernel. blocks [0,1152): QKV GEMM (K=384, 64-chunks) -> head layouts;
// blocks [1152,1408): distrow (32-chunks, own smem layout).
// ============================================================================
#define DR_ARS   40
#define DR_ABUF  (64 * DR_ARS * 2)
#define DR_BBUF  (256 * DR_ARS * 2)
#define DR_STAGE (DR_ABUF + DR_BBUF)
#define DR_RED   (3 * DR_STAGE)          /* 76800 */
#define DQ_SMEM  GK_SMEM_B               /* 110592 >= DR_RED + 512 */

__global__ __launch_bounds__(256, 2)
void dqkv_kernel(const __half* __restrict__ Z,
                 const __half* __restrict__ WT, const float* __restrict__ bias,
                 const float* __restrict__ mask) {
    extern __shared__ char smem[];
    const uint32_t sb = smem_to_u32(smem);
    const int t = threadIdx.x, lane = t & 31, wid = t >> 5;
    const int lq = lane >> 3, lr = lane & 7;
    const int aRow = (lq & 1) * 8 + lr, aCol = (lq >> 1) * 8;
    const int bRow = (lq >> 1) * 8 + lr, bCol = (lq & 1) * 8;

    if (blockIdx.x < 1152) {
        const int id = blockIdx.x;
        const int m0 = (id / 9) * 128, n0 = (id % 9) * 128;
        const int mW = (wid & 3) * 32, nW = (wid >> 2) * 64;
        const uint32_t aOff = (uint32_t)(((mW + aRow) * GK_RS + aCol) * 2);
        const uint32_t bOff = (uint32_t)(GK_OPB + ((nW + bRow) * GK_RS + bCol) * 2);

        float acc[2][8][4];
        #pragma unroll
        for (int i = 0; i < 2; i++)
            #pragma unroll
            for (int j = 0; j < 8; j++)
                #pragma unroll
                for (int r = 0; r < 4; r++) acc[i][j][r] = 0.f;

        const int nch = Hd >> 6;   // 6
        auto issue = [&](int ch) {
            const uint32_t dstA = sb + (uint32_t)(ch % GK_NSTG) * GK_STAGE_B;
            const uint32_t dstB = dstA + GK_OPB;
            const __half* sa  = Z  + (size_t)m0 * Hd + ch * 64;
            const __half* sbp = WT + (size_t)n0 * Hd + ch * 64;
            #pragma unroll
            for (int u = 0; u < 4; u++) {
                int p = t + u * 256, row = p >> 3, seg = p & 7;
                CP_ASYNC16(dstA + (uint32_t)((row * GK_RS + seg * 8) * 2),
                           sa + (size_t)row * Hd + seg * 8);
                CP_ASYNC16(dstB + (uint32_t)((row * GK_RS + seg * 8) * 2),
                           sbp + (size_t)row * Hd + seg * 8);
            }
            CP_COMMIT();
        };
        issue(0); issue(1);

        for (int ch = 0; ch < nch; ch++) {
            if (ch + 1 < nch) { CP_WAIT1(); } else { CP_WAIT0(); }
            __syncthreads();
            const uint32_t base = sb + (uint32_t)(ch % GK_NSTG) * GK_STAGE_B;
            #pragma unroll
            for (int ks = 0; ks < 4; ks++) {
                uint32_t a[2][4], b[4][4];
                #pragma unroll
                for (int mt = 0; mt < 2; mt++)
                    LDSM4(a[mt], base + aOff + (uint32_t)((mt * 16 * GK_RS + ks * 16) * 2));
                #pragma unroll
                for (int g = 0; g < 4; g++)
                    LDSM4(b[g], base + bOff + (uint32_t)((g * 16 * GK_RS + ks * 16) * 2));
                #pragma unroll
                for (int mt = 0; mt < 2; mt++)
                    #pragma unroll
                    for (int g = 0; g < 4; g++) {
                        MMA16816(acc[mt][2 * g],     a[mt], b[g][0], b[g][1]);
                        MMA16816(acc[mt][2 * g + 1], a[mt], b[g][2], b[g][3]);
                    }
            }
            if (ch + 2 < nch) issue(ch + 2);
        }

        const int rBase = m0 + mW + (lane >> 2);
        const int cBase = n0 + nW + (lane & 3) * 2;
        #pragma unroll
        for (int mt = 0; mt < 2; mt++) {
            #pragma unroll
            for (int nt = 0; nt < 8; nt++) {
                const int c = cBase + nt * 8;
                const float b0 = bias[c], b1 = bias[c + 1];
                float v00 = acc[mt][nt][0] + b0, v01 = acc[mt][nt][1] + b1;
                float v10 = acc[mt][nt][2] + b0, v11 = acc[mt][nt][3] + b1;
                const int rA = rBase + mt * 16, rB = rA + 8;
                const int sec = c / Hd;
                const int cc  = c - sec * Hd;
                const int h = cc / DHd, d = cc - h * DHd;
                const int bIdx = rA >> 8;
                if (sec < 2) {
                    __half* dst = (sec == 0) ? g_qhp : g_khp;
                    size_t p0 = ((((size_t)bIdx * NHd + h) << 8) | (rA & 255)) * 64 + d;
                    size_t p1 = ((((size_t)bIdx * NHd + h) << 8) | (rB & 255)) * 64 + d;
                    *(__half2*)(dst + p0) = __floats2half2_rn(v00, v01);
                    *(__half2*)(dst + p1) = __floats2half2_rn(v10, v11);
                } else {
                    size_t hb = ((size_t)bIdx * NHd + h) * DHd;
                    g_vth[(hb + d)     * Nn + (rA & 255)] = __float2half(v00);
                    g_vth[(hb + d + 1) * Nn + (rA & 255)] = __float2half(v01);
                    g_vth[(hb + d)     * Nn + (rB & 255)] = __float2half(v10);
                    g_vth[(hb + d + 1) * Nn + (rB & 255)] = __float2half(v11);
                }
            }
        }
    } else {
        // ---------------- distrow tile (unchanged 32-chunk pipeline) ----------------
        const int id = blockIdx.x - 1152;
        const int bz = id >> 2, m0 = (id & 3) * 64;
        float* rmax = (float*)(smem + DR_RED);
        const __half* A = Z + (size_t)bz * Nn * Hd + (size_t)m0 * Hd;
        const __half* B = Z + (size_t)bz * Nn * Hd;
        const int mW = (wid & 3) * 16, nW = (wid >> 2) * 128;
        const uint32_t aOff = (uint32_t)(((mW + aRow) * DR_ARS + aCol) * 2);
        const uint32_t bOff = (uint32_t)(DR_ABUF + ((nW + bRow) * DR_ARS + bCol) * 2);

        float acc[16][4];
        #pragma unroll
        for (int j = 0; j < 16; j++)
            #pragma unroll
            for (int r = 0; r < 4; r++) acc[j][r] = 0.f;

        auto issue = [&](int ch) {
            const uint32_t dstA = sb + (uint32_t)(ch % 3) * DR_STAGE;
            const uint32_t dstB = dstA + DR_ABUF;
            CP_ASYNC16(dstA + (uint32_t)(((t >> 2) * DR_ARS + (t & 3) * 8) * 2),
                       A + (size_t)(t >> 2) * Hd + ch * 32 + (t & 3) * 8);
            #pragma unroll
            for (int u = 0; u < 4; u++) {
                int p = t + u * 256, row = p >> 2, seg = p & 3;
                CP_ASYNC16(dstB + (uint32_t)((row * DR_ARS + seg * 8) * 2),
                           B + (size_t)row * Hd + ch * 32 + seg * 8);
            }
            CP_COMMIT();
        };
        issue(0); issue(1);

        const int nch = Hd >> 5;
        for (int ch = 0; ch < nch; ch++) {
            if (ch + 1 < nch) { CP_WAIT1(); } else { CP_WAIT0(); }
            __syncthreads();
            const uint32_t base = sb + (uint32_t)(ch % 3) * DR_STAGE;
            #pragma unroll
            for (int ks = 0; ks < 2; ks++) {
                uint32_t a[4];
                LDSM4(a, base + aOff + (uint32_t)(ks * 16 * 2));
                #pragma unroll
                for (int g = 0; g < 8; g++) {
                    uint32_t bf[4];
                    LDSM4(bf, base + bOff + (uint32_t)((g * 16 * DR_ARS + ks * 16) * 2));
                    MMA16816(acc[2 * g],     a, bf[0], bf[1]);
                    MMA16816(acc[2 * g + 1], a, bf[2], bf[3]);
                }
            }
            if (ch + 2 < nch) issue(ch + 2);
        }

        const int rloc0 = mW + (lane >> 2), rloc1 = rloc0 + 8;
        const int gi0 = m0 + rloc0, gi1 = m0 + rloc1;
        const int cB = nW + (lane & 3) * 2;
        const float sqi0 = g_sq[bz * Nn + gi0], sqi1 = g_sq[bz * Nn + gi1];
        const float mi0 = mask[bz * Nn + gi0],  mi1 = mask[bz * Nn + gi1];
        #pragma unroll
        for (int nt = 0; nt < 16; nt++) {
            const int gj = cB + nt * 8;
            float sj0 = g_sq[bz * Nn + gj], sj1 = g_sq[bz * Nn + gj + 1];
            float mj0 = mask[bz * Nn + gj], mj1 = mask[bz * Nn + gj + 1];
            float d2;
            d2 = fmaxf(sqi0 + sj0 - 2.f * acc[nt][0], 0.f);
            acc[nt][0] = ((d2 > 1e-12f) ? sqrtf(d2) : 0.f) * mi0 * mj0;
            d2 = fmaxf(sqi0 + sj1 - 2.f * acc[nt][1], 0.f);
            acc[nt][1] = ((d2 > 1e-12f) ? sqrtf(d2) : 0.f) * mi0 * mj1;
            d2 = fmaxf(sqi1 + sj0 - 2.f * acc[nt][2], 0.f);
            acc[nt][2] = ((d2 > 1e-12f) ? sqrtf(d2) : 0.f) * mi1 * mj0;
            d2 = fmaxf(sqi1 + sj1 - 2.f * acc[nt][3], 0.f);
            acc[nt][3] = ((d2 > 1e-12f) ? sqrtf(d2) : 0.f) * mi1 * mj1;
        }
        float mx0 = 0.f, mx1 = 0.f;
        #pragma unroll
        for (int nt = 0; nt < 16; nt++) {
            mx0 = fmaxf(mx0, fmaxf(acc[nt][0], acc[nt][1]));
            mx1 = fmaxf(mx1, fmaxf(acc[nt][2], acc[nt][3]));
        }
        #pragma unroll
        for (int o = 1; o < 4; o <<= 1) {
            mx0 = fmaxf(mx0, __shfl_xor_sync(0xffffffffu, mx0, o));
            mx1 = fmaxf(mx1, __shfl_xor_sync(0xffffffffu, mx1, o));
        }
        const int nw = wid >> 2;
        rmax[nw * 64 + rloc0] = mx0;
        rmax[nw * 64 + rloc1] = mx1;
        __syncthreads();
        const float M0 = fmaxf(rmax[rloc0], rmax[64 + rloc0]);
        const float M1 = fmaxf(rmax[rloc1], rmax[64 + rloc1]);
        float* Dp = g_D + (size_t)bz * Nn * Nn;
        #pragma unroll
        for (int nt = 0; nt < 16; nt++) {
            const int gj = cB + nt * 8;
            float mj0 = mask[bz * Nn + gj], mj1 = mask[bz * Nn + gj + 1];
            float o00 = (gi0 == gj)     ? 0.f : (M0 - acc[nt][0]) * mi0 * mj0;
            float o01 = (gi0 == gj + 1) ? 0.f : (M0 - acc[nt][1]) * mi0 * mj1;
            float o10 = (gi1 == gj)     ? 0.f : (M1 - acc[nt][2]) * mi1 * mj0;
            float o11 = (gi1 == gj + 1) ? 0.f : (M1 - acc[nt][3]) * mi1 * mj1;
            *(float2*)(Dp + (size_t)gi0 * Nn + gj) = make_float2(o00, o01);
            *(float2*)(Dp + (size_t)gi1 * Nn + gj) = make_float2(o10, o11);
        }
    }
}

// ============================================================================
// attn: fused QK^T + D-bias + softmax + P@V^T. AV split across all 8 warps.
// ============================================================================
#define AT_ARS   72
#define AT_PRS   264
#define AT_QBUF  0
#define AT_KBUF  (64 * AT_ARS * 2)
#define AT_PBUF  (AT_KBUF + 256 * AT_ARS * 2)
#define AT_VBUF  (AT_PBUF + 64 * AT_PRS * 2)
#define AT_RED   (AT_VBUF + 48 * AT_PRS * 2)
#define AT_SMEM  (AT_RED + 2 * 128 * 4)

__global__ __launch_bounds__(256)
void attn_kernel(const __half* __restrict__ qhp, const __half* __restrict__ khp) {
    extern __shared__ char smem[];
    const uint32_t sb = smem_to_u32(smem);
    float* rmax = (float*)(smem + AT_RED);
    float* rsum = rmax + 128;
    const int t = threadIdx.x, lane = t & 31, wid = t >> 5;
    const int bh = blockIdx.y, m0 = blockIdx.x * 64;
    const int b = bh >> 3, h = bh & 7;
    const __half* Aq = qhp + (size_t)bh * Nn * 64 + (size_t)m0 * 64;
    const __half* Bk = khp + (size_t)bh * Nn * 64;
    const __half* Vt = g_vth + (size_t)bh * DHd * Nn;
    const int mW = (wid & 3) * 16, nW = (wid >> 2) * 128;

    #pragma unroll
    for (int u = 0; u < 2; u++) {
        int p = t + u * 256, row = p >> 3, seg = p & 7;
        CP_ASYNC16(sb + AT_QBUF + (uint32_t)((row * AT_ARS + seg * 8) * 2),
                   Aq + (size_t)row * 64 + seg * 8);
    }
    #pragma unroll
    for (int u = 0; u < 8; u++) {
        int p = t + u * 256, row = p >> 3, seg = p & 7;
        CP_ASYNC16(sb + AT_KBUF + (uint32_t)((row * AT_ARS + seg * 8) * 2),
                   Bk + (size_t)row * 64 + seg * 8);
    }
    #pragma unroll
    for (int u = 0; u < 6; u++) {
        int p = t + u * 256, row = p >> 5, seg = p & 31;
        CP_ASYNC16(sb + AT_VBUF + (uint32_t)((row * AT_PRS + seg * 8) * 2),
                   Vt + (size_t)row * Nn + seg * 8);
    }
    CP_COMMIT();
    CP_WAIT0();
    __syncthreads();

    const int lq = lane >> 3, lr = lane & 7;
    const int aRow = (lq & 1) * 8 + lr, aCol = (lq >> 1) * 8;
    const int bRow = (lq >> 1) * 8 + lr, bCol = (lq & 1) * 8;
    const uint32_t aOff = sb + AT_QBUF + (uint32_t)(((mW + aRow) * AT_ARS + aCol) * 2);
    const uint32_t bOff = sb + AT_KBUF + (uint32_t)(((nW + bRow) * AT_ARS + bCol) * 2);

    float acc[16][4];
    #pragma unroll
    for (int j = 0; j < 16; j++)
        #pragma unroll
        for (int r = 0; r < 4; r++) acc[j][r] = 0.f;

    #pragma unroll
    for (int ks = 0; ks < 4; ks++) {
        uint32_t a[4];
        LDSM4(a, aOff + (uint32_t)(ks * 16 * 2));
        #pragma unroll
        for (int g = 0; g < 8; g++) {
            uint32_t bf[4];
            LDSM4(bf, bOff + (uint32_t)((g * 16 * AT_ARS + ks * 16) * 2));
            MMA16816(acc[2 * g],     a, bf[0], bf[1]);
            MMA16816(acc[2 * g + 1], a, bf[2], bf[3]);
        }
    }

    const float scale = 0.144337567297406441f;
    const int rloc0 = mW + (lane >> 2), rloc1 = rloc0 + 8;
    const int gi0 = m0 + rloc0, gi1 = m0 + rloc1;
    const int cB = nW + (lane & 3) * 2;
    #pragma unroll
    for (int nt = 0; nt < 16; nt++) {
        const int gj = cB + nt * 8;
        float2 d0 = *(const float2*)(g_D + ((size_t)b * Nn + gi0) * Nn + gj);
        float2 d1 = *(const float2*)(g_D + ((size_t)b * Nn + gi1) * Nn + gj);
        acc[nt][0] = acc[nt][0] * scale + d0.x;
        acc[nt][1] = acc[nt][1] * scale + d0.y;
        acc[nt][2] = acc[nt][2] * scale + d1.x;
        acc[nt][3] = acc[nt][3] * scale + d1.y;
    }
    float mx0 = -1e30f, mx1 = -1e30f;
    #pragma unroll
    for (int nt = 0; nt < 16; nt++) {
        mx0 = fmaxf(mx0, fmaxf(acc[nt][0], acc[nt][1]));
        mx1 = fmaxf(mx1, fmaxf(acc[nt][2], acc[nt][3]));
    }
    #pragma unroll
    for (int o = 1; o < 4; o <<= 1) {
        mx0 = fmaxf(mx0, __shfl_xor_sync(0xffffffffu, mx0, o));
        mx1 = fmaxf(mx1, __shfl_xor_sync(0xffffffffu, mx1, o));
    }
    const int nwg = wid >> 2;
    rmax[nwg * 64 + rloc0] = mx0;
    rmax[nwg * 64 + rloc1] = mx1;
    __syncthreads();
    const float M0 = fmaxf(rmax[rloc0], rmax[64 + rloc0]);
    const float M1 = fmaxf(rmax[rloc1], rmax[64 + rloc1]);
    float s0 = 0.f, s1 = 0.f;
    #pragma unroll
    for (int nt = 0; nt < 16; nt++) {
        acc[nt][0] = __expf(acc[nt][0] - M0);
        acc[nt][1] = __expf(acc[nt][1] - M0);
        acc[nt][2] = __expf(acc[nt][2] - M1);
        acc[nt][3] = __expf(acc[nt][3] - M1);
        s0 += acc[nt][0] + acc[nt][1];
        s1 += acc[nt][2] + acc[nt][3];
    }
    #pragma unroll
    for (int o = 1; o < 4; o <<= 1) {
        s0 += __shfl_xor_sync(0xffffffffu, s0, o);
        s1 += __shfl_xor_sync(0xffffffffu, s1, o);
    }
    rsum[nwg * 64 + rloc0] = s0;
    rsum[nwg * 64 + rloc1] = s1;
    __syncthreads();
    const float inv0 = 1.f / (rsum[rloc0] + rsum[64 + rloc0]);
    const float inv1 = 1.f / (rsum[rloc1] + rsum[64 + rloc1]);
    #pragma unroll
    for (int nt = 0; nt < 16; nt++) {
        const int gj = cB + nt * 8;
        *(__half2*)(smem + AT_PBUF + ((size_t)rloc0 * AT_PRS + gj) * 2) =
            __floats2half2_rn(acc[nt][0] * inv0, acc[nt][1] * inv0);
        *(__half2*)(smem + AT_PBUF + ((size_t)rloc1 * AT_PRS + gj) * 2) =
            __floats2half2_rn(acc[nt][2] * inv1, acc[nt][3] * inv1);
    }
    __syncthreads();

    {
        const int mW2 = (wid & 3) * 16;
        const int ksBase = (wid >> 2) * 8;
        const uint32_t pOff = sb + AT_PBUF + (uint32_t)(((mW2 + aRow) * AT_PRS + aCol) * 2);
        const uint32_t vOff = sb + AT_VBUF + (uint32_t)((bRow * AT_PRS + bCol) * 2);
        float av[6][4];
        #pragma unroll
        for (int j = 0; j < 6; j++)
            #pragma unroll
            for (int r = 0; r < 4; r++) av[j][r] = 0.f;
        #pragma unroll
        for (int ks = 0; ks < 8; ks++) {
            const int ksi = ksBase + ks;
            uint32_t a[4];
            LDSM4(a, pOff + (uint32_t)(ksi * 16 * 2));
            #pragma unroll
            for (int g = 0; g < 3; g++) {
                uint32_t bf[4];
                LDSM4(bf, vOff + (uint32_t)((g * 16 * AT_PRS + ksi * 16) * 2));
                MMA16816(av[2 * g],     a, bf[0], bf[1]);
                MMA16816(av[2 * g + 1], a, bf[2], bf[3]);
            }
        }
        float* pbuf = (float*)smem;
        const int rl = mW2 + (lane >> 2);
        const int cb2 = (lane & 3) * 2;
        if (wid >= 4) {
            #pragma unroll
            for (int nt = 0; nt < 6; nt++) {
                const int c = cb2 + nt * 8;
                pbuf[(rl)     * 48 + c]     = av[nt][0];
                pbuf[(rl)     * 48 + c + 1] = av[nt][1];
                pbuf[(rl + 8) * 48 + c]     = av[nt][2];
                pbuf[(rl + 8) * 48 + c + 1] = av[nt][3];
            }
        }
        __syncthreads();
        if (wid < 4) {
            const int rA = m0 + rl;
            #pragma unroll
            for (int nt = 0; nt < 6; nt++) {
                const int c = cb2 + nt * 8;
                float v00 = av[nt][0] + pbuf[(rl)     * 48 + c];
                float v01 = av[nt][1] + pbuf[(rl)     * 48 + c + 1];
                float v10 = av[nt][2] + pbuf[(rl + 8) * 48 + c];
                float v11 = av[nt][3] + pbuf[(rl + 8) * 48 + c + 1];
                *(__half2*)(g_yh + ((size_t)b * Nn + rA) * Hd + h * DHd + c) =
                    __floats2half2_rn(v00, v01);
                *(__half2*)(g_yh + ((size_t)b * Nn + rA + 8) * Hd + h * DHd + c) =
                    __floats2half2_rn(v10, v11);
            }
        }
    }
}

// ---------------- row squared norms of z (post-embed only) ----------------
__global__ void sqnorm_kernel() {
    int r = blockIdx.x;
    float s = 0.f;
    for (int c = threadIdx.x; c < Hd; c += 128) {
        float v = g_z[(size_t)r * Hd + c];
        s += v * v;
    }
    s = blocksum128(s);
    if (threadIdx.x == 0) g_sq[r] = s;
}

// ---------------- out = LayerNorm(a + r); warp-per-row, 8 rows/block ----------------
__global__ __launch_bounds__(256)
void addln_kernel(const float* __restrict__ a, const float* __restrict__ r,
                  const float* __restrict__ g, const float* __restrict__ be,
                  float* __restrict__ out, __half* __restrict__ outh,
                  float* __restrict__ sqout) {
    const int lane = threadIdx.x & 31;
    const int row = blockIdx.x * 8 + (threadIdx.x >> 5);
    const size_t base = (size_t)row * Hd;
    float4 va[3];
    float s = 0.f;
    #pragma unroll
    for (int u = 0; u < 3; u++) {
        const int c = u * 128 + lane * 4;
        float4 av = *(const float4*)(a + base + c);
        float4 rv = *(const float4*)(r + base + c);
        va[u] = make_float4(av.x + rv.x, av.y + rv.y, av.z + rv.z, av.w + rv.w);
        s += va[u].x + va[u].y + va[u].z + va[u].w;
    }
    const float mu = warpsum(s) * (1.f / Hd);
    float s2 = 0.f;
    #pragma unroll
    for (int u = 0; u < 3; u++) {
        float d;
        d = va[u].x - mu; s2 += d * d;
        d = va[u].y - mu; s2 += d * d;
        d = va[u].z - mu; s2 += d * d;
        d = va[u].w - mu; s2 += d * d;
    }
    const float rstd = rsqrtf(warpsum(s2) * (1.f / Hd) + 1e-5f);
    float s3 = 0.f;
    #pragma unroll
    for (int u = 0; u < 3; u++) {
        const int c = u * 128 + lane * 4;
        float4 gv = *(const float4*)(g + c);
        float4 bv = *(const float4*)(be + c);
        float4 o;
        o.x = (va[u].x - mu) * rstd * gv.x + bv.x;
        o.y = (va[u].y - mu) * rstd * gv.y + bv.y;
        o.z = (va[u].z - mu) * rstd * gv.z + bv.z;
        o.w = (va[u].w - mu) * rstd * gv.w + bv.w;
        *(float4*)(out + base + c) = o;
        *(__half2*)(outh + base + c)     = __floats2half2_rn(o.x, o.y);
        *(__half2*)(outh + base + c + 2) = __floats2half2_rn(o.z, o.w);
        s3 += o.x * o.x + o.y * o.y + o.z * o.z + o.w * o.w;
    }
    if (sqout) {
        s3 = warpsum(s3);
        if (lane == 0) sqout[row] = s3;
    }
}

// ---------------- masked outputs ----------------
__global__ void out_x_kernel(const float* __restrict__ x, const float* __restrict__ mask,
                             float* __restrict__ out) {
    size_t idx = (size_t)blockIdx.x * blockDim.x + threadIdx.x;
    if (idx >= (size_t)Bn * Nn * XDim) return;
    out[idx] = x[idx] * mask[idx / XDim];
}
__global__ void out_e_kernel(const float* __restrict__ e, const float* __restrict__ mask,
                             float* __restrict__ out) {
    size_t pair = (size_t)blockIdx.x * blockDim.x + threadIdx.x;
    if (pair >= (size_t)Bn * Nn * Nn) return;
    int j  = (int)(pair & (Nn - 1));
    size_t bi = pair >> 8;
    int b  = (int)(bi >> 8);
    float mm = mask[bi] * mask[(size_t)b * Nn + j];
    const float* ep = e + pair * EDim;
    float* op = out + pair * EDim;
    #pragma unroll
    for (int k = 0; k < EDim; k++) op[k] = ep[k] * mm;
}
__global__ void out_z_kernel(const float* __restrict__ mask, float* __restrict__ out) {
    size_t idx = (size_t)blockIdx.x * blockDim.x + threadIdx.x;
    if (idx >= (size_t)Mrows * Hd) return;
    out[idx] = g_z[idx] * mask[idx / Hd];
}

// ---------------- launcher ----------------
extern "C" void kernel_launch(void* const* d_in, const int* in_sizes, int n_in,
                              void* d_out, int out_size) {
    const float* x    = (const float*)d_in[0];
    const float* e    = (const float*)d_in[1];
    const float* mask = (const float*)d_in[2];
    const float* Wemb = (const float*)d_in[3];
    const float* Wq = (const float*)d_in[4];  const float* bq = (const float*)d_in[5];
    const float* Wk = (const float*)d_in[6];  const float* bk = (const float*)d_in[7];
    const float* Wv = (const float*)d_in[8];  const float* bv = (const float*)d_in[9];
    const float* Wo = (const float*)d_in[10]; const float* bo = (const float*)d_in[11];
    const float* g1 = (const float*)d_in[12]; const float* be1 = (const float*)d_in[13];
    const float* W1 = (const float*)d_in[14]; const float* b1  = (const float*)d_in[15];
    const float* W2 = (const float*)d_in[16]; const float* b2  = (const float*)d_in[17];
    const float* g2 = (const float*)d_in[18]; const float* be2 = (const float*)d_in[19];
    float* out = (float*)d_out;

    float  *z, *q, *x1, *sq, *bqkv;
    __half *cath, *zh, *x1h, *yh, *ffnh, *qhp, *khp;
    __half *wembTh, *wqkvT, *woTh, *w1Th, *w2Th;
    cudaGetSymbolAddress((void**)&cath,  g_cath);
    cudaGetSymbolAddress((void**)&z,     g_z);
    cudaGetSymbolAddress((void**)&zh,    g_zh);
    cudaGetSymbolAddress((void**)&q,     g_q);
    cudaGetSymbolAddress((void**)&yh,    g_yh);
    cudaGetSymbolAddress((void**)&x1,    g_x1);
    cudaGetSymbolAddress((void**)&x1h,   g_x1h);
    cudaGetSymbolAddress((void**)&ffnh,  g_ffnh);
    cudaGetSymbolAddress((void**)&qhp,   g_qhp);
    cudaGetSymbolAddress((void**)&khp,   g_khp);
    cudaGetSymbolAddress((void**)&sq,    g_sq);
    cudaGetSymbolAddress((void**)&bqkv,  g_bqkv);
    cudaGetSymbolAddress((void**)&wembTh, g_wembTh);
    cudaGetSymbolAddress((void**)&wqkvT, g_wqkvT);
    cudaGetSymbolAddress((void**)&woTh,  g_woTh);
    cudaGetSymbolAddress((void**)&w1Th,  g_w1Th);
    cudaGetSymbolAddress((void**)&w2Th,  g_w2Th);

    cudaFuncSetAttribute(gemm_h_kernel,
                         cudaFuncAttributeMaxDynamicSharedMemorySize, GK_SMEM_B);
    cudaFuncSetAttribute(dqkv_kernel,
                         cudaFuncAttributeMaxDynamicSharedMemorySize, DQ_SMEM);
    cudaFuncSetAttribute(attn_kernel,
                         cudaFuncAttributeMaxDynamicSharedMemorySize, AT_SMEM);

    dim3 tb(32, 8);
    {
        size_t tot = (size_t)Mrows * KPAD;
        cat_kernel<<<(unsigned)((tot + 255) / 256), 256>>>(x, e);
    }
    transpose_kernel<<<dim3(12, 44, 1), tb>>>(Wemb, wembTh, KCAT, Hd, KPAD, 0, 0);
    transpose_kernel<<<dim3(12, 12, DEPTH), tb>>>(Wq, wqkvT, Hd, Hd, Hd,
                                                  (size_t)Hd * Hd, (size_t)H3 * Hd);
    transpose_kernel<<<dim3(12, 12, DEPTH), tb>>>(Wk, wqkvT + (size_t)Hd * Hd, Hd, Hd, Hd,
                                                  (size_t)Hd * Hd, (size_t)H3 * Hd);
    transpose_kernel<<<dim3(12, 12, DEPTH), tb>>>(Wv, wqkvT + 2 * (size_t)Hd * Hd, Hd, Hd, Hd,
                                                  (size_t)Hd * Hd, (size_t)H3 * Hd);
    qkvbias_kernel<<<(DEPTH * H3 + 255) / 256, 256>>>(bq, bk, bv);
    gemm_h_kernel<<<dim3(Hd / 128, Mrows / 128), 256, GK_SMEM_B>>>(
        cath, KPAD, wembTh, KPAD, nullptr, z, zh, Hd, KPAD, 0);
    transpose_kernel<<<dim3(12, 12, DEPTH), tb>>>(Wo, woTh, Hd, Hd, Hd,
                                                  (size_t)Hd * Hd, (size_t)Hd * Hd);
    transpose_kernel<<<dim3(48, 12, DEPTH), tb>>>(W1, w1Th, Hd, DFFd, Hd,
                                                  (size_t)Hd * DFFd, (size_t)DFFd * Hd);
    transpose_kernel<<<dim3(12, 48, DEPTH), tb>>>(W2, w2Th, DFFd, Hd, DFFd,
                                                  (size_t)DFFd * Hd, (size_t)Hd * DFFd);
    sqnorm_kernel<<<Mrows, 128>>>();

    for (int l = 0; l < DEPTH; l++) {
        const size_t wofs  = (size_t)l * Hd * Hd;
        const size_t w1ofs = (size_t)l * DFFd * Hd;
        dqkv_kernel<<<1152 + 256, 256, DQ_SMEM>>>(
            zh, wqkvT + (size_t)l * H3 * Hd, bqkv + (size_t)l * H3, mask);
        attn_kernel<<<dim3(4, Bn * NHd), 256, AT_SMEM>>>(qhp, khp);
        gemm_h_kernel<<<dim3(Hd / 128, Mrows / 128), 256, GK_SMEM_B>>>(
            yh, Hd, woTh + wofs, Hd, bo + (size_t)l * Hd, q, nullptr, Hd, Hd, 0);
        addln_kernel<<<Mrows / 8, 256>>>(z, q, g1 + (size_t)l * Hd, be1 + (size_t)l * Hd,
                                         x1, x1h, nullptr);
        gemm_h_kernel<<<dim3(DFFd / 128, Mrows / 128), 256, GK_SMEM_B>>>(
            x1h, Hd, w1Th + w1ofs, Hd, b1 + (size_t)l * DFFd,
            nullptr, ffnh, DFFd, Hd, 1);
        gemm_h_kernel<<<dim3(Hd / 128, Mrows / 128), 256, GK_SMEM_B>>>(
            ffnh, DFFd, w2Th + w1ofs, DFFd, b2 + (size_t)l * Hd,
            q, nullptr, Hd, DFFd, 0);
        addln_kernel<<<Mrows / 8, 256>>>(x1, q, g2 + (size_t)l * Hd, be2 + (size_t)l * Hd,
                                         z, zh, sq);
    }

    // outputs: [X_out | E_out | z_out]
    const size_t XTOT = (size_t)Bn * Nn * XDim;
    const size_t ETOT = (size_t)Bn * Nn * Nn * EDim;
    const size_t ZTOT = (size_t)Mrows * Hd;
    const size_t EPAIRS = (size_t)Bn * Nn * Nn;
    out_x_kernel<<<(unsigned)((XTOT + 255) / 256), 256>>>(x, mask, out);
    out_e_kernel<<<(unsigned)((EPAIRS + 255) / 256), 256>>>(e, mask, out + XTOT);
    out_z_kernel<<<(unsigned)((ZTOT + 255) / 256), 256>>>(mask, out + XTOT + ETOT);
    (void)in_sizes; (void)n_in; (void)out_size;
}